// round 1
// baseline (speedup 1.0000x reference)
#include <cuda_runtime.h>
#include <cstdint>
#include <cstddef>

#define BB  8
#define NN  4096
#define KK  32
#define CC  64
#define CIN 67

// -------- scratch (no allocation allowed -> __device__ globals) --------
__device__ float g_GA[(size_t)BB*NN*CC];   // b_attn + w_attn[:,3:] @ f, layout [b, j, c]
__device__ float g_G1[(size_t)BB*NN*CC];   // b1     + w1[:,3:]     @ f, layout [b, j, c]
__device__ int   g_idx[(size_t)BB*NN*KK];  // ball-query neighbor indices
__device__ float g_wap[CC*3];              // w_attn[:, 0:3]
__device__ float g_w1p[CC*3];              // w1[:, 0:3]
__device__ float g_wf1T[CC*CC];            // wf1 transposed [c'][c]
__device__ float g_wf2T[CC*CC];            // wf2 transposed [c'][c]

// ---------------- small param prep ----------------
__global__ void prep_kernel(const float* __restrict__ w_attn, const float* __restrict__ w1,
                            const float* __restrict__ wf1, const float* __restrict__ wf2) {
    int t = threadIdx.x;
    for (int i = t; i < CC*3; i += blockDim.x) {
        int c = i / 3, d = i % 3;
        g_wap[i] = w_attn[c*CIN + d];
        g_w1p[i] = w1[c*CIN + d];
    }
    for (int i = t; i < CC*CC; i += blockDim.x) {
        int c = i / CC, cp = i % CC;
        g_wf1T[cp*CC + c] = wf1[i];
        g_wf2T[cp*CC + c] = wf2[i];
    }
}

// ---------------- GA/G1 precompute: hoist the 64-channel part of conv_attn / conv1 ----------------
// GA[b,j,c] = b_attn[c] + sum_i w_attn[c, 3+i] * f[b,i,j]   (same for G1 with w1/b1)
__global__ void __launch_bounds__(256) ga_kernel(const float* __restrict__ f,
        const float* __restrict__ w_attn, const float* __restrict__ b_attn,
        const float* __restrict__ w1, const float* __restrict__ b1) {
    __shared__ float s_f[64*64];
    __shared__ float s_wa[64*64];   // s_wa[i*64 + c] = w_attn[c, 3+i]
    __shared__ float s_w1[64*64];
    int b  = blockIdx.x >> 6;
    int j0 = (blockIdx.x & 63) << 6;
    int tid = threadIdx.x;

    for (int lin = tid; lin < 64*64; lin += 256) {
        int i = lin >> 6, c = lin & 63;            // consecutive lin -> consecutive c
        s_wa[i*64 + c] = w_attn[c*CIN + 3 + i];    // strided global read (one-time, cached)
        s_w1[i*64 + c] = w1[c*CIN + 3 + i];
    }
    for (int lin = tid; lin < 64*64; lin += 256) {
        int i = lin >> 6, jj = lin & 63;
        s_f[i*64 + jj] = f[((size_t)b*CC + i)*NN + j0 + jj];   // coalesced
    }
    __syncthreads();

    int j  = tid & 63;
    int c0 = (tid >> 6) << 4;
    float accA[16], acc1[16];
#pragma unroll
    for (int q = 0; q < 16; q++) { accA[q] = __ldg(&b_attn[c0+q]); acc1[q] = __ldg(&b1[c0+q]); }

#pragma unroll 4
    for (int i = 0; i < 64; i++) {
        float fv = s_f[i*64 + j];
        const float4* wa = reinterpret_cast<const float4*>(&s_wa[i*64 + c0]);
        const float4* wb = reinterpret_cast<const float4*>(&s_w1[i*64 + c0]);
#pragma unroll
        for (int q = 0; q < 4; q++) {
            float4 a = wa[q], o = wb[q];
            accA[4*q+0] += a.x*fv; accA[4*q+1] += a.y*fv; accA[4*q+2] += a.z*fv; accA[4*q+3] += a.w*fv;
            acc1[4*q+0] += o.x*fv; acc1[4*q+1] += o.y*fv; acc1[4*q+2] += o.z*fv; acc1[4*q+3] += o.w*fv;
        }
    }
    size_t base = ((size_t)b*NN + j0 + j)*CC + c0;
#pragma unroll
    for (int q = 0; q < 4; q++) {
        *reinterpret_cast<float4*>(&g_GA[base + 4*q]) =
            make_float4(accA[4*q+0], accA[4*q+1], accA[4*q+2], accA[4*q+3]);
        *reinterpret_cast<float4*>(&g_G1[base + 4*q]) =
            make_float4(acc1[4*q+0], acc1[4*q+1], acc1[4*q+2], acc1[4*q+3]);
    }
}

// ---------------- ball query: one warp per query, warp-ballot first-K selection ----------------
__global__ void __launch_bounds__(512) bq_kernel(const float* __restrict__ p) {
    extern __shared__ float sm[];
    float* s_px = sm;
    float* s_py = sm + NN;
    float* s_pz = sm + 2*NN;
    int*   s_idx = reinterpret_cast<int*>(sm + 3*NN);   // [16 warps][KK]

    int b     = blockIdx.x >> 8;            // 256 blocks per batch
    int nbase = (blockIdx.x & 255) << 4;    // 16 queries per block
    int tid = threadIdx.x;
    const float* pb = p + (size_t)b*NN*3;
    for (int jj = tid; jj < NN; jj += 512) {
        s_px[jj] = pb[jj*3+0];
        s_py[jj] = pb[jj*3+1];
        s_pz[jj] = pb[jj*3+2];
    }
    __syncthreads();

    int wi = tid >> 5, lane = tid & 31;
    int n = nbase + wi;
    float xn = s_px[n], yn = s_py[n], zn = s_pz[n];
    // match reference: d2 = (|pi|^2 + |pj|^2) - 2*dot, no fma contraction
    float sqn = __fadd_rn(__fadd_rn(__fmul_rn(xn,xn), __fmul_rn(yn,yn)), __fmul_rn(zn,zn));
    const float r2 = (float)(0.15*0.15);
    int* my = s_idx + wi*KK;

    int cnt = 0;
    for (int base = 0; base < NN && cnt < KK; base += 32) {
        int jj = base + lane;
        float xj = s_px[jj], yj = s_py[jj], zj = s_pz[jj];
        float sqj = __fadd_rn(__fadd_rn(__fmul_rn(xj,xj), __fmul_rn(yj,yj)), __fmul_rn(zj,zj));
        float dt  = __fadd_rn(__fadd_rn(__fmul_rn(xn,xj), __fmul_rn(yn,yj)), __fmul_rn(zn,zj));
        float d2  = __fsub_rn(__fadd_rn(sqn, sqj), __fmul_rn(2.0f, dt));
        bool within = (d2 <= r2);
        unsigned m = __ballot_sync(0xffffffffu, within);
        int pos = cnt + __popc(m & ((1u << lane) - 1u));
        if (within && pos < KK) my[pos] = jj;
        cnt += __popc(m);
    }
    __syncwarp();
    if (cnt > KK) cnt = KK;
    // pad with first valid neighbor (always >=1: query itself has d2 == 0 exactly)
    int v = my[(lane < cnt) ? lane : 0];
    g_idx[((size_t)b*NN + n)*KK + lane] = v;
}

// ---------------- fused main: gather + dp-terms + softmax + w2 GEMM + residual MLP ----------------
__global__ void __launch_bounds__(128) main_kernel(const float* __restrict__ p,
        const float* __restrict__ f, const float* __restrict__ w2,
        const float* __restrict__ b2, const float* __restrict__ bf1,
        const float* __restrict__ bf2, float* __restrict__ out) {
    __shared__ float s_w2T[64*68];     // s_w2T[cp*68 + c] = w2[c][cp], pad 68 for alignment
    __shared__ float s_R[64*32];       // relu(conv1) values, [c][k]
    __shared__ float s_dp[3][32];
    __shared__ int   s_j[32];
    __shared__ float s_wap[192], s_w1p[192];
    __shared__ float s_F0[64], s_F1[64], s_H[64];

    int bid = blockIdx.x;
    int b = bid >> 12, n = bid & 4095;
    int tid = threadIdx.x;
    int lane = tid & 31;
    int c0 = (tid >> 5) << 4;          // warp w handles channels [c0, c0+16)

    // stage w2 transposed into smem (broadcast-friendly for the X loop)
    for (int lin = tid*4; lin < 4096; lin += 512) {
        float4 v = __ldg(reinterpret_cast<const float4*>(w2 + lin));
        int c = lin >> 6, cp = lin & 63;
        s_w2T[(cp+0)*68 + c] = v.x;
        s_w2T[(cp+1)*68 + c] = v.y;
        s_w2T[(cp+2)*68 + c] = v.z;
        s_w2T[(cp+3)*68 + c] = v.w;
    }
    for (int i = tid; i < 192; i += 128) { s_wap[i] = g_wap[i]; s_w1p[i] = g_w1p[i]; }
    if (tid < KK) {
        int j = g_idx[(size_t)bid*KK + tid];
        s_j[tid] = j;
        const float* pn = p + ((size_t)b*NN + n)*3;
        const float* pj = p + ((size_t)b*NN + j)*3;
        s_dp[0][tid] = pj[0] - pn[0];
        s_dp[1][tid] = pj[1] - pn[1];
        s_dp[2][tid] = pj[2] - pn[2];
    }
    __syncthreads();

    int j = s_j[lane];
    float dx = s_dp[0][lane], dy = s_dp[1][lane], dz = s_dp[2][lane];

    float at[16], X[16], sfm[16];
    {
        const float4* gaP = reinterpret_cast<const float4*>(g_GA + ((size_t)b*NN + j)*CC + c0);
        const float4* g1P = reinterpret_cast<const float4*>(g_G1 + ((size_t)b*NN + j)*CC + c0);
        float h1[16];
#pragma unroll
        for (int q = 0; q < 4; q++) {
            float4 a = __ldg(gaP + q);
            float4 h = __ldg(g1P + q);
            at[4*q+0]=a.x; at[4*q+1]=a.y; at[4*q+2]=a.z; at[4*q+3]=a.w;
            h1[4*q+0]=h.x; h1[4*q+1]=h.y; h1[4*q+2]=h.z; h1[4*q+3]=h.w;
        }
#pragma unroll
        for (int ii = 0; ii < 16; ii++) {
            int c = c0 + ii;
            at[ii] += s_wap[c*3+0]*dx + s_wap[c*3+1]*dy + s_wap[c*3+2]*dz;
            float t = h1[ii] + s_w1p[c*3+0]*dx + s_w1p[c*3+1]*dy + s_w1p[c*3+2]*dz;
            s_R[c*32 + lane] = fmaxf(t, 0.0f);
        }
    }
    // softmax over k (= lanes) per channel, all in shuffles
#pragma unroll
    for (int ii = 0; ii < 16; ii++) {
        float m = at[ii];
#pragma unroll
        for (int off = 16; off > 0; off >>= 1) m = fmaxf(m, __shfl_xor_sync(0xffffffffu, m, off));
        float e = __expf(at[ii] - m);
        float ssum = e;
#pragma unroll
        for (int off = 16; off > 0; off >>= 1) ssum += __shfl_xor_sync(0xffffffffu, ssum, off);
        sfm[ii] = __fdividef(e, ssum);
    }
#pragma unroll
    for (int ii = 0; ii < 16; ii++) X[ii] = __ldg(&b2[c0+ii]);   // fold conv2 bias into acc init
    __syncthreads();   // s_R complete

    // X[c, k=lane] = b2[c] + sum_c' w2[c,c'] * R[c',k]
#pragma unroll 4
    for (int cp = 0; cp < 64; cp++) {
        float rv = s_R[cp*32 + lane];
        const float4* wv = reinterpret_cast<const float4*>(&s_w2T[cp*68 + c0]);
#pragma unroll
        for (int q = 0; q < 4; q++) {
            float4 a = wv[q];
            X[4*q+0] += a.x*rv; X[4*q+1] += a.y*rv; X[4*q+2] += a.z*rv; X[4*q+3] += a.w*rv;
        }
    }
    // fout0[c] = sum_k softmax * X  (reduce over lanes)
#pragma unroll
    for (int ii = 0; ii < 16; ii++) {
        float v = sfm[ii] * X[ii];
#pragma unroll
        for (int off = 16; off > 0; off >>= 1) v += __shfl_xor_sync(0xffffffffu, v, off);
        if (lane == 0) s_F0[c0 + ii] = v;
    }
    __syncthreads();

    float f1r = 0.0f;
    if (tid < 64) {
        float fv = __ldg(&f[((size_t)b*CC + tid)*NN + n]);
        f1r = fmaxf(s_F0[tid] + fv, 0.0f);       // relu(fout + f)
        s_F1[tid] = f1r;
    }
    __syncthreads();
    if (tid < 64) {
        float acc = __ldg(&bf1[tid]);
#pragma unroll 4
        for (int cp = 0; cp < 64; cp++) acc += __ldg(&g_wf1T[cp*64 + tid]) * s_F1[cp];
        s_H[tid] = fmaxf(acc, 0.0f);
    }
    __syncthreads();
    if (tid < 64) {
        float acc = __ldg(&bf2[tid]);
#pragma unroll 4
        for (int cp = 0; cp < 64; cp++) acc += __ldg(&g_wf2T[cp*64 + tid]) * s_H[cp];
        float o = fmaxf(acc + f1r, 0.0f);        // relu(h + identity)
        out[(size_t)BB*NN*3 + ((size_t)b*CC + tid)*NN + n] = o;
    }
}

// ---------------- launch ----------------
extern "C" void kernel_launch(void* const* d_in, const int* in_sizes, int n_in,
                              void* d_out, int out_size) {
    const float* p      = (const float*)d_in[0];
    const float* f      = (const float*)d_in[1];
    const float* w_attn = (const float*)d_in[2];
    const float* b_attn = (const float*)d_in[3];
    const float* w1     = (const float*)d_in[4];
    const float* b1     = (const float*)d_in[5];
    const float* w2     = (const float*)d_in[6];
    const float* b2     = (const float*)d_in[7];
    const float* wf1    = (const float*)d_in[8];
    const float* bf1    = (const float*)d_in[9];
    const float* wf2    = (const float*)d_in[10];
    const float* bf2    = (const float*)d_in[11];
    float* out = (float*)d_out;

    // output tuple (p, fout): p passthrough first
    cudaMemcpyAsync(out, p, (size_t)BB*NN*3*sizeof(float), cudaMemcpyDeviceToDevice);

    prep_kernel<<<1, 256>>>(w_attn, w1, wf1, wf2);
    ga_kernel<<<BB*(NN/64), 256>>>(f, w_attn, b_attn, w1, b1);

    int bq_smem = (3*NN + 16*KK) * (int)sizeof(float);   // 50 KB -> dynamic smem
    cudaFuncSetAttribute(bq_kernel, cudaFuncAttributeMaxDynamicSharedMemorySize, bq_smem);
    bq_kernel<<<BB*(NN/16), 512, bq_smem>>>(p);

    main_kernel<<<BB*NN, 128>>>(p, f, w2, b2, bf1, bf2, out);
}

// round 3
// speedup vs baseline: 1.4419x; 1.4419x over previous
#include <cuda_runtime.h>
#include <cstdint>
#include <cstddef>

#define BB  8
#define NN  4096
#define KK  32
#define CC  64
#define CIN 67

// -------- scratch (no allocation allowed -> __device__ globals) --------
__device__ __align__(16) float g_GA[(size_t)BB*NN*CC];   // b_attn + w_attn[:,3:] @ f, [b, j, c]
__device__ __align__(16) float g_G1[(size_t)BB*NN*CC];   // b1     + w1[:,3:]     @ f, [b, j, c]
__device__ __align__(16) float g_F0[(size_t)BB*NN*CC];   // attention output (pre-residual), [b, n, c]
__device__ int   g_idx[(size_t)BB*NN*KK];                // ball-query neighbor indices
__device__ __align__(16) float g_wap[CC*4];              // w_attn[:, 0:3]
__device__ __align__(16) float g_w1p[CC*4];              // w1[:, 0:3]
__device__ __align__(16) float g_w2T[CC*CC];             // w2 transposed: [cp][c]
__device__ __align__(16) float g_wf1T[CC*CC];            // wf1 transposed [cp][c]
__device__ __align__(16) float g_wf2T[CC*CC];            // wf2 transposed [cp][c]

// ---------------- helpers: packed f32x2 FMA ----------------
__device__ __forceinline__ unsigned long long pack2(float lo, float hi) {
    unsigned long long r;
    asm("mov.b64 %0, {%1, %2};" : "=l"(r) : "f"(lo), "f"(hi));
    return r;
}
__device__ __forceinline__ float2 unpack2(unsigned long long v) {
    float2 r;
    asm("mov.b64 {%0, %1}, %2;" : "=f"(r.x), "=f"(r.y) : "l"(v));
    return r;
}
__device__ __forceinline__ void fma2(unsigned long long &acc, unsigned long long a, unsigned long long b) {
    asm("fma.rn.f32x2 %0, %1, %2, %3;" : "=l"(acc) : "l"(a), "l"(b), "l"(acc));
}

// merging butterfly: reduce 2*HALF lane-distributed values to HALF, one step.
// After calling with HALF=16,8,4,2,1 on v[32], lane l holds the full lane-sum of v[l].
template<int HALF>
__device__ __forceinline__ void merge_step(float* v, int lane) {
    bool up = (lane & HALF) != 0;
#pragma unroll
    for (int i = 0; i < HALF; i++) {
        float sel = up ? v[i] : v[HALF + i];
        float r = __shfl_xor_sync(0xffffffffu, sel, HALF);
        v[i] = (up ? v[HALF + i] : v[i]) + r;
    }
}

// ---------------- small param prep ----------------
__global__ void prep_kernel(const float* __restrict__ w_attn, const float* __restrict__ w1,
                            const float* __restrict__ w2,
                            const float* __restrict__ wf1, const float* __restrict__ wf2) {
    int t = threadIdx.x;
    for (int i = t; i < CC*3; i += blockDim.x) {
        int c = i / 3, d = i % 3;
        g_wap[i] = w_attn[c*CIN + d];
        g_w1p[i] = w1[c*CIN + d];
    }
    for (int i = t; i < CC*CC; i += blockDim.x) {
        int c = i / CC, cp = i % CC;
        g_w2T[cp*CC + c]  = w2[i];
        g_wf1T[cp*CC + c] = wf1[i];
        g_wf2T[cp*CC + c] = wf2[i];
    }
}

// ---------------- GA/G1 precompute: hoist the 64-channel part of conv_attn / conv1 ----------------
__global__ void __launch_bounds__(256) ga_kernel(const float* __restrict__ f,
        const float* __restrict__ w_attn, const float* __restrict__ b_attn,
        const float* __restrict__ w1, const float* __restrict__ b1) {
    __shared__ float s_f[64*64];
    __shared__ float s_wa[64*64];   // s_wa[i*64 + c] = w_attn[c, 3+i]
    __shared__ float s_w1[64*64];
    int b  = blockIdx.x >> 6;
    int j0 = (blockIdx.x & 63) << 6;
    int tid = threadIdx.x;

    for (int lin = tid; lin < 64*64; lin += 256) {
        int i = lin >> 6, c = lin & 63;
        s_wa[i*64 + c] = w_attn[c*CIN + 3 + i];
        s_w1[i*64 + c] = w1[c*CIN + 3 + i];
    }
    for (int lin = tid; lin < 64*64; lin += 256) {
        int i = lin >> 6, jj = lin & 63;
        s_f[i*64 + jj] = f[((size_t)b*CC + i)*NN + j0 + jj];
    }
    __syncthreads();

    int j  = tid & 63;
    int c0 = (tid >> 6) << 4;
    float accA[16], acc1[16];
#pragma unroll
    for (int q = 0; q < 16; q++) { accA[q] = __ldg(&b_attn[c0+q]); acc1[q] = __ldg(&b1[c0+q]); }

#pragma unroll 4
    for (int i = 0; i < 64; i++) {
        float fv = s_f[i*64 + j];
        const float4* wa = reinterpret_cast<const float4*>(&s_wa[i*64 + c0]);
        const float4* wb = reinterpret_cast<const float4*>(&s_w1[i*64 + c0]);
#pragma unroll
        for (int q = 0; q < 4; q++) {
            float4 a = wa[q], o = wb[q];
            accA[4*q+0] += a.x*fv; accA[4*q+1] += a.y*fv; accA[4*q+2] += a.z*fv; accA[4*q+3] += a.w*fv;
            acc1[4*q+0] += o.x*fv; acc1[4*q+1] += o.y*fv; acc1[4*q+2] += o.z*fv; acc1[4*q+3] += o.w*fv;
        }
    }
    size_t base = ((size_t)b*NN + j0 + j)*CC + c0;
#pragma unroll
    for (int q = 0; q < 4; q++) {
        *reinterpret_cast<float4*>(&g_GA[base + 4*q]) =
            make_float4(accA[4*q+0], accA[4*q+1], accA[4*q+2], accA[4*q+3]);
        *reinterpret_cast<float4*>(&g_G1[base + 4*q]) =
            make_float4(acc1[4*q+0], acc1[4*q+1], acc1[4*q+2], acc1[4*q+3]);
    }
}

// ---------------- ball query: one warp per query, warp-ballot first-K selection ----------------
__global__ void __launch_bounds__(512) bq_kernel(const float* __restrict__ p) {
    extern __shared__ float sm[];
    float* s_px = sm;
    float* s_py = sm + NN;
    float* s_pz = sm + 2*NN;
    int*   s_idx = reinterpret_cast<int*>(sm + 3*NN);   // [16 warps][KK]

    int b     = blockIdx.x >> 8;
    int nbase = (blockIdx.x & 255) << 4;
    int tid = threadIdx.x;
    const float* pb = p + (size_t)b*NN*3;
    for (int jj = tid; jj < NN; jj += 512) {
        s_px[jj] = pb[jj*3+0];
        s_py[jj] = pb[jj*3+1];
        s_pz[jj] = pb[jj*3+2];
    }
    __syncthreads();

    int wi = tid >> 5, lane = tid & 31;
    int n = nbase + wi;
    float xn = s_px[n], yn = s_py[n], zn = s_pz[n];
    float sqn = __fadd_rn(__fadd_rn(__fmul_rn(xn,xn), __fmul_rn(yn,yn)), __fmul_rn(zn,zn));
    const float r2 = (float)(0.15*0.15);
    int* my = s_idx + wi*KK;

    int cnt = 0;
    for (int base = 0; base < NN && cnt < KK; base += 32) {
        int jj = base + lane;
        float xj = s_px[jj], yj = s_py[jj], zj = s_pz[jj];
        float sqj = __fadd_rn(__fadd_rn(__fmul_rn(xj,xj), __fmul_rn(yj,yj)), __fmul_rn(zj,zj));
        float dt  = __fadd_rn(__fadd_rn(__fmul_rn(xn,xj), __fmul_rn(yn,yj)), __fmul_rn(zn,zj));
        float d2  = __fsub_rn(__fadd_rn(sqn, sqj), __fmul_rn(2.0f, dt));
        bool within = (d2 <= r2);
        unsigned m = __ballot_sync(0xffffffffu, within);
        int pos = cnt + __popc(m & ((1u << lane) - 1u));
        if (within && pos < KK) my[pos] = jj;
        cnt += __popc(m);
    }
    __syncwarp();
    if (cnt > KK) cnt = KK;
    int v = my[(lane < cnt) ? lane : 0];
    g_idx[((size_t)b*NN + n)*KK + lane] = v;
}

// ---------------- fused main: gather + dp-terms + softmax + w2 GEMM (2 points / block) ----------------
__global__ void __launch_bounds__(256) main_kernel(const float* __restrict__ p,
        const float* __restrict__ b2) {
    __shared__ float s_w2T[64*64];     // [cp][c] — broadcast reads
    __shared__ float s_R[2][64*32];    // relu(conv1), [pt][c][k]
    __shared__ float s_dp[2][3][32];
    __shared__ int   s_j[2][32];
    __shared__ float s_wap[192], s_w1p[192];

    int tid  = threadIdx.x;
    int w    = tid >> 5;
    int lane = tid & 31;
    int pt   = w >> 2;                 // 0/1: which point this warp serves
    int c0   = (w & 3) << 4;           // 16-channel slice
    int pid  = blockIdx.x*2 + pt;
    int b    = pid >> 12, n = pid & 4095;

    // stage w2T (already transposed in prep) with clean float4 copies
    for (int i = tid; i < 1024; i += 256)
        reinterpret_cast<float4*>(s_w2T)[i] = reinterpret_cast<const float4*>(g_w2T)[i];
    for (int i = tid; i < 192; i += 256) { s_wap[i] = g_wap[i]; s_w1p[i] = g_w1p[i]; }

    if ((w & 3) == 0) {
        int j = g_idx[(size_t)pid*KK + lane];
        s_j[pt][lane] = j;
        const float* pn = p + ((size_t)b*NN + n)*3;
        const float* pj = p + ((size_t)b*NN + j)*3;
        s_dp[pt][0][lane] = pj[0] - pn[0];
        s_dp[pt][1][lane] = pj[1] - pn[1];
        s_dp[pt][2][lane] = pj[2] - pn[2];
    }
    __syncthreads();

    int j = s_j[pt][lane];
    float dx = s_dp[pt][0][lane], dy = s_dp[pt][1][lane], dz = s_dp[pt][2][lane];

    float e[16];
    {
        const float4* gaP = reinterpret_cast<const float4*>(g_GA + ((size_t)b*NN + j)*CC + c0);
        const float4* g1P = reinterpret_cast<const float4*>(g_G1 + ((size_t)b*NN + j)*CC + c0);
        float h1[16];
#pragma unroll
        for (int q = 0; q < 4; q++) {
            float4 a = __ldg(gaP + q);
            float4 h = __ldg(g1P + q);
            e[4*q+0]=a.x; e[4*q+1]=a.y; e[4*q+2]=a.z; e[4*q+3]=a.w;
            h1[4*q+0]=h.x; h1[4*q+1]=h.y; h1[4*q+2]=h.z; h1[4*q+3]=h.w;
        }
#pragma unroll
        for (int ii = 0; ii < 16; ii++) {
            int c = c0 + ii;
            e[ii] += s_wap[c*3+0]*dx + s_wap[c*3+1]*dy + s_wap[c*3+2]*dz;
            float t = h1[ii] + s_w1p[c*3+0]*dx + s_w1p[c*3+1]*dy + s_w1p[c*3+2]*dz;
            s_R[pt][c*32 + lane] = fmaxf(t, 0.0f);
        }
    }
    // un-normalized softmax weights, no max-shift (attn magnitude is O(1); exp is safe,
    // softmax result is mathematically identical and numerically within ~1e-7)
#pragma unroll
    for (int ii = 0; ii < 16; ii++) e[ii] = __expf(e[ii]);

    // accumulators as packed f32x2 (init with conv2 bias)
    unsigned long long X[8];
#pragma unroll
    for (int q = 0; q < 8; q++) X[q] = pack2(__ldg(&b2[c0+2*q]), __ldg(&b2[c0+2*q+1]));

    __syncthreads();   // s_R complete for both points

    // X[c, k=lane] += sum_cp w2[c,cp] * R[cp,k]   (FFMA2: 8 packed FMAs per cp)
    const float* Rp = &s_R[pt][0];
#pragma unroll 4
    for (int cp = 0; cp < 64; cp++) {
        float rv = Rp[cp*32 + lane];
        unsigned long long rv2 = pack2(rv, rv);
        const ulonglong2* wr = reinterpret_cast<const ulonglong2*>(&s_w2T[cp*64 + c0]);
        ulonglong2 a0 = wr[0], a1 = wr[1], a2 = wr[2], a3 = wr[3];
        fma2(X[0], a0.x, rv2); fma2(X[1], a0.y, rv2);
        fma2(X[2], a1.x, rv2); fma2(X[3], a1.y, rv2);
        fma2(X[4], a2.x, rv2); fma2(X[5], a2.y, rv2);
        fma2(X[6], a3.x, rv2); fma2(X[7], a3.y, rv2);
    }

    // 32 simultaneous lane-reductions via merging butterfly (31 SHFL total):
    // v[i]    = e[i] * X[i]   (numerator for channel c0+i)
    // v[16+i] = e[i]          (denominator for channel c0+i)
    float v[32];
#pragma unroll
    for (int q = 0; q < 8; q++) {
        float2 xv = unpack2(X[q]);
        v[2*q+0] = e[2*q+0] * xv.x;
        v[2*q+1] = e[2*q+1] * xv.y;
        v[16+2*q+0] = e[2*q+0];
        v[16+2*q+1] = e[2*q+1];
    }
    merge_step<16>(v, lane);
    merge_step<8>(v, lane);
    merge_step<4>(v, lane);
    merge_step<2>(v, lane);
    merge_step<1>(v, lane);
    // lane l (l<16): v[0] = total numerator of channel c0+l; lane 16+l: denominator
    float den = __shfl_xor_sync(0xffffffffu, v[0], 16);
    if (lane < 16)
        g_F0[(size_t)pid*CC + c0 + lane] = v[0] / den;
}

// ---------------- tail: relu(F0+f) -> 2x (64x64) MLP -> relu residual, 64 points / block ----------------
__global__ void __launch_bounds__(256) tail_kernel(const float* __restrict__ f,
        const float* __restrict__ bf1, const float* __restrict__ bf2,
        float* __restrict__ outF) {
    __shared__ float s_F1[64*68];   // [c][n], padded
    __shared__ float s_H[64*68];

    int b   = blockIdx.x >> 6;
    int n0g = (blockIdx.x & 63) << 6;
    int tid = threadIdx.x;

    // build F1[c][n] = relu(F0[n][c] + f[c][n])
    {
        int c = tid >> 2, q = tid & 3;
        const float* frow = f + ((size_t)b*CC + c)*NN + n0g;
        const float* f0b  = g_F0 + ((size_t)b*NN + n0g)*CC + c;
#pragma unroll
        for (int i = 0; i < 4; i++) {
            int nn = q*16 + i*4;
            float4 fv = *reinterpret_cast<const float4*>(frow + nn);
            float a0 = __ldg(&f0b[(nn+0)*CC]);
            float a1 = __ldg(&f0b[(nn+1)*CC]);
            float a2 = __ldg(&f0b[(nn+2)*CC]);
            float a3 = __ldg(&f0b[(nn+3)*CC]);
            float4 r;
            r.x = fmaxf(a0 + fv.x, 0.0f);
            r.y = fmaxf(a1 + fv.y, 0.0f);
            r.z = fmaxf(a2 + fv.z, 0.0f);
            r.w = fmaxf(a3 + fv.w, 0.0f);
            *reinterpret_cast<float4*>(&s_F1[c*68 + nn]) = r;
        }
    }
    __syncthreads();

    int ct = (tid >> 4) << 2;   // 4 channels
    int nt = (tid & 15) << 2;   // 4 points

    // GEMM1: H = relu(bf1 + wf1 @ F1)
    {
        float acc[16];
#pragma unroll
        for (int r = 0; r < 4; r++) {
            float bv = __ldg(&bf1[ct+r]);
#pragma unroll
            for (int jj = 0; jj < 4; jj++) acc[r*4+jj] = bv;
        }
#pragma unroll 4
        for (int cp = 0; cp < 64; cp++) {
            float4 wv = __ldg(reinterpret_cast<const float4*>(&g_wf1T[cp*64 + ct]));
            float4 fv = *reinterpret_cast<const float4*>(&s_F1[cp*68 + nt]);
            acc[0]  += wv.x*fv.x; acc[1]  += wv.x*fv.y; acc[2]  += wv.x*fv.z; acc[3]  += wv.x*fv.w;
            acc[4]  += wv.y*fv.x; acc[5]  += wv.y*fv.y; acc[6]  += wv.y*fv.z; acc[7]  += wv.y*fv.w;
            acc[8]  += wv.z*fv.x; acc[9]  += wv.z*fv.y; acc[10] += wv.z*fv.z; acc[11] += wv.z*fv.w;
            acc[12] += wv.w*fv.x; acc[13] += wv.w*fv.y; acc[14] += wv.w*fv.z; acc[15] += wv.w*fv.w;
        }
#pragma unroll
        for (int r = 0; r < 4; r++) {
            float4 o;
            o.x = fmaxf(acc[r*4+0], 0.0f);
            o.y = fmaxf(acc[r*4+1], 0.0f);
            o.z = fmaxf(acc[r*4+2], 0.0f);
            o.w = fmaxf(acc[r*4+3], 0.0f);
            *reinterpret_cast<float4*>(&s_H[(ct+r)*68 + nt]) = o;
        }
    }
    __syncthreads();

    // GEMM2: out = relu(bf2 + wf2 @ H + F1)
    {
        float acc[16];
#pragma unroll
        for (int r = 0; r < 4; r++) {
            float bv = __ldg(&bf2[ct+r]);
#pragma unroll
            for (int jj = 0; jj < 4; jj++) acc[r*4+jj] = bv;
        }
#pragma unroll 4
        for (int cp = 0; cp < 64; cp++) {
            float4 wv = __ldg(reinterpret_cast<const float4*>(&g_wf2T[cp*64 + ct]));
            float4 hv = *reinterpret_cast<const float4*>(&s_H[cp*68 + nt]);
            acc[0]  += wv.x*hv.x; acc[1]  += wv.x*hv.y; acc[2]  += wv.x*hv.z; acc[3]  += wv.x*hv.w;
            acc[4]  += wv.y*hv.x; acc[5]  += wv.y*hv.y; acc[6]  += wv.y*hv.z; acc[7]  += wv.y*hv.w;
            acc[8]  += wv.z*hv.x; acc[9]  += wv.z*hv.y; acc[10] += wv.z*hv.z; acc[11] += wv.z*hv.w;
            acc[12] += wv.w*hv.x; acc[13] += wv.w*hv.y; acc[14] += wv.w*hv.z; acc[15] += wv.w*hv.w;
        }
#pragma unroll
        for (int r = 0; r < 4; r++) {
            const float* idn = &s_F1[(ct+r)*68 + nt];
            float4 o;
            o.x = fmaxf(acc[r*4+0] + idn[0], 0.0f);
            o.y = fmaxf(acc[r*4+1] + idn[1], 0.0f);
            o.z = fmaxf(acc[r*4+2] + idn[2], 0.0f);
            o.w = fmaxf(acc[r*4+3] + idn[3], 0.0f);
            *reinterpret_cast<float4*>(&outF[((size_t)b*CC + ct + r)*NN + n0g + nt]) = o;
        }
    }
}

// ---------------- launch ----------------
extern "C" void kernel_launch(void* const* d_in, const int* in_sizes, int n_in,
                              void* d_out, int out_size) {
    const float* p      = (const float*)d_in[0];
    const float* f      = (const float*)d_in[1];
    const float* w_attn = (const float*)d_in[2];
    const float* b_attn = (const float*)d_in[3];
    const float* w1     = (const float*)d_in[4];
    const float* b1     = (const float*)d_in[5];
    const float* w2     = (const float*)d_in[6];
    const float* b2     = (const float*)d_in[7];
    const float* wf1    = (const float*)d_in[8];
    const float* bf1    = (const float*)d_in[9];
    const float* wf2    = (const float*)d_in[10];
    const float* bf2    = (const float*)d_in[11];
    float* out = (float*)d_out;

    // output tuple (p, fout): p passthrough first
    cudaMemcpyAsync(out, p, (size_t)BB*NN*3*sizeof(float), cudaMemcpyDeviceToDevice);

    prep_kernel<<<1, 256>>>(w_attn, w1, w2, wf1, wf2);
    ga_kernel<<<BB*(NN/64), 256>>>(f, w_attn, b_attn, w1, b1);

    int bq_smem = (3*NN + 16*KK) * (int)sizeof(float);   // 50 KB -> dynamic smem
    cudaFuncSetAttribute(bq_kernel, cudaFuncAttributeMaxDynamicSharedMemorySize, bq_smem);
    bq_kernel<<<BB*(NN/16), 512, bq_smem>>>(p);

    main_kernel<<<BB*NN/2, 256>>>(p, b2);
    tail_kernel<<<BB*(NN/64), 256>>>(f, bf1, bf2, out + (size_t)BB*NN*3);
}

// round 4
// speedup vs baseline: 1.5894x; 1.1023x over previous
#include <cuda_runtime.h>
#include <cstdint>
#include <cstddef>

#define BB  8
#define NN  4096
#define KK  32
#define CC  64
#define CIN 67

// -------- scratch (no allocation allowed -> __device__ globals) --------
__device__ __align__(16) float g_G[(size_t)BB*NN*128]; // merged [b][j][0:64]=GA, [64:128]=G1
__device__ __align__(16) float g_F0[(size_t)BB*NN*CC]; // attention output (pre-residual), [b, n, c]
__device__ int   g_idx[(size_t)BB*NN*KK];              // ball-query neighbor indices
__device__ __align__(16) float g_wD3[3*128];           // [d][u]: u<64 -> w_attn[u][d], else w1[u-64][d]
__device__ __align__(16) float g_w2T[CC*CC];           // w2 transposed: [cp][c]
__device__ __align__(16) float g_wf1T[CC*CC];          // wf1 transposed [cp][c]
__device__ __align__(16) float g_wf2T[CC*CC];          // wf2 transposed [cp][c]

// ---------------- helpers: packed f32x2 FMA ----------------
__device__ __forceinline__ unsigned long long pack2(float lo, float hi) {
    unsigned long long r;
    asm("mov.b64 %0, {%1, %2};" : "=l"(r) : "f"(lo), "f"(hi));
    return r;
}
__device__ __forceinline__ float2 unpack2(unsigned long long v) {
    float2 r;
    asm("mov.b64 {%0, %1}, %2;" : "=f"(r.x), "=f"(r.y) : "l"(v));
    return r;
}
__device__ __forceinline__ void fma2(unsigned long long &acc, unsigned long long a, unsigned long long b) {
    asm("fma.rn.f32x2 %0, %1, %2, %3;" : "=l"(acc) : "l"(a), "l"(b), "l"(acc));
}

// merging butterfly: after HALF=16,8,4,2,1 on v[32], lane l holds full lane-sum of v[l].
template<int HALF>
__device__ __forceinline__ void merge_step(float* v, int lane) {
    bool up = (lane & HALF) != 0;
#pragma unroll
    for (int i = 0; i < HALF; i++) {
        float sel = up ? v[i] : v[HALF + i];
        float r = __shfl_xor_sync(0xffffffffu, sel, HALF);
        v[i] = (up ? v[HALF + i] : v[i]) + r;
    }
}

// ---------------- small param prep ----------------
__global__ void prep_kernel(const float* __restrict__ w_attn, const float* __restrict__ w1,
                            const float* __restrict__ w2,
                            const float* __restrict__ wf1, const float* __restrict__ wf2) {
    int t = threadIdx.x;
    for (int i = t; i < 3*128; i += blockDim.x) {
        int d = i / 128, u = i % 128;
        g_wD3[i] = (u < 64) ? w_attn[u*CIN + d] : w1[(u-64)*CIN + d];
    }
    for (int i = t; i < CC*CC; i += blockDim.x) {
        int c = i / CC, cp = i % CC;
        g_w2T[cp*CC + c]  = w2[i];
        g_wf1T[cp*CC + c] = wf1[i];
        g_wf2T[cp*CC + c] = wf2[i];
    }
}

// ---------------- GA/G1 precompute -> merged g_G rows ----------------
__global__ void __launch_bounds__(256) ga_kernel(const float* __restrict__ f,
        const float* __restrict__ w_attn, const float* __restrict__ b_attn,
        const float* __restrict__ w1, const float* __restrict__ b1) {
    __shared__ float s_f[64*64];
    __shared__ float s_wa[64*64];   // s_wa[i*64 + c] = w_attn[c, 3+i]
    __shared__ float s_w1[64*64];
    int b  = blockIdx.x >> 6;
    int j0 = (blockIdx.x & 63) << 6;
    int tid = threadIdx.x;

    for (int lin = tid; lin < 64*64; lin += 256) {
        int i = lin >> 6, c = lin & 63;
        s_wa[i*64 + c] = w_attn[c*CIN + 3 + i];
        s_w1[i*64 + c] = w1[c*CIN + 3 + i];
    }
    for (int lin = tid; lin < 64*64; lin += 256) {
        int i = lin >> 6, jj = lin & 63;
        s_f[i*64 + jj] = f[((size_t)b*CC + i)*NN + j0 + jj];
    }
    __syncthreads();

    int j  = tid & 63;
    int c0 = (tid >> 6) << 4;
    float accA[16], acc1[16];
#pragma unroll
    for (int q = 0; q < 16; q++) { accA[q] = __ldg(&b_attn[c0+q]); acc1[q] = __ldg(&b1[c0+q]); }

#pragma unroll 4
    for (int i = 0; i < 64; i++) {
        float fv = s_f[i*64 + j];
        const float4* wa = reinterpret_cast<const float4*>(&s_wa[i*64 + c0]);
        const float4* wb = reinterpret_cast<const float4*>(&s_w1[i*64 + c0]);
#pragma unroll
        for (int q = 0; q < 4; q++) {
            float4 a = wa[q], o = wb[q];
            accA[4*q+0] += a.x*fv; accA[4*q+1] += a.y*fv; accA[4*q+2] += a.z*fv; accA[4*q+3] += a.w*fv;
            acc1[4*q+0] += o.x*fv; acc1[4*q+1] += o.y*fv; acc1[4*q+2] += o.z*fv; acc1[4*q+3] += o.w*fv;
        }
    }
    size_t base = ((size_t)b*NN + j0 + j)*128 + c0;
#pragma unroll
    for (int q = 0; q < 4; q++) {
        *reinterpret_cast<float4*>(&g_G[base + 4*q]) =
            make_float4(accA[4*q+0], accA[4*q+1], accA[4*q+2], accA[4*q+3]);
        *reinterpret_cast<float4*>(&g_G[base + 64 + 4*q]) =
            make_float4(acc1[4*q+0], acc1[4*q+1], acc1[4*q+2], acc1[4*q+3]);
    }
}

// ---------------- ball query (unchanged) ----------------
__global__ void __launch_bounds__(512) bq_kernel(const float* __restrict__ p) {
    extern __shared__ float sm[];
    float* s_px = sm;
    float* s_py = sm + NN;
    float* s_pz = sm + 2*NN;
    int*   s_idx = reinterpret_cast<int*>(sm + 3*NN);

    int b     = blockIdx.x >> 8;
    int nbase = (blockIdx.x & 255) << 4;
    int tid = threadIdx.x;
    const float* pb = p + (size_t)b*NN*3;
    for (int jj = tid; jj < NN; jj += 512) {
        s_px[jj] = pb[jj*3+0];
        s_py[jj] = pb[jj*3+1];
        s_pz[jj] = pb[jj*3+2];
    }
    __syncthreads();

    int wi = tid >> 5, lane = tid & 31;
    int n = nbase + wi;
    float xn = s_px[n], yn = s_py[n], zn = s_pz[n];
    float sqn = __fadd_rn(__fadd_rn(__fmul_rn(xn,xn), __fmul_rn(yn,yn)), __fmul_rn(zn,zn));
    const float r2 = (float)(0.15*0.15);
    int* my = s_idx + wi*KK;

    int cnt = 0;
    for (int base = 0; base < NN && cnt < KK; base += 32) {
        int jj = base + lane;
        float xj = s_px[jj], yj = s_py[jj], zj = s_pz[jj];
        float sqj = __fadd_rn(__fadd_rn(__fmul_rn(xj,xj), __fmul_rn(yj,yj)), __fmul_rn(zj,zj));
        float dt  = __fadd_rn(__fadd_rn(__fmul_rn(xn,xj), __fmul_rn(yn,yj)), __fmul_rn(zn,zj));
        float d2  = __fsub_rn(__fadd_rn(sqn, sqj), __fmul_rn(2.0f, dt));
        bool within = (d2 <= r2);
        unsigned m = __ballot_sync(0xffffffffu, within);
        int pos = cnt + __popc(m & ((1u << lane) - 1u));
        if (within && pos < KK) my[pos] = jj;
        cnt += __popc(m);
    }
    __syncwarp();
    if (cnt > KK) cnt = KK;
    int v = my[(lane < cnt) ? lane : 0];
    g_idx[((size_t)b*NN + n)*KK + lane] = v;
}

// ---------------- fused main: 4 points/block, coalesced gather + smem transpose ----------------
// dyn smem layout (floats):
//   s_w2T   : [0, 4096)
//   s_R[pt] : 4096 + pt*2048           (R[cp][slot], slot=(k+cp)&31)
//   s_E[pt] : 12288 + pt*2176          (E[k][c], pitch 68)
//   s_meta  : 20992 + (pt*32+k)*4      (float4: dx,dy,dz,j)
#define SM_R0   4096
#define SM_E0   12288
#define SM_META 20992
#define SM_TOT  (21504*4)   // bytes

__device__ __forceinline__ void epilogue_point(const unsigned long long* X,
        const float* Erow /* = s_E[pt] + lane*68 + c0 */,
        float* outp /* = g_F0 + pid*64 + c0 */, int lane) {
    float4 e0 = *reinterpret_cast<const float4*>(Erow + 0);
    float4 e1 = *reinterpret_cast<const float4*>(Erow + 4);
    float4 e2 = *reinterpret_cast<const float4*>(Erow + 8);
    float4 e3 = *reinterpret_cast<const float4*>(Erow + 12);
    float ev[16] = {e0.x,e0.y,e0.z,e0.w, e1.x,e1.y,e1.z,e1.w,
                    e2.x,e2.y,e2.z,e2.w, e3.x,e3.y,e3.z,e3.w};
    float v[32];
#pragma unroll
    for (int q = 0; q < 8; q++) {
        float2 xv = unpack2(X[q]);
        v[2*q+0]    = ev[2*q+0] * xv.x;
        v[2*q+1]    = ev[2*q+1] * xv.y;
        v[16+2*q+0] = ev[2*q+0];
        v[16+2*q+1] = ev[2*q+1];
    }
    merge_step<16>(v, lane);
    merge_step<8>(v, lane);
    merge_step<4>(v, lane);
    merge_step<2>(v, lane);
    merge_step<1>(v, lane);
    float den = __shfl_xor_sync(0xffffffffu, v[0], 16);
    if (lane < 16) outp[lane] = v[0] / den;
}

__global__ void __launch_bounds__(256, 2) main_kernel(const float* __restrict__ p,
        const float* __restrict__ b2) {
    extern __shared__ float sm[];
    float*  s_w2T  = sm;
    float4* s_meta = reinterpret_cast<float4*>(sm + SM_META);

    int tid  = threadIdx.x;
    int w    = tid >> 5;
    int lane = tid & 31;
    int pbase = blockIdx.x * 4;

    // stage w2T (pre-transposed) via clean float4 copies
    for (int i = tid; i < 1024; i += 256)
        reinterpret_cast<float4*>(s_w2T)[i] = reinterpret_cast<const float4*>(g_w2T)[i];

    // meta: warps 0..3 stage (dp, j) for point w
    if (w < 4) {
        int pid = pbase + w;
        int b = pid >> 12, n = pid & 4095;
        int j = g_idx[(size_t)pid*KK + lane];
        const float* pn = p + ((size_t)b*NN + n)*3;
        const float* pj = p + ((size_t)b*NN + j)*3;
        float4 m;
        m.x = pj[0] - pn[0];
        m.y = pj[1] - pn[1];
        m.z = pj[2] - pn[2];
        m.w = __int_as_float(j);
        s_meta[w*32 + lane] = m;
    }
    __syncthreads();

    // ---- phase 1: gather + at/exp/R, warp = (pt = w&3, k-half = w>>2) ----
    {
        int pt = w & 3;
        int k0 = (w >> 2) * 16;
        int pid = pbase + pt;
        int b = pid >> 12;
        int u = lane * 4;              // unified channel index: <64 GA, >=64 G1
        bool isE = (lane < 16);
        float4 wx = *reinterpret_cast<const float4*>(&g_wD3[0*128 + u]);
        float4 wy = *reinterpret_cast<const float4*>(&g_wD3[1*128 + u]);
        float4 wz = *reinterpret_cast<const float4*>(&g_wD3[2*128 + u]);
        float* Rp = sm + SM_R0 + pt*2048;
        float* Ep = sm + SM_E0 + pt*2176;
        const float* Gb = g_G + (size_t)b*NN*128;
        int cpb = u - 64;

#pragma unroll 4
        for (int kk = 0; kk < 16; kk++) {
            int k = k0 + kk;
            float4 m = s_meta[pt*32 + k];
            int j = __float_as_int(m.w);
            float4 g = __ldg(reinterpret_cast<const float4*>(&Gb[(size_t)j*128 + u]));
            float4 v;
            v.x = g.x + wx.x*m.x + wy.x*m.y + wz.x*m.z;
            v.y = g.y + wx.y*m.x + wy.y*m.y + wz.y*m.z;
            v.z = g.z + wx.z*m.x + wy.z*m.y + wz.z*m.z;
            v.w = g.w + wx.w*m.x + wy.w*m.y + wz.w*m.z;
            if (isE) {
                float4 o;
                o.x = __expf(v.x); o.y = __expf(v.y);
                o.z = __expf(v.z); o.w = __expf(v.w);
                *reinterpret_cast<float4*>(&Ep[k*68 + u]) = o;
            } else {
                Rp[(cpb+0)*32 + ((k+cpb+0)&31)] = fmaxf(v.x, 0.0f);
                Rp[(cpb+1)*32 + ((k+cpb+1)&31)] = fmaxf(v.y, 0.0f);
                Rp[(cpb+2)*32 + ((k+cpb+2)&31)] = fmaxf(v.z, 0.0f);
                Rp[(cpb+3)*32 + ((k+cpb+3)&31)] = fmaxf(v.w, 0.0f);
            }
        }
    }
    __syncthreads();

    // ---- phase 2: GEMM (point-paired) + softmax-weighted reduction ----
    {
        int cs = w & 3, pp = w >> 2;
        int c0 = cs << 4;
        int ptA = 2*pp, ptB = 2*pp + 1;
        const float* RA = sm + SM_R0 + ptA*2048;
        const float* RB = sm + SM_R0 + ptB*2048;

        unsigned long long XA[8], XB[8];
#pragma unroll
        for (int q = 0; q < 8; q++) {
            unsigned long long bi = pack2(__ldg(&b2[c0+2*q]), __ldg(&b2[c0+2*q+1]));
            XA[q] = bi; XB[q] = bi;
        }

#pragma unroll 4
        for (int cp = 0; cp < 64; cp++) {
            const ulonglong2* wr = reinterpret_cast<const ulonglong2*>(&s_w2T[cp*64 + c0]);
            ulonglong2 w01 = wr[0], w23 = wr[1], w45 = wr[2], w67 = wr[3];
            int slot = (lane + cp) & 31;
            float rA = RA[cp*32 + slot];
            float rB = RB[cp*32 + slot];
            unsigned long long rA2 = pack2(rA, rA);
            unsigned long long rB2 = pack2(rB, rB);
            fma2(XA[0], w01.x, rA2); fma2(XA[1], w01.y, rA2);
            fma2(XA[2], w23.x, rA2); fma2(XA[3], w23.y, rA2);
            fma2(XA[4], w45.x, rA2); fma2(XA[5], w45.y, rA2);
            fma2(XA[6], w67.x, rA2); fma2(XA[7], w67.y, rA2);
            fma2(XB[0], w01.x, rB2); fma2(XB[1], w01.y, rB2);
            fma2(XB[2], w23.x, rB2); fma2(XB[3], w23.y, rB2);
            fma2(XB[4], w45.x, rB2); fma2(XB[5], w45.y, rB2);
            fma2(XB[6], w67.x, rB2); fma2(XB[7], w67.y, rB2);
        }

        epilogue_point(XA, sm + SM_E0 + ptA*2176 + lane*68 + c0,
                       g_F0 + (size_t)(pbase + ptA)*CC + c0, lane);
        epilogue_point(XB, sm + SM_E0 + ptB*2176 + lane*68 + c0,
                       g_F0 + (size_t)(pbase + ptB)*CC + c0, lane);
    }
}

// ---------------- tail: relu(F0+f) -> 2x (64x64) MLP -> relu residual ----------------
__global__ void __launch_bounds__(256) tail_kernel(const float* __restrict__ f,
        const float* __restrict__ bf1, const float* __restrict__ bf2,
        float* __restrict__ outF) {
    __shared__ float s_F1[64*68];
    __shared__ float s_H[64*68];

    int b   = blockIdx.x >> 6;
    int n0g = (blockIdx.x & 63) << 6;
    int tid = threadIdx.x;

    {
        int c = tid >> 2, q = tid & 3;
        const float* frow = f + ((size_t)b*CC + c)*NN + n0g;
        const float* f0b  = g_F0 + ((size_t)b*NN + n0g)*CC + c;
#pragma unroll
        for (int i = 0; i < 4; i++) {
            int nn = q*16 + i*4;
            float4 fv = *reinterpret_cast<const float4*>(frow + nn);
            float a0 = __ldg(&f0b[(nn+0)*CC]);
            float a1 = __ldg(&f0b[(nn+1)*CC]);
            float a2 = __ldg(&f0b[(nn+2)*CC]);
            float a3 = __ldg(&f0b[(nn+3)*CC]);
            float4 r;
            r.x = fmaxf(a0 + fv.x, 0.0f);
            r.y = fmaxf(a1 + fv.y, 0.0f);
            r.z = fmaxf(a2 + fv.z, 0.0f);
            r.w = fmaxf(a3 + fv.w, 0.0f);
            *reinterpret_cast<float4*>(&s_F1[c*68 + nn]) = r;
        }
    }
    __syncthreads();

    int ct = (tid >> 4) << 2;
    int nt = (tid & 15) << 2;

    {
        float acc[16];
#pragma unroll
        for (int r = 0; r < 4; r++) {
            float bv = __ldg(&bf1[ct+r]);
#pragma unroll
            for (int jj = 0; jj < 4; jj++) acc[r*4+jj] = bv;
        }
#pragma unroll 4
        for (int cp = 0; cp < 64; cp++) {
            float4 wv = __ldg(reinterpret_cast<const float4*>(&g_wf1T[cp*64 + ct]));
            float4 fv = *reinterpret_cast<const float4*>(&s_F1[cp*68 + nt]);
            acc[0]  += wv.x*fv.x; acc[1]  += wv.x*fv.y; acc[2]  += wv.x*fv.z; acc[3]  += wv.x*fv.w;
            acc[4]  += wv.y*fv.x; acc[5]  += wv.y*fv.y; acc[6]  += wv.y*fv.z; acc[7]  += wv.y*fv.w;
            acc[8]  += wv.z*fv.x; acc[9]  += wv.z*fv.y; acc[10] += wv.z*fv.z; acc[11] += wv.z*fv.w;
            acc[12] += wv.w*fv.x; acc[13] += wv.w*fv.y; acc[14] += wv.w*fv.z; acc[15] += wv.w*fv.w;
        }
#pragma unroll
        for (int r = 0; r < 4; r++) {
            float4 o;
            o.x = fmaxf(acc[r*4+0], 0.0f);
            o.y = fmaxf(acc[r*4+1], 0.0f);
            o.z = fmaxf(acc[r*4+2], 0.0f);
            o.w = fmaxf(acc[r*4+3], 0.0f);
            *reinterpret_cast<float4*>(&s_H[(ct+r)*68 + nt]) = o;
        }
    }
    __syncthreads();

    {
        float acc[16];
#pragma unroll
        for (int r = 0; r < 4; r++) {
            float bv = __ldg(&bf2[ct+r]);
#pragma unroll
            for (int jj = 0; jj < 4; jj++) acc[r*4+jj] = bv;
        }
#pragma unroll 4
        for (int cp = 0; cp < 64; cp++) {
            float4 wv = __ldg(reinterpret_cast<const float4*>(&g_wf2T[cp*64 + ct]));
            float4 hv = *reinterpret_cast<const float4*>(&s_H[cp*68 + nt]);
            acc[0]  += wv.x*hv.x; acc[1]  += wv.x*hv.y; acc[2]  += wv.x*hv.z; acc[3]  += wv.x*hv.w;
            acc[4]  += wv.y*hv.x; acc[5]  += wv.y*hv.y; acc[6]  += wv.y*hv.z; acc[7]  += wv.y*hv.w;
            acc[8]  += wv.z*hv.x; acc[9]  += wv.z*hv.y; acc[10] += wv.z*hv.z; acc[11] += wv.z*hv.w;
            acc[12] += wv.w*hv.x; acc[13] += wv.w*hv.y; acc[14] += wv.w*hv.z; acc[15] += wv.w*hv.w;
        }
#pragma unroll
        for (int r = 0; r < 4; r++) {
            const float* idn = &s_F1[(ct+r)*68 + nt];
            float4 o;
            o.x = fmaxf(acc[r*4+0] + idn[0], 0.0f);
            o.y = fmaxf(acc[r*4+1] + idn[1], 0.0f);
            o.z = fmaxf(acc[r*4+2] + idn[2], 0.0f);
            o.w = fmaxf(acc[r*4+3] + idn[3], 0.0f);
            *reinterpret_cast<float4*>(&outF[((size_t)b*CC + ct + r)*NN + n0g + nt]) = o;
        }
    }
}

// ---------------- launch ----------------
extern "C" void kernel_launch(void* const* d_in, const int* in_sizes, int n_in,
                              void* d_out, int out_size) {
    const float* p      = (const float*)d_in[0];
    const float* f      = (const float*)d_in[1];
    const float* w_attn = (const float*)d_in[2];
    const float* b_attn = (const float*)d_in[3];
    const float* w1     = (const float*)d_in[4];
    const float* b1     = (const float*)d_in[5];
    const float* w2     = (const float*)d_in[6];
    const float* b2     = (const float*)d_in[7];
    const float* wf1    = (const float*)d_in[8];
    const float* bf1    = (const float*)d_in[9];
    const float* wf2    = (const float*)d_in[10];
    const float* bf2    = (const float*)d_in[11];
    float* out = (float*)d_out;

    cudaMemcpyAsync(out, p, (size_t)BB*NN*3*sizeof(float), cudaMemcpyDeviceToDevice);

    prep_kernel<<<1, 256>>>(w_attn, w1, w2, wf1, wf2);
    ga_kernel<<<BB*(NN/64), 256>>>(f, w_attn, b_attn, w1, b1);

    int bq_smem = (3*NN + 16*KK) * (int)sizeof(float);
    cudaFuncSetAttribute(bq_kernel, cudaFuncAttributeMaxDynamicSharedMemorySize, bq_smem);
    bq_kernel<<<BB*(NN/16), 512, bq_smem>>>(p);

    cudaFuncSetAttribute(main_kernel, cudaFuncAttributeMaxDynamicSharedMemorySize, SM_TOT);
    main_kernel<<<BB*NN/4, 256, SM_TOT>>>(p, b2);

    tail_kernel<<<BB*(NN/64), 256>>>(f, bf1, bf2, out + (size_t)BB*NN*3);
}

// round 5
// speedup vs baseline: 1.9066x; 1.1996x over previous
#include <cuda_runtime.h>
#include <cuda_fp16.h>
#include <cstdint>
#include <cstddef>

#define BB  8
#define NN  4096
#define KK  32
#define CC  64
#define CIN 67

// -------- scratch (no allocation allowed -> __device__ globals) --------
__device__ __align__(16) float g_G[(size_t)BB*NN*128]; // merged [b][j][0:64]=GA, [64:128]=G1
__device__ __align__(16) float g_F0[(size_t)BB*NN*CC]; // attention output (pre-residual), [b, n, c]
__device__ int   g_idx[(size_t)BB*NN*KK];              // ball-query neighbor indices
__device__ __align__(16) float g_wD3[3*128];           // [d][u]: u<64 -> w_attn[u][d], else w1[u-64][d]
__device__ __align__(16) float g_w2T[CC*CC];           // w2 transposed: [cp][c]
__device__ __align__(16) float g_wf1T[CC*CC];          // wf1 transposed [cp][c]
__device__ __align__(16) float g_wf2T[CC*CC];          // wf2 transposed [cp][c]

// ---------------- helpers: packed f32x2 FMA ----------------
__device__ __forceinline__ unsigned long long pack2(float lo, float hi) {
    unsigned long long r;
    asm("mov.b64 %0, {%1, %2};" : "=l"(r) : "f"(lo), "f"(hi));
    return r;
}
__device__ __forceinline__ float2 unpack2(unsigned long long v) {
    float2 r;
    asm("mov.b64 {%0, %1}, %2;" : "=f"(r.x), "=f"(r.y) : "l"(v));
    return r;
}
__device__ __forceinline__ void fma2(unsigned long long &acc, unsigned long long a, unsigned long long b) {
    asm("fma.rn.f32x2 %0, %1, %2, %3;" : "=l"(acc) : "l"(a), "l"(b), "l"(acc));
}

// merging butterfly: after HALF=16,8,4,2,1 on v[32], lane l holds full lane-sum of v[l].
template<int HALF>
__device__ __forceinline__ void merge_step(float* v, int lane) {
    bool up = (lane & HALF) != 0;
#pragma unroll
    for (int i = 0; i < HALF; i++) {
        float sel = up ? v[i] : v[HALF + i];
        float r = __shfl_xor_sync(0xffffffffu, sel, HALF);
        v[i] = (up ? v[HALF + i] : v[i]) + r;
    }
}

// ================== fused pre-kernel: ga | bq | p-copy | prep ==================
// grid: [0,512) ga, [512,2560) bq, [2560,2592) copy, 2592 prep. block=512, dynsmem=51200B.
#define PRE_SMEM 51200

__global__ void __launch_bounds__(512) fused_pre(
        const float* __restrict__ p, const float* __restrict__ f,
        const float* __restrict__ w_attn, const float* __restrict__ b_attn,
        const float* __restrict__ w1, const float* __restrict__ b1,
        const float* __restrict__ w2,
        const float* __restrict__ wf1, const float* __restrict__ wf2,
        float* __restrict__ out) {
    extern __shared__ float sm[];
    int blk = blockIdx.x;
    int tid = threadIdx.x;

    if (blk < 512) {
        // ---------- ga: GA/G1 precompute -> merged g_G rows ----------
        float* s_f  = sm;
        float* s_wa = sm + 4096;   // s_wa[i*64 + c] = w_attn[c, 3+i]
        float* s_w1 = sm + 8192;
        int b  = blk >> 6;
        int j0 = (blk & 63) << 6;

        for (int lin = tid; lin < 64*64; lin += 512) {
            int i = lin >> 6, c = lin & 63;
            s_wa[i*64 + c] = w_attn[c*CIN + 3 + i];
            s_w1[i*64 + c] = w1[c*CIN + 3 + i];
        }
        for (int lin = tid; lin < 64*64; lin += 512) {
            int i = lin >> 6, jj = lin & 63;
            s_f[i*64 + jj] = f[((size_t)b*CC + i)*NN + j0 + jj];
        }
        __syncthreads();

        int j  = tid & 63;
        int c0 = (tid >> 6) << 3;       // 8 channels per thread (512 threads)
        float accA[8], acc1[8];
#pragma unroll
        for (int q = 0; q < 8; q++) { accA[q] = __ldg(&b_attn[c0+q]); acc1[q] = __ldg(&b1[c0+q]); }

#pragma unroll 4
        for (int i = 0; i < 64; i++) {
            float fv = s_f[i*64 + j];
            const float4* wa = reinterpret_cast<const float4*>(&s_wa[i*64 + c0]);
            const float4* wb = reinterpret_cast<const float4*>(&s_w1[i*64 + c0]);
#pragma unroll
            for (int q = 0; q < 2; q++) {
                float4 a = wa[q], o = wb[q];
                accA[4*q+0] += a.x*fv; accA[4*q+1] += a.y*fv; accA[4*q+2] += a.z*fv; accA[4*q+3] += a.w*fv;
                acc1[4*q+0] += o.x*fv; acc1[4*q+1] += o.y*fv; acc1[4*q+2] += o.z*fv; acc1[4*q+3] += o.w*fv;
            }
        }
        size_t base = ((size_t)b*NN + j0 + j)*128 + c0;
        *reinterpret_cast<float4*>(&g_G[base + 0]) = make_float4(accA[0],accA[1],accA[2],accA[3]);
        *reinterpret_cast<float4*>(&g_G[base + 4]) = make_float4(accA[4],accA[5],accA[6],accA[7]);
        *reinterpret_cast<float4*>(&g_G[base + 64]) = make_float4(acc1[0],acc1[1],acc1[2],acc1[3]);
        *reinterpret_cast<float4*>(&g_G[base + 68]) = make_float4(acc1[4],acc1[5],acc1[6],acc1[7]);

    } else if (blk < 2560) {
        // ---------- bq: ball query, one warp per query ----------
        int bb = blk - 512;
        float* s_px = sm;
        float* s_py = sm + NN;
        float* s_pz = sm + 2*NN;
        int*   s_idx = reinterpret_cast<int*>(sm + 3*NN);   // [16 warps][KK]

        int b     = bb >> 8;
        int nbase = (bb & 255) << 4;
        const float* pb = p + (size_t)b*NN*3;
        for (int jj = tid; jj < NN; jj += 512) {
            s_px[jj] = pb[jj*3+0];
            s_py[jj] = pb[jj*3+1];
            s_pz[jj] = pb[jj*3+2];
        }
        __syncthreads();

        int wi = tid >> 5, lane = tid & 31;
        int n = nbase + wi;
        float xn = s_px[n], yn = s_py[n], zn = s_pz[n];
        float sqn = __fadd_rn(__fadd_rn(__fmul_rn(xn,xn), __fmul_rn(yn,yn)), __fmul_rn(zn,zn));
        const float r2 = (float)(0.15*0.15);
        int* my = s_idx + wi*KK;

        int cnt = 0;
        for (int base = 0; base < NN && cnt < KK; base += 32) {
            int jj = base + lane;
            float xj = s_px[jj], yj = s_py[jj], zj = s_pz[jj];
            float sqj = __fadd_rn(__fadd_rn(__fmul_rn(xj,xj), __fmul_rn(yj,yj)), __fmul_rn(zj,zj));
            float dt  = __fadd_rn(__fadd_rn(__fmul_rn(xn,xj), __fmul_rn(yn,yj)), __fmul_rn(zn,zj));
            float d2  = __fsub_rn(__fadd_rn(sqn, sqj), __fmul_rn(2.0f, dt));
            bool within = (d2 <= r2);
            unsigned m = __ballot_sync(0xffffffffu, within);
            int pos = cnt + __popc(m & ((1u << lane) - 1u));
            if (within && pos < KK) my[pos] = jj;
            cnt += __popc(m);
        }
        __syncwarp();
        if (cnt > KK) cnt = KK;
        int v = my[(lane < cnt) ? lane : 0];
        g_idx[((size_t)b*NN + n)*KK + lane] = v;

    } else if (blk < 2592) {
        // ---------- p passthrough copy into out[0 : B*N*3) ----------
        int cb = blk - 2560;
        const float4* src = reinterpret_cast<const float4*>(p);
        float4* dst = reinterpret_cast<float4*>(out);
        int lo = cb*768, hi = lo + 768;    // 32 blocks x 768 float4 = 24576
        for (int i = lo + tid; i < hi; i += 512) dst[i] = src[i];

    } else {
        // ---------- prep: weight repack ----------
        for (int i = tid; i < 3*128; i += 512) {
            int d = i / 128, u = i % 128;
            g_wD3[i] = (u < 64) ? w_attn[u*CIN + d] : w1[(u-64)*CIN + d];
        }
        for (int i = tid; i < CC*CC; i += 512) {
            int c = i / CC, cp = i % CC;
            g_w2T[cp*CC + c]  = w2[i];
            g_wf1T[cp*CC + c] = wf1[i];
            g_wf2T[cp*CC + c] = wf2[i];
        }
    }
}

// ---------------- fused main: 4 points/block, 3 blocks/SM ----------------
// dyn smem layout:
//   s_w2T : float [0, 4096)                        (16384 B)
//   s_R   : float 4096 + pt*2048, R[cp][(k+cp)&31] (32768 B)
//   s_E   : half  @byte 49152, pt*2304 halves, E[k][c] pitch 72 halves (18432 B)
//   s_meta: float4 @float 16896                    (2048 B)
#define SM_MAIN 69632

__device__ __forceinline__ void epilogue_point(const unsigned long long* X,
        const __half* Erow /* = E_pt + lane*72 + c0 */,
        float* outp, int lane) {
    const __half2* Eh = reinterpret_cast<const __half2*>(Erow);
    float v[32];
#pragma unroll
    for (int q = 0; q < 8; q++) {
        float2 ef = __half22float2(Eh[q]);
        float2 xv = unpack2(X[q]);
        v[2*q+0]    = ef.x * xv.x;
        v[2*q+1]    = ef.y * xv.y;
        v[16+2*q+0] = ef.x;
        v[16+2*q+1] = ef.y;
    }
    merge_step<16>(v, lane);
    merge_step<8>(v, lane);
    merge_step<4>(v, lane);
    merge_step<2>(v, lane);
    merge_step<1>(v, lane);
    float den = __shfl_xor_sync(0xffffffffu, v[0], 16);
    if (lane < 16) outp[lane] = v[0] / den;
}

__global__ void __launch_bounds__(256, 3) main_kernel(const float* __restrict__ p,
        const float* __restrict__ b2) {
    extern __shared__ float sm[];
    float*  s_w2T  = sm;
    float4* s_meta = reinterpret_cast<float4*>(sm + 16896);
    __half* s_Eb   = reinterpret_cast<__half*>(reinterpret_cast<char*>(sm) + 49152);

    int tid  = threadIdx.x;
    int w    = tid >> 5;
    int lane = tid & 31;
    int pbase = blockIdx.x * 4;

    // stage w2T (pre-transposed) via clean float4 copies
    for (int i = tid; i < 1024; i += 256)
        reinterpret_cast<float4*>(s_w2T)[i] = reinterpret_cast<const float4*>(g_w2T)[i];

    // meta: warps 0..3 stage (dp, j) for point w
    if (w < 4) {
        int pid = pbase + w;
        int b = pid >> 12, n = pid & 4095;
        int j = g_idx[(size_t)pid*KK + lane];
        const float* pn = p + ((size_t)b*NN + n)*3;
        const float* pj = p + ((size_t)b*NN + j)*3;
        float4 m;
        m.x = pj[0] - pn[0];
        m.y = pj[1] - pn[1];
        m.z = pj[2] - pn[2];
        m.w = __int_as_float(j);
        s_meta[w*32 + lane] = m;
    }
    __syncthreads();

    // ---- phase 1: gather + at/exp/R, warp = (pt = w&3, k-half = w>>2) ----
    {
        int pt = w & 3;
        int k0 = (w >> 2) * 16;
        int pid = pbase + pt;
        int b = pid >> 12;
        int u = lane * 4;              // unified channel index: <64 GA(->E), >=64 G1(->R)
        bool isE = (lane < 16);
        float4 wx = *reinterpret_cast<const float4*>(&g_wD3[0*128 + u]);
        float4 wy = *reinterpret_cast<const float4*>(&g_wD3[1*128 + u]);
        float4 wz = *reinterpret_cast<const float4*>(&g_wD3[2*128 + u]);
        float*  Rp = sm + 4096 + pt*2048;
        __half* Ep = s_Eb + pt*2304;
        const float* Gb = g_G + (size_t)b*NN*128;
        int cpb = u - 64;

#pragma unroll 4
        for (int kk = 0; kk < 16; kk++) {
            int k = k0 + kk;
            float4 m = s_meta[pt*32 + k];
            int j = __float_as_int(m.w);
            float4 g = __ldg(reinterpret_cast<const float4*>(&Gb[(size_t)j*128 + u]));
            float4 v;
            v.x = g.x + wx.x*m.x + wy.x*m.y + wz.x*m.z;
            v.y = g.y + wx.y*m.x + wy.y*m.y + wz.y*m.z;
            v.z = g.z + wx.z*m.x + wy.z*m.y + wz.z*m.z;
            v.w = g.w + wx.w*m.x + wy.w*m.y + wz.w*m.z;
            if (isE) {
                union { __half2 h[2]; uint2 u2; } cv;
                cv.h[0] = __floats2half2_rn(__expf(v.x), __expf(v.y));
                cv.h[1] = __floats2half2_rn(__expf(v.z), __expf(v.w));
                *reinterpret_cast<uint2*>(&Ep[k*72 + u]) = cv.u2;
            } else {
                Rp[(cpb+0)*32 + ((k+cpb+0)&31)] = fmaxf(v.x, 0.0f);
                Rp[(cpb+1)*32 + ((k+cpb+1)&31)] = fmaxf(v.y, 0.0f);
                Rp[(cpb+2)*32 + ((k+cpb+2)&31)] = fmaxf(v.z, 0.0f);
                Rp[(cpb+3)*32 + ((k+cpb+3)&31)] = fmaxf(v.w, 0.0f);
            }
        }
    }
    __syncthreads();

    // ---- phase 2: GEMM (point-paired) + softmax-weighted reduction ----
    {
        int cs = w & 3, pp = w >> 2;
        int c0 = cs << 4;
        int ptA = 2*pp, ptB = 2*pp + 1;
        const float* RA = sm + 4096 + ptA*2048;
        const float* RB = sm + 4096 + ptB*2048;

        unsigned long long XA[8], XB[8];
#pragma unroll
        for (int q = 0; q < 8; q++) {
            unsigned long long bi = pack2(__ldg(&b2[c0+2*q]), __ldg(&b2[c0+2*q+1]));
            XA[q] = bi; XB[q] = bi;
        }

#pragma unroll 4
        for (int cp = 0; cp < 64; cp++) {
            const ulonglong2* wr = reinterpret_cast<const ulonglong2*>(&s_w2T[cp*64 + c0]);
            ulonglong2 w01 = wr[0], w23 = wr[1], w45 = wr[2], w67 = wr[3];
            int slot = (lane + cp) & 31;
            float rA = RA[cp*32 + slot];
            float rB = RB[cp*32 + slot];
            unsigned long long rA2 = pack2(rA, rA);
            unsigned long long rB2 = pack2(rB, rB);
            fma2(XA[0], w01.x, rA2); fma2(XA[1], w01.y, rA2);
            fma2(XA[2], w23.x, rA2); fma2(XA[3], w23.y, rA2);
            fma2(XA[4], w45.x, rA2); fma2(XA[5], w45.y, rA2);
            fma2(XA[6], w67.x, rA2); fma2(XA[7], w67.y, rA2);
            fma2(XB[0], w01.x, rB2); fma2(XB[1], w01.y, rB2);
            fma2(XB[2], w23.x, rB2); fma2(XB[3], w23.y, rB2);
            fma2(XB[4], w45.x, rB2); fma2(XB[5], w45.y, rB2);
            fma2(XB[6], w67.x, rB2); fma2(XB[7], w67.y, rB2);
        }

        epilogue_point(XA, s_Eb + ptA*2304 + lane*72 + c0,
                       g_F0 + (size_t)(pbase + ptA)*CC + c0, lane);
        epilogue_point(XB, s_Eb + ptB*2304 + lane*72 + c0,
                       g_F0 + (size_t)(pbase + ptB)*CC + c0, lane);
    }
}

// ---------------- tail: relu(F0+f) -> 2x (64x64) MLP -> relu residual ----------------
__global__ void __launch_bounds__(256) tail_kernel(const float* __restrict__ f,
        const float* __restrict__ bf1, const float* __restrict__ bf2,
        float* __restrict__ outF) {
    __shared__ float s_F1[64*68];
    __shared__ float s_H[64*68];

    int b   = blockIdx.x >> 6;
    int n0g = (blockIdx.x & 63) << 6;
    int tid = threadIdx.x;

    {
        int c = tid >> 2, q = tid & 3;
        const float* frow = f + ((size_t)b*CC + c)*NN + n0g;
        const float* f0b  = g_F0 + ((size_t)b*NN + n0g)*CC + c;
#pragma unroll
        for (int i = 0; i < 4; i++) {
            int nn = q*16 + i*4;
            float4 fv = *reinterpret_cast<const float4*>(frow + nn);
            float a0 = __ldg(&f0b[(nn+0)*CC]);
            float a1 = __ldg(&f0b[(nn+1)*CC]);
            float a2 = __ldg(&f0b[(nn+2)*CC]);
            float a3 = __ldg(&f0b[(nn+3)*CC]);
            float4 r;
            r.x = fmaxf(a0 + fv.x, 0.0f);
            r.y = fmaxf(a1 + fv.y, 0.0f);
            r.z = fmaxf(a2 + fv.z, 0.0f);
            r.w = fmaxf(a3 + fv.w, 0.0f);
            *reinterpret_cast<float4*>(&s_F1[c*68 + nn]) = r;
        }
    }
    __syncthreads();

    int ct = (tid >> 4) << 2;
    int nt = (tid & 15) << 2;

    {
        float acc[16];
#pragma unroll
        for (int r = 0; r < 4; r++) {
            float bv = __ldg(&bf1[ct+r]);
#pragma unroll
            for (int jj = 0; jj < 4; jj++) acc[r*4+jj] = bv;
        }
#pragma unroll 4
        for (int cp = 0; cp < 64; cp++) {
            float4 wv = __ldg(reinterpret_cast<const float4*>(&g_wf1T[cp*64 + ct]));
            float4 fv = *reinterpret_cast<const float4*>(&s_F1[cp*68 + nt]);
            acc[0]  += wv.x*fv.x; acc[1]  += wv.x*fv.y; acc[2]  += wv.x*fv.z; acc[3]  += wv.x*fv.w;
            acc[4]  += wv.y*fv.x; acc[5]  += wv.y*fv.y; acc[6]  += wv.y*fv.z; acc[7]  += wv.y*fv.w;
            acc[8]  += wv.z*fv.x; acc[9]  += wv.z*fv.y; acc[10] += wv.z*fv.z; acc[11] += wv.z*fv.w;
            acc[12] += wv.w*fv.x; acc[13] += wv.w*fv.y; acc[14] += wv.w*fv.z; acc[15] += wv.w*fv.w;
        }
#pragma unroll
        for (int r = 0; r < 4; r++) {
            float4 o;
            o.x = fmaxf(acc[r*4+0], 0.0f);
            o.y = fmaxf(acc[r*4+1], 0.0f);
            o.z = fmaxf(acc[r*4+2], 0.0f);
            o.w = fmaxf(acc[r*4+3], 0.0f);
            *reinterpret_cast<float4*>(&s_H[(ct+r)*68 + nt]) = o;
        }
    }
    __syncthreads();

    {
        float acc[16];
#pragma unroll
        for (int r = 0; r < 4; r++) {
            float bv = __ldg(&bf2[ct+r]);
#pragma unroll
            for (int jj = 0; jj < 4; jj++) acc[r*4+jj] = bv;
        }
#pragma unroll 4
        for (int cp = 0; cp < 64; cp++) {
            float4 wv = __ldg(reinterpret_cast<const float4*>(&g_wf2T[cp*64 + ct]));
            float4 hv = *reinterpret_cast<const float4*>(&s_H[cp*68 + nt]);
            acc[0]  += wv.x*hv.x; acc[1]  += wv.x*hv.y; acc[2]  += wv.x*hv.z; acc[3]  += wv.x*hv.w;
            acc[4]  += wv.y*hv.x; acc[5]  += wv.y*hv.y; acc[6]  += wv.y*hv.z; acc[7]  += wv.y*hv.w;
            acc[8]  += wv.z*hv.x; acc[9]  += wv.z*hv.y; acc[10] += wv.z*hv.z; acc[11] += wv.z*hv.w;
            acc[12] += wv.w*hv.x; acc[13] += wv.w*hv.y; acc[14] += wv.w*hv.z; acc[15] += wv.w*hv.w;
        }
#pragma unroll
        for (int r = 0; r < 4; r++) {
            const float* idn = &s_F1[(ct+r)*68 + nt];
            float4 o;
            o.x = fmaxf(acc[r*4+0] + idn[0], 0.0f);
            o.y = fmaxf(acc[r*4+1] + idn[1], 0.0f);
            o.z = fmaxf(acc[r*4+2] + idn[2], 0.0f);
            o.w = fmaxf(acc[r*4+3] + idn[3], 0.0f);
            *reinterpret_cast<float4*>(&outF[((size_t)b*CC + ct + r)*NN + n0g + nt]) = o;
        }
    }
}

// ---------------- launch ----------------
extern "C" void kernel_launch(void* const* d_in, const int* in_sizes, int n_in,
                              void* d_out, int out_size) {
    const float* p      = (const float*)d_in[0];
    const float* f      = (const float*)d_in[1];
    const float* w_attn = (const float*)d_in[2];
    const float* b_attn = (const float*)d_in[3];
    const float* w1     = (const float*)d_in[4];
    const float* b1     = (const float*)d_in[5];
    const float* w2     = (const float*)d_in[6];
    const float* b2     = (const float*)d_in[7];
    const float* wf1    = (const float*)d_in[8];
    const float* bf1    = (const float*)d_in[9];
    const float* wf2    = (const float*)d_in[10];
    const float* bf2    = (const float*)d_in[11];
    float* out = (float*)d_out;

    cudaFuncSetAttribute(fused_pre, cudaFuncAttributeMaxDynamicSharedMemorySize, PRE_SMEM);
    fused_pre<<<2593, 512, PRE_SMEM>>>(p, f, w_attn, b_attn, w1, b1, w2, wf1, wf2, out);

    cudaFuncSetAttribute(main_kernel, cudaFuncAttributeMaxDynamicSharedMemorySize, SM_MAIN);
    main_kernel<<<BB*NN/4, 256, SM_MAIN>>>(p, b2);

    tail_kernel<<<BB*(NN/64), 256>>>(f, bf1, bf2, out + (size_t)BB*NN*3);
}

// round 6
// speedup vs baseline: 1.9902x; 1.0438x over previous
#include <cuda_runtime.h>
#include <cuda_fp16.h>
#include <cstdint>
#include <cstddef>

#define BB  8
#define NN  4096
#define KK  32
#define CC  64
#define CIN 67

// -------- scratch (no allocation allowed -> __device__ globals) --------
__device__ __align__(16) float g_G[(size_t)BB*NN*128]; // merged [b][j][0:64]=GA, [64:128]=G1
__device__ __align__(16) float g_F0[(size_t)BB*NN*CC]; // attention output (pre-residual), [b, n, c]
__device__ int   g_idx[(size_t)BB*NN*KK];              // ball-query neighbor indices
__device__ __align__(16) float g_wD3[3*128];           // [d][u]: u<64 -> w_attn[u][d], else w1[u-64][d]
__device__ __align__(16) float g_w2T[CC*CC];           // w2 transposed: [cp][c]
__device__ __align__(16) float g_wf1T[CC*CC];          // wf1 transposed [cp][c]
__device__ __align__(16) float g_wf2T[CC*CC];          // wf2 transposed [cp][c]

// ---------------- helpers: packed f32x2 FMA ----------------
__device__ __forceinline__ unsigned long long pack2(float lo, float hi) {
    unsigned long long r;
    asm("mov.b64 %0, {%1, %2};" : "=l"(r) : "f"(lo), "f"(hi));
    return r;
}
__device__ __forceinline__ float2 unpack2(unsigned long long v) {
    float2 r;
    asm("mov.b64 {%0, %1}, %2;" : "=f"(r.x), "=f"(r.y) : "l"(v));
    return r;
}
__device__ __forceinline__ void fma2(unsigned long long &acc, unsigned long long a, unsigned long long b) {
    asm("fma.rn.f32x2 %0, %1, %2, %3;" : "=l"(acc) : "l"(a), "l"(b), "l"(acc));
}

// merging butterfly: after HALF=16,8,4,2,1 on v[32], lane l holds full lane-sum of v[l].
template<int HALF>
__device__ __forceinline__ void merge_step(float* v, int lane) {
    bool up = (lane & HALF) != 0;
#pragma unroll
    for (int i = 0; i < HALF; i++) {
        float sel = up ? v[i] : v[HALF + i];
        float r = __shfl_xor_sync(0xffffffffu, sel, HALF);
        v[i] = (up ? v[HALF + i] : v[i]) + r;
    }
}

// ================== fused pre-kernel: ga | bq | p-copy | prep ==================
// grid: [0,512) ga, [512,2560) bq, [2560,2592) copy, 2592 prep. block=512.
#define PRE_SMEM 67584

__global__ void __launch_bounds__(512) fused_pre(
        const float* __restrict__ p, const float* __restrict__ f,
        const float* __restrict__ w_attn, const float* __restrict__ b_attn,
        const float* __restrict__ w1, const float* __restrict__ b1,
        const float* __restrict__ w2,
        const float* __restrict__ wf1, const float* __restrict__ wf2,
        float* __restrict__ out) {
    extern __shared__ float sm[];
    int blk = blockIdx.x;
    int tid = threadIdx.x;

    if (blk < 512) {
        // ---------- ga: GA/G1 precompute -> merged g_G rows ----------
        float* s_f  = sm;
        float* s_wa = sm + 4096;   // s_wa[i*64 + c] = w_attn[c, 3+i]
        float* s_w1 = sm + 8192;
        int b  = blk >> 6;
        int j0 = (blk & 63) << 6;

        for (int lin = tid; lin < 64*64; lin += 512) {
            int i = lin >> 6, c = lin & 63;
            s_wa[i*64 + c] = w_attn[c*CIN + 3 + i];
            s_w1[i*64 + c] = w1[c*CIN + 3 + i];
        }
        for (int lin = tid; lin < 64*64; lin += 512) {
            int i = lin >> 6, jj = lin & 63;
            s_f[i*64 + jj] = f[((size_t)b*CC + i)*NN + j0 + jj];
        }
        __syncthreads();

        int j  = tid & 63;
        int c0 = (tid >> 6) << 3;       // 8 channels per thread (512 threads)
        float accA[8], acc1[8];
#pragma unroll
        for (int q = 0; q < 8; q++) { accA[q] = __ldg(&b_attn[c0+q]); acc1[q] = __ldg(&b1[c0+q]); }

#pragma unroll 4
        for (int i = 0; i < 64; i++) {
            float fv = s_f[i*64 + j];
            const float4* wa = reinterpret_cast<const float4*>(&s_wa[i*64 + c0]);
            const float4* wb = reinterpret_cast<const float4*>(&s_w1[i*64 + c0]);
#pragma unroll
            for (int q = 0; q < 2; q++) {
                float4 a = wa[q], o = wb[q];
                accA[4*q+0] += a.x*fv; accA[4*q+1] += a.y*fv; accA[4*q+2] += a.z*fv; accA[4*q+3] += a.w*fv;
                acc1[4*q+0] += o.x*fv; acc1[4*q+1] += o.y*fv; acc1[4*q+2] += o.z*fv; acc1[4*q+3] += o.w*fv;
            }
        }
        size_t base = ((size_t)b*NN + j0 + j)*128 + c0;
        *reinterpret_cast<float4*>(&g_G[base + 0]) = make_float4(accA[0],accA[1],accA[2],accA[3]);
        *reinterpret_cast<float4*>(&g_G[base + 4]) = make_float4(accA[4],accA[5],accA[6],accA[7]);
        *reinterpret_cast<float4*>(&g_G[base + 64]) = make_float4(acc1[0],acc1[1],acc1[2],acc1[3]);
        *reinterpret_cast<float4*>(&g_G[base + 68]) = make_float4(acc1[4],acc1[5],acc1[6],acc1[7]);

    } else if (blk < 2560) {
        // ---------- bq: ball query, one warp per query, float4 (x,y,z,|p|^2) cache ----------
        int bb = blk - 512;
        float4* s_p4 = reinterpret_cast<float4*>(sm);           // [NN]
        int*    s_idx = reinterpret_cast<int*>(sm + 4*NN);      // [16 warps][KK]

        int b     = bb >> 8;
        int nbase = (bb & 255) << 4;
        const float* pb = p + (size_t)b*NN*3;
        for (int jj = tid; jj < NN; jj += 512) {
            float x = pb[jj*3+0], y = pb[jj*3+1], z = pb[jj*3+2];
            // identical rounding to the reference's sq computation
            float sq = __fadd_rn(__fadd_rn(__fmul_rn(x,x), __fmul_rn(y,y)), __fmul_rn(z,z));
            s_p4[jj] = make_float4(x, y, z, sq);
        }
        __syncthreads();

        int wi = tid >> 5, lane = tid & 31;
        int n = nbase + wi;
        float4 pn = s_p4[n];
        float xn = pn.x, yn = pn.y, zn = pn.z, sqn = pn.w;
        const float r2 = (float)(0.15*0.15);
        int* my = s_idx + wi*KK;

        int cnt = 0;
        for (int base = 0; base < NN && cnt < KK; base += 32) {
            float4 pj = s_p4[base + lane];
            float dt  = __fadd_rn(__fadd_rn(__fmul_rn(xn,pj.x), __fmul_rn(yn,pj.y)), __fmul_rn(zn,pj.z));
            float d2  = __fsub_rn(__fadd_rn(sqn, pj.w), __fmul_rn(2.0f, dt));
            bool within = (d2 <= r2);
            unsigned m = __ballot_sync(0xffffffffu, within);
            int pos = cnt + __popc(m & ((1u << lane) - 1u));
            if (within && pos < KK) my[pos] = base + lane;
            cnt += __popc(m);
        }
        __syncwarp();
        if (cnt > KK) cnt = KK;
        int v = my[(lane < cnt) ? lane : 0];
        g_idx[((size_t)b*NN + n)*KK + lane] = v;

    } else if (blk < 2592) {
        // ---------- p passthrough copy into out[0 : B*N*3) ----------
        int cb = blk - 2560;
        const float4* src = reinterpret_cast<const float4*>(p);
        float4* dst = reinterpret_cast<float4*>(out);
        int lo = cb*768, hi = lo + 768;    // 32 blocks x 768 float4 = 24576
        for (int i = lo + tid; i < hi; i += 512) dst[i] = src[i];

    } else {
        // ---------- prep: weight repack ----------
        for (int i = tid; i < 3*128; i += 512) {
            int d = i / 128, u = i % 128;
            g_wD3[i] = (u < 64) ? w_attn[u*CIN + d] : w1[(u-64)*CIN + d];
        }
        for (int i = tid; i < CC*CC; i += 512) {
            int c = i / CC, cp = i % CC;
            g_w2T[cp*CC + c]  = w2[i];
            g_wf1T[cp*CC + c] = wf1[i];
            g_wf2T[cp*CC + c] = wf2[i];
        }
    }
}

// ---------------- fused main: 4 points/block, 3 blocks/SM ----------------
// dyn smem layout:
//   s_w2T : float [0, 4096)                         (16384 B)
//   s_R   : float 4096 + pt*2176, R[k][cp] pitch 68 (34816 B)
//   s_meta: float4 @float 12800                     ( 2048 B)
//   s_E   : half  @byte 53248, pt*2304 halves, E[k][c] pitch 72 (18432 B)
#define SM_MAIN 71680

__device__ __forceinline__ void epilogue_point(const unsigned long long* X,
        const __half* Erow /* = E_pt + lane*72 + c0 */,
        float* outp, int lane) {
    const __half2* Eh = reinterpret_cast<const __half2*>(Erow);
    float v[32];
#pragma unroll
    for (int q = 0; q < 8; q++) {
        float2 ef = __half22float2(Eh[q]);
        float2 xv = unpack2(X[q]);
        v[2*q+0]    = ef.x * xv.x;
        v[2*q+1]    = ef.y * xv.y;
        v[16+2*q+0] = ef.x;
        v[16+2*q+1] = ef.y;
    }
    merge_step<16>(v, lane);
    merge_step<8>(v, lane);
    merge_step<4>(v, lane);
    merge_step<2>(v, lane);
    merge_step<1>(v, lane);
    float den = __shfl_xor_sync(0xffffffffu, v[0], 16);
    if (lane < 16) outp[lane] = v[0] / den;
}

__global__ void __launch_bounds__(256, 3) main_kernel(const float* __restrict__ p,
        const float* __restrict__ b2) {
    extern __shared__ float sm[];
    float*  s_w2T  = sm;
    float4* s_meta = reinterpret_cast<float4*>(sm + 12800);
    __half* s_Eb   = reinterpret_cast<__half*>(reinterpret_cast<char*>(sm) + 53248);

    int tid  = threadIdx.x;
    int w    = tid >> 5;
    int lane = tid & 31;
    int pbase = blockIdx.x * 4;

    // stage w2T (pre-transposed) via clean float4 copies
    for (int i = tid; i < 1024; i += 256)
        reinterpret_cast<float4*>(s_w2T)[i] = reinterpret_cast<const float4*>(g_w2T)[i];

    // meta: warps 0..3 stage (dp, j) for point w
    if (w < 4) {
        int pid = pbase + w;
        int b = pid >> 12, n = pid & 4095;
        int j = g_idx[(size_t)pid*KK + lane];
        const float* pn = p + ((size_t)b*NN + n)*3;
        const float* pj = p + ((size_t)b*NN + j)*3;
        float4 m;
        m.x = pj[0] - pn[0];
        m.y = pj[1] - pn[1];
        m.z = pj[2] - pn[2];
        m.w = __int_as_float(j);
        s_meta[w*32 + lane] = m;
    }
    __syncthreads();

    // ---- phase 1: gather + at/exp/R, warp = (pt = w&3, k-half = w>>2) ----
    {
        int pt = w & 3;
        int k0 = (w >> 2) * 16;
        int pid = pbase + pt;
        int b = pid >> 12;
        int u = lane * 4;              // unified channel index: <64 GA(->E), >=64 G1(->R)
        bool isE = (lane < 16);
        float4 wx = *reinterpret_cast<const float4*>(&g_wD3[0*128 + u]);
        float4 wy = *reinterpret_cast<const float4*>(&g_wD3[1*128 + u]);
        float4 wz = *reinterpret_cast<const float4*>(&g_wD3[2*128 + u]);
        float*  Rp = sm + 4096 + pt*2176;
        __half* Ep = s_Eb + pt*2304;
        const float* Gb = g_G + (size_t)b*NN*128;
        int cpb = u - 64;              // R channel base (lanes 16..31): 0,4,...,60

#pragma unroll 4
        for (int kk = 0; kk < 16; kk++) {
            int k = k0 + kk;
            float4 m = s_meta[pt*32 + k];
            int j = __float_as_int(m.w);
            float4 g = __ldg(reinterpret_cast<const float4*>(&Gb[(size_t)j*128 + u]));
            float4 v;
            v.x = g.x + wx.x*m.x + wy.x*m.y + wz.x*m.z;
            v.y = g.y + wx.y*m.x + wy.y*m.y + wz.y*m.z;
            v.z = g.z + wx.z*m.x + wy.z*m.y + wz.z*m.z;
            v.w = g.w + wx.w*m.x + wy.w*m.y + wz.w*m.z;
            if (isE) {
                union { __half2 h[2]; uint2 u2; } cv;
                cv.h[0] = __floats2half2_rn(__expf(v.x), __expf(v.y));
                cv.h[1] = __floats2half2_rn(__expf(v.z), __expf(v.w));
                *reinterpret_cast<uint2*>(&Ep[k*72 + u]) = cv.u2;
            } else {
                // k-major R: one STS.128, conflict-free (16 consecutive float4s)
                *reinterpret_cast<float4*>(&Rp[k*68 + cpb]) =
                    make_float4(fmaxf(v.x, 0.0f), fmaxf(v.y, 0.0f),
                                fmaxf(v.z, 0.0f), fmaxf(v.w, 0.0f));
            }
        }
    }
    __syncthreads();

    // ---- phase 2: GEMM (point-paired) + softmax-weighted reduction; lane = k ----
    {
        int cs = w & 3, pp = w >> 2;
        int c0 = cs << 4;
        int ptA = 2*pp, ptB = 2*pp + 1;
        const float* RA = sm + 4096 + ptA*2176 + lane*68;
        const float* RB = sm + 4096 + ptB*2176 + lane*68;

        unsigned long long XA[8], XB[8];
#pragma unroll
        for (int q = 0; q < 8; q++) {
            unsigned long long bi = pack2(__ldg(&b2[c0+2*q]), __ldg(&b2[c0+2*q+1]));
            XA[q] = bi; XB[q] = bi;
        }

#pragma unroll 4
        for (int cp4 = 0; cp4 < 16; cp4++) {
            float4 rA4 = *reinterpret_cast<const float4*>(RA + cp4*4);
            float4 rB4 = *reinterpret_cast<const float4*>(RB + cp4*4);
            float rAa[4] = {rA4.x, rA4.y, rA4.z, rA4.w};
            float rBa[4] = {rB4.x, rB4.y, rB4.z, rB4.w};
#pragma unroll
            for (int jj = 0; jj < 4; jj++) {
                int cp = cp4*4 + jj;
                const ulonglong2* wr = reinterpret_cast<const ulonglong2*>(&s_w2T[cp*64 + c0]);
                ulonglong2 w01 = wr[0], w23 = wr[1], w45 = wr[2], w67 = wr[3];
                unsigned long long rA2 = pack2(rAa[jj], rAa[jj]);
                unsigned long long rB2 = pack2(rBa[jj], rBa[jj]);
                fma2(XA[0], w01.x, rA2); fma2(XA[1], w01.y, rA2);
                fma2(XA[2], w23.x, rA2); fma2(XA[3], w23.y, rA2);
                fma2(XA[4], w45.x, rA2); fma2(XA[5], w45.y, rA2);
                fma2(XA[6], w67.x, rA2); fma2(XA[7], w67.y, rA2);
                fma2(XB[0], w01.x, rB2); fma2(XB[1], w01.y, rB2);
                fma2(XB[2], w23.x, rB2); fma2(XB[3], w23.y, rB2);
                fma2(XB[4], w45.x, rB2); fma2(XB[5], w45.y, rB2);
                fma2(XB[6], w67.x, rB2); fma2(XB[7], w67.y, rB2);
            }
        }

        epilogue_point(XA, s_Eb + ptA*2304 + lane*72 + c0,
                       g_F0 + (size_t)(pbase + ptA)*CC + c0, lane);
        epilogue_point(XB, s_Eb + ptB*2304 + lane*72 + c0,
                       g_F0 + (size_t)(pbase + ptB)*CC + c0, lane);
    }
}

// ---------------- tail: relu(F0+f) -> 2x (64x64) MLP -> relu residual ----------------
__global__ void __launch_bounds__(256) tail_kernel(const float* __restrict__ f,
        const float* __restrict__ bf1, const float* __restrict__ bf2,
        float* __restrict__ outF) {
    __shared__ float s_F1[64*68];
    __shared__ float s_H[64*68];

    int b   = blockIdx.x >> 6;
    int n0g = (blockIdx.x & 63) << 6;
    int tid = threadIdx.x;

    {
        int c = tid >> 2, q = tid & 3;
        const float* frow = f + ((size_t)b*CC + c)*NN + n0g;
        const float* f0b  = g_F0 + ((size_t)b*NN + n0g)*CC + c;
#pragma unroll
        for (int i = 0; i < 4; i++) {
            int nn = q*16 + i*4;
            float4 fv = *reinterpret_cast<const float4*>(frow + nn);
            float a0 = __ldg(&f0b[(nn+0)*CC]);
            float a1 = __ldg(&f0b[(nn+1)*CC]);
            float a2 = __ldg(&f0b[(nn+2)*CC]);
            float a3 = __ldg(&f0b[(nn+3)*CC]);
            float4 r;
            r.x = fmaxf(a0 + fv.x, 0.0f);
            r.y = fmaxf(a1 + fv.y, 0.0f);
            r.z = fmaxf(a2 + fv.z, 0.0f);
            r.w = fmaxf(a3 + fv.w, 0.0f);
            *reinterpret_cast<float4*>(&s_F1[c*68 + nn]) = r;
        }
    }
    __syncthreads();

    int ct = (tid >> 4) << 2;
    int nt = (tid & 15) << 2;

    {
        float acc[16];
#pragma unroll
        for (int r = 0; r < 4; r++) {
            float bv = __ldg(&bf1[ct+r]);
#pragma unroll
            for (int jj = 0; jj < 4; jj++) acc[r*4+jj] = bv;
        }
#pragma unroll 4
        for (int cp = 0; cp < 64; cp++) {
            float4 wv = __ldg(reinterpret_cast<const float4*>(&g_wf1T[cp*64 + ct]));
            float4 fv = *reinterpret_cast<const float4*>(&s_F1[cp*68 + nt]);
            acc[0]  += wv.x*fv.x; acc[1]  += wv.x*fv.y; acc[2]  += wv.x*fv.z; acc[3]  += wv.x*fv.w;
            acc[4]  += wv.y*fv.x; acc[5]  += wv.y*fv.y; acc[6]  += wv.y*fv.z; acc[7]  += wv.y*fv.w;
            acc[8]  += wv.z*fv.x; acc[9]  += wv.z*fv.y; acc[10] += wv.z*fv.z; acc[11] += wv.z*fv.w;
            acc[12] += wv.w*fv.x; acc[13] += wv.w*fv.y; acc[14] += wv.w*fv.z; acc[15] += wv.w*fv.w;
        }
#pragma unroll
        for (int r = 0; r < 4; r++) {
            float4 o;
            o.x = fmaxf(acc[r*4+0], 0.0f);
            o.y = fmaxf(acc[r*4+1], 0.0f);
            o.z = fmaxf(acc[r*4+2], 0.0f);
            o.w = fmaxf(acc[r*4+3], 0.0f);
            *reinterpret_cast<float4*>(&s_H[(ct+r)*68 + nt]) = o;
        }
    }
    __syncthreads();

    {
        float acc[16];
#pragma unroll
        for (int r = 0; r < 4; r++) {
            float bv = __ldg(&bf2[ct+r]);
#pragma unroll
            for (int jj = 0; jj < 4; jj++) acc[r*4+jj] = bv;
        }
#pragma unroll 4
        for (int cp = 0; cp < 64; cp++) {
            float4 wv = __ldg(reinterpret_cast<const float4*>(&g_wf2T[cp*64 + ct]));
            float4 hv = *reinterpret_cast<const float4*>(&s_H[cp*68 + nt]);
            acc[0]  += wv.x*hv.x; acc[1]  += wv.x*hv.y; acc[2]  += wv.x*hv.z; acc[3]  += wv.x*hv.w;
            acc[4]  += wv.y*hv.x; acc[5]  += wv.y*hv.y; acc[6]  += wv.y*hv.z; acc[7]  += wv.y*hv.w;
            acc[8]  += wv.z*hv.x; acc[9]  += wv.z*hv.y; acc[10] += wv.z*hv.z; acc[11] += wv.z*hv.w;
            acc[12] += wv.w*hv.x; acc[13] += wv.w*hv.y; acc[14] += wv.w*hv.z; acc[15] += wv.w*hv.w;
        }
#pragma unroll
        for (int r = 0; r < 4; r++) {
            const float* idn = &s_F1[(ct+r)*68 + nt];
            float4 o;
            o.x = fmaxf(acc[r*4+0] + idn[0], 0.0f);
            o.y = fmaxf(acc[r*4+1] + idn[1], 0.0f);
            o.z = fmaxf(acc[r*4+2] + idn[2], 0.0f);
            o.w = fmaxf(acc[r*4+3] + idn[3], 0.0f);
            *reinterpret_cast<float4*>(&outF[((size_t)b*CC + ct + r)*NN + n0g + nt]) = o;
        }
    }
}

// ---------------- launch ----------------
extern "C" void kernel_launch(void* const* d_in, const int* in_sizes, int n_in,
                              void* d_out, int out_size) {
    const float* p      = (const float*)d_in[0];
    const float* f      = (const float*)d_in[1];
    const float* w_attn = (const float*)d_in[2];
    const float* b_attn = (const float*)d_in[3];
    const float* w1     = (const float*)d_in[4];
    const float* b1     = (const float*)d_in[5];
    const float* w2     = (const float*)d_in[6];
    const float* b2     = (const float*)d_in[7];
    const float* wf1    = (const float*)d_in[8];
    const float* bf1    = (const float*)d_in[9];
    const float* wf2    = (const float*)d_in[10];
    const float* bf2    = (const float*)d_in[11];
    float* out = (float*)d_out;

    cudaFuncSetAttribute(fused_pre, cudaFuncAttributeMaxDynamicSharedMemorySize, PRE_SMEM);
    fused_pre<<<2593, 512, PRE_SMEM>>>(p, f, w_attn, b_attn, w1, b1, w2, wf1, wf2, out);

    cudaFuncSetAttribute(main_kernel, cudaFuncAttributeMaxDynamicSharedMemorySize, SM_MAIN);
    main_kernel<<<BB*NN/4, 256, SM_MAIN>>>(p, b2);

    tail_kernel<<<BB*(NN/64), 256>>>(f, bf1, bf2, out + (size_t)BB*NN*3);
}

// round 8
// speedup vs baseline: 2.5730x; 1.2928x over previous
#include <cuda_runtime.h>
#include <cuda_fp16.h>
#include <cuda_bf16.h>
#include <cstdint>
#include <cstddef>

#define BB  8
#define NN  4096
#define KK  32
#define CC  64
#define CIN 67

// -------- scratch (no allocation allowed -> __device__ globals) --------
__device__ __align__(16) float g_G[(size_t)BB*NN*128]; // merged [b][j][0:64]=GA, [64:128]=G1
__device__ __align__(16) float g_F0[(size_t)BB*NN*CC]; // attention output (pre-residual), [b, n, c]
__device__ int   g_idx[(size_t)BB*NN*KK];              // ball-query neighbor indices
__device__ __align__(16) float g_wD3[3*128];           // [d][u]: u<64 -> w_attn[u][d], else w1[u-64][d]
__device__ __align__(16) uint32_t g_bfH[2048];         // w2 hi-bf16 B-fragments [kt][nt][lane][2]
__device__ __align__(16) uint32_t g_bfL[2048];         // w2 lo-bf16 residual fragments
__device__ __align__(16) float g_wf1T[CC*CC];          // wf1 transposed [cp][c]
__device__ __align__(16) float g_wf2T[CC*CC];          // wf2 transposed [cp][c]

// ---------------- helpers ----------------
__device__ __forceinline__ uint32_t smem_u32(const void* p_) {
    uint32_t a;
    asm("{ .reg .u64 t; cvta.to.shared.u64 t, %1; cvt.u32.u64 %0, t; }" : "=r"(a) : "l"(p_));
    return a;
}
__device__ __forceinline__ void ldsm_x4(uint32_t* r, uint32_t addr) {
    asm volatile("ldmatrix.sync.aligned.m8n8.x4.shared.b16 {%0,%1,%2,%3}, [%4];"
        : "=r"(r[0]), "=r"(r[1]), "=r"(r[2]), "=r"(r[3]) : "r"(addr));
}
__device__ __forceinline__ void mma_bf16(float* d, const uint32_t* a, uint32_t b0, uint32_t b1) {
    asm volatile("mma.sync.aligned.m16n8k16.row.col.f32.bf16.bf16.f32 "
        "{%0,%1,%2,%3}, {%4,%5,%6,%7}, {%8,%9}, {%0,%1,%2,%3};"
        : "+f"(d[0]), "+f"(d[1]), "+f"(d[2]), "+f"(d[3])
        : "r"(a[0]), "r"(a[1]), "r"(a[2]), "r"(a[3]), "r"(b0), "r"(b1));
}

// ================== fused pre-kernel: ga | bq | p-copy | prep ==================
// grid: [0,512) ga, [512,1024) bq (64 queries/block), [1024,1056) copy, 1056 prep.
#define PRE_SMEM 67584

__global__ void __launch_bounds__(512) fused_pre(
        const float* __restrict__ p, const float* __restrict__ f,
        const float* __restrict__ w_attn, const float* __restrict__ b_attn,
        const float* __restrict__ w1, const float* __restrict__ b1,
        const float* __restrict__ w2,
        const float* __restrict__ wf1, const float* __restrict__ wf2,
        float* __restrict__ out) {
    extern __shared__ float sm[];
    int blk = blockIdx.x;
    int tid = threadIdx.x;

    if (blk < 512) {
        // ---------- ga: GA/G1 precompute -> merged g_G rows ----------
        float* s_f  = sm;
        float* s_wa = sm + 4096;
        float* s_w1 = sm + 8192;
        int b  = blk >> 6;
        int j0 = (blk & 63) << 6;

        for (int lin = tid; lin < 64*64; lin += 512) {
            int i = lin >> 6, c = lin & 63;
            s_wa[i*64 + c] = w_attn[c*CIN + 3 + i];
            s_w1[i*64 + c] = w1[c*CIN + 3 + i];
        }
        for (int lin = tid; lin < 64*64; lin += 512) {
            int i = lin >> 6, jj = lin & 63;
            s_f[i*64 + jj] = f[((size_t)b*CC + i)*NN + j0 + jj];
        }
        __syncthreads();

        int j  = tid & 63;
        int c0 = (tid >> 6) << 3;
        float accA[8], acc1[8];
#pragma unroll
        for (int q = 0; q < 8; q++) { accA[q] = __ldg(&b_attn[c0+q]); acc1[q] = __ldg(&b1[c0+q]); }

#pragma unroll 4
        for (int i = 0; i < 64; i++) {
            float fv = s_f[i*64 + j];
            const float4* wa = reinterpret_cast<const float4*>(&s_wa[i*64 + c0]);
            const float4* wb = reinterpret_cast<const float4*>(&s_w1[i*64 + c0]);
#pragma unroll
            for (int q = 0; q < 2; q++) {
                float4 a = wa[q], o = wb[q];
                accA[4*q+0] += a.x*fv; accA[4*q+1] += a.y*fv; accA[4*q+2] += a.z*fv; accA[4*q+3] += a.w*fv;
                acc1[4*q+0] += o.x*fv; acc1[4*q+1] += o.y*fv; acc1[4*q+2] += o.z*fv; acc1[4*q+3] += o.w*fv;
            }
        }
        size_t base = ((size_t)b*NN + j0 + j)*128 + c0;
        *reinterpret_cast<float4*>(&g_G[base + 0])  = make_float4(accA[0],accA[1],accA[2],accA[3]);
        *reinterpret_cast<float4*>(&g_G[base + 4])  = make_float4(accA[4],accA[5],accA[6],accA[7]);
        *reinterpret_cast<float4*>(&g_G[base + 64]) = make_float4(acc1[0],acc1[1],acc1[2],acc1[3]);
        *reinterpret_cast<float4*>(&g_G[base + 68]) = make_float4(acc1[4],acc1[5],acc1[6],acc1[7]);

    } else if (blk < 1024) {
        // ---------- bq: ball query, 64 queries/block (4 per warp) ----------
        int bb = blk - 512;
        float4* s_p4 = reinterpret_cast<float4*>(sm);
        int*    s_idx = reinterpret_cast<int*>(sm + 4*NN);

        int b     = bb >> 6;
        int nbase = (bb & 63) << 6;
        const float* pb = p + (size_t)b*NN*3;
        for (int jj = tid; jj < NN; jj += 512) {
            float x = pb[jj*3+0], y = pb[jj*3+1], z = pb[jj*3+2];
            float sq = __fadd_rn(__fadd_rn(__fmul_rn(x,x), __fmul_rn(y,y)), __fmul_rn(z,z));
            s_p4[jj] = make_float4(x, y, z, sq);
        }
        __syncthreads();

        int wi = tid >> 5, lane = tid & 31;
        const float r2 = (float)(0.15*0.15);
        int* my = s_idx + wi*KK;

#pragma unroll 1
        for (int qq = 0; qq < 4; qq++) {
            int n = nbase + wi*4 + qq;
            float4 pn = s_p4[n];
            float xn = pn.x, yn = pn.y, zn = pn.z, sqn = pn.w;

            int cnt = 0;
            for (int base = 0; base < NN && cnt < KK; base += 32) {
                float4 pj = s_p4[base + lane];
                float dt  = __fadd_rn(__fadd_rn(__fmul_rn(xn,pj.x), __fmul_rn(yn,pj.y)), __fmul_rn(zn,pj.z));
                float d2  = __fsub_rn(__fadd_rn(sqn, pj.w), __fmul_rn(2.0f, dt));
                bool within = (d2 <= r2);
                unsigned m = __ballot_sync(0xffffffffu, within);
                int pos = cnt + __popc(m & ((1u << lane) - 1u));
                if (within && pos < KK) my[pos] = base + lane;
                cnt += __popc(m);
            }
            __syncwarp();
            if (cnt > KK) cnt = KK;
            int v = my[(lane < cnt) ? lane : 0];
            g_idx[((size_t)b*NN + n)*KK + lane] = v;
            __syncwarp();
        }

    } else if (blk < 1056) {
        // ---------- p passthrough copy into out[0 : B*N*3) ----------
        int cb = blk - 1024;
        const float4* src = reinterpret_cast<const float4*>(p);
        float4* dst = reinterpret_cast<float4*>(out);
        int lo = cb*768, hi = lo + 768;
        for (int i = lo + tid; i < hi; i += 512) dst[i] = src[i];

    } else {
        // ---------- prep: weight repack ----------
        for (int i = tid; i < 3*128; i += 512) {
            int d = i / 128, u = i % 128;
            g_wD3[i] = (u < 64) ? w_attn[u*CIN + d] : w1[(u-64)*CIN + d];
        }
        // w2 B-fragments for mma.sync m16n8k16 (row.col): B[k=cp][n=c] = w2[c][cp]
        // frag reg r of lane: pair {B[k0][n], B[k0+1][n]}, k0 = kt*16 + (lane%4)*2 + r*8, n = nt*8 + lane/4
        for (int i = tid; i < 2048; i += 512) {
            int r    = i & 1;
            int lane = (i >> 1) & 31;
            int nt   = (i >> 6) & 7;
            int kt   = i >> 9;
            int k0 = kt*16 + (lane & 3)*2 + r*8;
            int n  = nt*8 + (lane >> 2);
            float v0 = w2[n*64 + k0], v1 = w2[n*64 + k0 + 1];
            __nv_bfloat16 h0 = __float2bfloat16(v0), h1 = __float2bfloat16(v1);
            __nv_bfloat162 hi2; hi2.x = h0; hi2.y = h1;
            __nv_bfloat162 lo2;
            lo2.x = __float2bfloat16(v0 - __bfloat162float(h0));
            lo2.y = __float2bfloat16(v1 - __bfloat162float(h1));
            g_bfH[i] = *reinterpret_cast<uint32_t*>(&hi2);
            g_bfL[i] = *reinterpret_cast<uint32_t*>(&lo2);
        }
        for (int i = tid; i < CC*CC; i += 512) {
            int c = i / CC, cp = i % CC;
            g_wf1T[cp*CC + c] = wf1[i];
            g_wf2T[cp*CC + c] = wf2[i];
        }
    }
}

// ---------------- fused main: mma.sync GEMM, 4 points/block, 3 blocks/SM ----------------
// dyn smem bytes:
//   Rhi bf16 [128 rows(pt*32+k)][72] pitch-72  : 0     .. 18432
//   Rlo                                        : 18432 .. 36864
//   E half [pt][32 k][72]                      : 36864 .. 55296
//   meta float4[128]  (phase 1) ∪ s_red[2][4][64][2] f32 (epilogue) : 55296 .. 59392
#define SMM_RHI  0
#define SMM_RLO  18432
#define SMM_E    36864
#define SMM_META 55296
#define SM_MAIN  59392

__global__ void __launch_bounds__(256, 3) main_kernel(const float* __restrict__ p,
        const float* __restrict__ b2) {
    extern __shared__ char smc[];
    uint32_t smem_base = smem_u32(smc);
    float4* s_meta = reinterpret_cast<float4*>(smc + SMM_META);

    int tid  = threadIdx.x;
    int w    = tid >> 5;
    int lane = tid & 31;
    int pbase = blockIdx.x * 4;

    // meta: warps 0..3 stage (dp, j) for point w
    if (w < 4) {
        int pid = pbase + w;
        int b = pid >> 12, n = pid & 4095;
        int j = g_idx[(size_t)pid*KK + lane];
        const float* pn = p + ((size_t)b*NN + n)*3;
        const float* pj = p + ((size_t)b*NN + j)*3;
        float4 m;
        m.x = pj[0] - pn[0];
        m.y = pj[1] - pn[1];
        m.z = pj[2] - pn[2];
        m.w = __int_as_float(j);
        s_meta[w*32 + lane] = m;
    }
    __syncthreads();

    // ---- phase 1: gather + attn/exp (lanes 0-15) | relu + bf16 hi/lo R store (lanes 16-31) ----
    {
        int pt = w & 3;
        int k0 = (w >> 2) * 16;
        int pid = pbase + pt;
        int b = pid >> 12;
        int u = lane * 4;
        bool isE = (lane < 16);
        float4 wx = *reinterpret_cast<const float4*>(&g_wD3[0*128 + u]);
        float4 wy = *reinterpret_cast<const float4*>(&g_wD3[1*128 + u]);
        float4 wz = *reinterpret_cast<const float4*>(&g_wD3[2*128 + u]);
        __half* Ep = reinterpret_cast<__half*>(smc + SMM_E) + pt*2304;
        const float* Gb = g_G + (size_t)b*NN*128;
        int cpb = u - 64;   // R channel base for lanes 16..31: 0,4,...,60

#pragma unroll 4
        for (int kk = 0; kk < 16; kk++) {
            int k = k0 + kk;
            float4 m = s_meta[pt*32 + k];
            int j = __float_as_int(m.w);
            float4 g = __ldg(reinterpret_cast<const float4*>(&Gb[(size_t)j*128 + u]));
            float4 v;
            v.x = g.x + wx.x*m.x + wy.x*m.y + wz.x*m.z;
            v.y = g.y + wx.y*m.x + wy.y*m.y + wz.y*m.z;
            v.z = g.z + wx.z*m.x + wy.z*m.y + wz.z*m.z;
            v.w = g.w + wx.w*m.x + wy.w*m.y + wz.w*m.z;
            if (isE) {
                union { __half2 h[2]; uint2 u2; } cv;
                cv.h[0] = __floats2half2_rn(__expf(v.x), __expf(v.y));
                cv.h[1] = __floats2half2_rn(__expf(v.z), __expf(v.w));
                *reinterpret_cast<uint2*>(&Ep[k*72 + u]) = cv.u2;
            } else {
                float r0 = fmaxf(v.x, 0.0f), r1 = fmaxf(v.y, 0.0f);
                float r2v = fmaxf(v.z, 0.0f), r3 = fmaxf(v.w, 0.0f);
                __nv_bfloat16 h0 = __float2bfloat16(r0), h1 = __float2bfloat16(r1);
                __nv_bfloat16 h2 = __float2bfloat16(r2v), h3 = __float2bfloat16(r3);
                __nv_bfloat162 hp0; hp0.x = h0; hp0.y = h1;
                __nv_bfloat162 hp1; hp1.x = h2; hp1.y = h3;
                __nv_bfloat162 lp0; lp0.x = __float2bfloat16(r0 - __bfloat162float(h0));
                                    lp0.y = __float2bfloat16(r1 - __bfloat162float(h1));
                __nv_bfloat162 lp1; lp1.x = __float2bfloat16(r2v - __bfloat162float(h2));
                                    lp1.y = __float2bfloat16(r3 - __bfloat162float(h3));
                int row = pt*32 + k;
                uint32_t roff = (uint32_t)(row*72 + cpb)*2;
                *reinterpret_cast<uint2*>(smc + SMM_RHI + roff) =
                    make_uint2(*reinterpret_cast<uint32_t*>(&hp0), *reinterpret_cast<uint32_t*>(&hp1));
                *reinterpret_cast<uint2*>(smc + SMM_RLO + roff) =
                    make_uint2(*reinterpret_cast<uint32_t*>(&lp0), *reinterpret_cast<uint32_t*>(&lp1));
            }
        }
    }
    __syncthreads();

    // ---- mma GEMM + softmax-weighted epilogue: warp = (pt = w&3, mh = w>>2) ----
    {
        int pt = w & 3;
        int mh = w >> 2;            // 0/1: which 16 k-rows

        // ldmatrix lane->address: m8n8 x4 matrices = (r0..7,c0..7),(r8..15,c0..7),(r0..7,c8..15),(r8..15,c8..15)
        int r8 = lane & 7, mmat = lane >> 3;
        int arow = pt*32 + mh*16 + r8 + ((mmat & 1) << 3);
        uint32_t acolB = (uint32_t)(((mmat >> 1) << 3) * 2);  // col bytes
        uint32_t abase = smem_base + (uint32_t)(arow * 144) + acolB;

        float acc[8][4];
#pragma unroll
        for (int nt = 0; nt < 8; nt++)
#pragma unroll
            for (int q = 0; q < 4; q++) acc[nt][q] = 0.0f;

#pragma unroll
        for (int kt = 0; kt < 4; kt++) {
            uint32_t ah[4], al[4];
            ldsm_x4(ah, abase + SMM_RHI + kt*32);
            ldsm_x4(al, abase + SMM_RLO + kt*32);
#pragma unroll
            for (int nt = 0; nt < 8; nt++) {
                int bidx = ((kt*8 + nt)*32 + lane)*2;
                uint2 bh = __ldg(reinterpret_cast<const uint2*>(&g_bfH[bidx]));
                uint2 bl = __ldg(reinterpret_cast<const uint2*>(&g_bfL[bidx]));
                mma_bf16(acc[nt], ah, bh.x, bh.y);
                mma_bf16(acc[nt], al, bh.x, bh.y);
                mma_bf16(acc[nt], ah, bl.x, bl.y);
            }
        }

        // epilogue: e-weighted sums over k. Lane holds rows r0, r0+8; cols (lane%4)*2 + nt*8.
        const __half* Eb = reinterpret_cast<const __half*>(smc + SMM_E);
        float* red = reinterpret_cast<float*>(smc + SMM_META);
        int r0 = mh*16 + (lane >> 2);
        int c00 = (lane & 3) * 2;
#pragma unroll
        for (int nt = 0; nt < 8; nt++) {
            int c0 = nt*8 + c00;
            float2 e0 = __half22float2(*reinterpret_cast<const __half2*>(&Eb[pt*2304 + r0*72 + c0]));
            float2 e1 = __half22float2(*reinterpret_cast<const __half2*>(&Eb[pt*2304 + (r0+8)*72 + c0]));
            float num0 = e0.x*acc[nt][0] + e1.x*acc[nt][2];
            float num1 = e0.y*acc[nt][1] + e1.y*acc[nt][3];
            float den0 = e0.x + e1.x;
            float den1 = e0.y + e1.y;
#pragma unroll
            for (int off = 4; off <= 16; off <<= 1) {
                num0 += __shfl_xor_sync(0xffffffffu, num0, off);
                num1 += __shfl_xor_sync(0xffffffffu, num1, off);
                den0 += __shfl_xor_sync(0xffffffffu, den0, off);
                den1 += __shfl_xor_sync(0xffffffffu, den1, off);
            }
            if (lane < 4) {
                int base = ((mh*4 + pt)*64 + c0)*2;
                red[base+0] = num0; red[base+1] = den0;
                red[base+2] = num1; red[base+3] = den1;
            }
        }
    }
    __syncthreads();

    // ---- final: combine mh halves, divide, add bias, coalesced store ----
    {
        int pt = tid >> 6, c = tid & 63;
        const float* red = reinterpret_cast<const float*>(smc + SMM_META);
        float num = red[(pt*64 + c)*2 + 0] + red[((4 + pt)*64 + c)*2 + 0];
        float den = red[(pt*64 + c)*2 + 1] + red[((4 + pt)*64 + c)*2 + 1];
        g_F0[(size_t)(pbase + pt)*CC + c] = num / den + __ldg(&b2[c]);
    }
}

// ---------------- tail: relu(F0+f) -> 2x (64x64) MLP -> relu residual ----------------
__global__ void __launch_bounds__(256) tail_kernel(const float* __restrict__ f,
        const float* __restrict__ bf1, const float* __restrict__ bf2,
        float* __restrict__ outF) {
    __shared__ float s_F1[64*68];
    __shared__ float s_H[64*68];

    int b   = blockIdx.x >> 6;
    int n0g = (blockIdx.x & 63) << 6;
    int tid = threadIdx.x;

    {
        int c = tid >> 2, q = tid & 3;
        const float* frow = f + ((size_t)b*CC + c)*NN + n0g;
        const float* f0b  = g_F0 + ((size_t)b*NN + n0g)*CC + c;
#pragma unroll
        for (int i = 0; i < 4; i++) {
            int nn = q*16 + i*4;
            float4 fv = *reinterpret_cast<const float4*>(frow + nn);
            float a0 = __ldg(&f0b[(nn+0)*CC]);
            float a1 = __ldg(&f0b[(nn+1)*CC]);
            float a2 = __ldg(&f0b[(nn+2)*CC]);
            float a3 = __ldg(&f0b[(nn+3)*CC]);
            float4 r;
            r.x = fmaxf(a0 + fv.x, 0.0f);
            r.y = fmaxf(a1 + fv.y, 0.0f);
            r.z = fmaxf(a2 + fv.z, 0.0f);
            r.w = fmaxf(a3 + fv.w, 0.0f);
            *reinterpret_cast<float4*>(&s_F1[c*68 + nn]) = r;
        }
    }
    __syncthreads();

    int ct = (tid >> 4) << 2;
    int nt = (tid & 15) << 2;

    {
        float acc[16];
#pragma unroll
        for (int r = 0; r < 4; r++) {
            float bv = __ldg(&bf1[ct+r]);
#pragma unroll
            for (int jj = 0; jj < 4; jj++) acc[r*4+jj] = bv;
        }
#pragma unroll 4
        for (int cp = 0; cp < 64; cp++) {
            float4 wv = __ldg(reinterpret_cast<const float4*>(&g_wf1T[cp*64 + ct]));
            float4 fv = *reinterpret_cast<const float4*>(&s_F1[cp*68 + nt]);
            acc[0]  += wv.x*fv.x; acc[1]  += wv.x*fv.y; acc[2]  += wv.x*fv.z; acc[3]  += wv.x*fv.w;
            acc[4]  += wv.y*fv.x; acc[5]  += wv.y*fv.y; acc[6]  += wv.y*fv.z; acc[7]  += wv.y*fv.w;
            acc[8]  += wv.z*fv.x; acc[9]  += wv.z*fv.y; acc[10] += wv.z*fv.z; acc[11] += wv.z*fv.w;
            acc[12] += wv.w*fv.x; acc[13] += wv.w*fv.y; acc[14] += wv.w*fv.z; acc[15] += wv.w*fv.w;
        }
#pragma unroll
        for (int r = 0; r < 4; r++) {
            float4 o;
            o.x = fmaxf(acc[r*4+0], 0.0f);
            o.y = fmaxf(acc[r*4+1], 0.0f);
            o.z = fmaxf(acc[r*4+2], 0.0f);
            o.w = fmaxf(acc[r*4+3], 0.0f);
            *reinterpret_cast<float4*>(&s_H[(ct+r)*68 + nt]) = o;
        }
    }
    __syncthreads();

    {
        float acc[16];
#pragma unroll
        for (int r = 0; r < 4; r++) {
            float bv = __ldg(&bf2[ct+r]);
#pragma unroll
            for (int jj = 0; jj < 4; jj++) acc[r*4+jj] = bv;
        }
#pragma unroll 4
        for (int cp = 0; cp < 64; cp++) {
            float4 wv = __ldg(reinterpret_cast<const float4*>(&g_wf2T[cp*64 + ct]));
            float4 hv = *reinterpret_cast<const float4*>(&s_H[cp*68 + nt]);
            acc[0]  += wv.x*hv.x; acc[1]  += wv.x*hv.y; acc[2]  += wv.x*hv.z; acc[3]  += wv.x*hv.w;
            acc[4]  += wv.y*hv.x; acc[5]  += wv.y*hv.y; acc[6]  += wv.y*hv.z; acc[7]  += wv.y*hv.w;
            acc[8]  += wv.z*hv.x; acc[9]  += wv.z*hv.y; acc[10] += wv.z*hv.z; acc[11] += wv.z*hv.w;
            acc[12] += wv.w*hv.x; acc[13] += wv.w*hv.y; acc[14] += wv.w*hv.z; acc[15] += wv.w*hv.w;
        }
#pragma unroll
        for (int r = 0; r < 4; r++) {
            const float* idn = &s_F1[(ct+r)*68 + nt];
            float4 o;
            o.x = fmaxf(acc[r*4+0] + idn[0], 0.0f);
            o.y = fmaxf(acc[r*4+1] + idn[1], 0.0f);
            o.z = fmaxf(acc[r*4+2] + idn[2], 0.0f);
            o.w = fmaxf(acc[r*4+3] + idn[3], 0.0f);
            *reinterpret_cast<float4*>(&outF[((size_t)b*CC + ct + r)*NN + n0g + nt]) = o;
        }
    }
}

// ---------------- launch ----------------
extern "C" void kernel_launch(void* const* d_in, const int* in_sizes, int n_in,
                              void* d_out, int out_size) {
    const float* p      = (const float*)d_in[0];
    const float* f      = (const float*)d_in[1];
    const float* w_attn = (const float*)d_in[2];
    const float* b_attn = (const float*)d_in[3];
    const float* w1     = (const float*)d_in[4];
    const float* b1     = (const float*)d_in[5];
    const float* w2     = (const float*)d_in[6];
    const float* b2     = (const float*)d_in[7];
    const float* wf1    = (const float*)d_in[8];
    const float* bf1    = (const float*)d_in[9];
    const float* wf2    = (const float*)d_in[10];
    const float* bf2    = (const float*)d_in[11];
    float* out = (float*)d_out;

    cudaFuncSetAttribute(fused_pre, cudaFuncAttributeMaxDynamicSharedMemorySize, PRE_SMEM);
    fused_pre<<<1057, 512, PRE_SMEM>>>(p, f, w_attn, b_attn, w1, b1, w2, wf1, wf2, out);

    cudaFuncSetAttribute(main_kernel, cudaFuncAttributeMaxDynamicSharedMemorySize, SM_MAIN);
    main_kernel<<<BB*NN/4, 256, SM_MAIN>>>(p, b2);

    tail_kernel<<<BB*(NN/64), 256>>>(f, bf1, bf2, out + (size_t)BB*NN*3);
}

// round 9
// speedup vs baseline: 2.8681x; 1.1147x over previous
#include <cuda_runtime.h>
#include <cuda_fp16.h>
#include <cuda_bf16.h>
#include <cstdint>
#include <cstddef>

#define BB  8
#define NN  4096
#define KK  32
#define CC  64
#define CIN 67

// -------- scratch (no allocation allowed -> __device__ globals) --------
__device__ __align__(16) float g_G[(size_t)BB*NN*128]; // merged [b][j][0:64]=GA, [64:128]=G1
__device__ __align__(16) float g_F0[(size_t)BB*NN*CC]; // attention output (pre-residual), [b, n, c]
__device__ int   g_idx[(size_t)BB*NN*KK];              // ball-query neighbor indices
__device__ __align__(16) float g_wD3[3*128];           // [d][u]: u<64 -> w_attn[u][d], else w1[u-64][d]
__device__ __align__(16) uint32_t g_bfH[2048];         // w2 hi-bf16 B-fragments [kt][nt][lane][2]
__device__ __align__(16) uint32_t g_bfL[2048];         // w2 lo-bf16 residual fragments
__device__ __align__(16) float g_wf1T[CC*CC];          // wf1 transposed [cp][c]
__device__ __align__(16) float g_wf2T[CC*CC];          // wf2 transposed [cp][c]

// ---------------- helpers ----------------
__device__ __forceinline__ uint32_t smem_u32(const void* p_) {
    uint32_t a;
    asm("{ .reg .u64 t; cvta.to.shared.u64 t, %1; cvt.u32.u64 %0, t; }" : "=r"(a) : "l"(p_));
    return a;
}
__device__ __forceinline__ void ldsm_x4(uint32_t* r, uint32_t addr) {
    asm volatile("ldmatrix.sync.aligned.m8n8.x4.shared.b16 {%0,%1,%2,%3}, [%4];"
        : "=r"(r[0]), "=r"(r[1]), "=r"(r[2]), "=r"(r[3]) : "r"(addr));
}
__device__ __forceinline__ void mma_bf16(float* d, const uint32_t* a, uint32_t b0, uint32_t b1) {
    asm volatile("mma.sync.aligned.m16n8k16.row.col.f32.bf16.bf16.f32 "
        "{%0,%1,%2,%3}, {%4,%5,%6,%7}, {%8,%9}, {%0,%1,%2,%3};"
        : "+f"(d[0]), "+f"(d[1]), "+f"(d[2]), "+f"(d[3])
        : "r"(a[0]), "r"(a[1]), "r"(a[2]), "r"(a[3]), "r"(b0), "r"(b1));
}
__device__ __forceinline__ unsigned long long pack2(float lo, float hi) {
    unsigned long long r;
    asm("mov.b64 %0, {%1, %2};" : "=l"(r) : "f"(lo), "f"(hi));
    return r;
}
__device__ __forceinline__ float2 unpack2(unsigned long long v) {
    float2 r;
    asm("mov.b64 {%0, %1}, %2;" : "=f"(r.x), "=f"(r.y) : "l"(v));
    return r;
}
__device__ __forceinline__ void fma2(unsigned long long &acc, unsigned long long a, unsigned long long b) {
    asm("fma.rn.f32x2 %0, %1, %2, %3;" : "=l"(acc) : "l"(a), "l"(b), "l"(acc));
}

// ================== fused pre-kernel: bq | ga | p-copy | prep ==================
// grid: [0,512) bq (64 queries/block, scheduled FIRST - longest pole),
//       [512,1024) ga, [1024,1056) copy, 1056 prep. block=512.
#define PRE_SMEM 67584

__global__ void __launch_bounds__(512) fused_pre(
        const float* __restrict__ p, const float* __restrict__ f,
        const float* __restrict__ w_attn, const float* __restrict__ b_attn,
        const float* __restrict__ w1, const float* __restrict__ b1,
        const float* __restrict__ w2,
        const float* __restrict__ wf1, const float* __restrict__ wf2,
        float* __restrict__ out) {
    extern __shared__ float sm[];
    int blk = blockIdx.x;
    int tid = threadIdx.x;

    if (blk < 512) {
        // ---------- bq: ball query, 64 queries/block (4 per warp), 64 candidates/iter ----------
        int bb = blk;
        float4* s_p4 = reinterpret_cast<float4*>(sm);
        int*    s_idx = reinterpret_cast<int*>(sm + 4*NN);

        int b     = bb >> 6;
        int nbase = (bb & 63) << 6;
        const float* pb = p + (size_t)b*NN*3;
        for (int jj = tid; jj < NN; jj += 512) {
            float x = pb[jj*3+0], y = pb[jj*3+1], z = pb[jj*3+2];
            float sq = __fadd_rn(__fadd_rn(__fmul_rn(x,x), __fmul_rn(y,y)), __fmul_rn(z,z));
            s_p4[jj] = make_float4(x, y, z, sq);
        }
        __syncthreads();

        int wi = tid >> 5, lane = tid & 31;
        const float r2 = (float)(0.15*0.15);
        unsigned lmask = (1u << lane) - 1u;
        int* my = s_idx + wi*KK;

#pragma unroll 1
        for (int qq = 0; qq < 4; qq++) {
            int n = nbase + wi*4 + qq;
            float4 pn = s_p4[n];
            float xn = pn.x, yn = pn.y, zn = pn.z, sqn = pn.w;

            int cnt = 0;
#pragma unroll 1
            for (int base = 0; base < NN && cnt < KK; base += 64) {
                float4 pa = s_p4[base + lane];
                float4 pbv = s_p4[base + 32 + lane];
                float dta = __fadd_rn(__fadd_rn(__fmul_rn(xn,pa.x), __fmul_rn(yn,pa.y)), __fmul_rn(zn,pa.z));
                float d2a = __fsub_rn(__fadd_rn(sqn, pa.w), __fmul_rn(2.0f, dta));
                float dtb = __fadd_rn(__fadd_rn(__fmul_rn(xn,pbv.x), __fmul_rn(yn,pbv.y)), __fmul_rn(zn,pbv.z));
                float d2b = __fsub_rn(__fadd_rn(sqn, pbv.w), __fmul_rn(2.0f, dtb));
                bool wa = (d2a <= r2);
                bool wb = (d2b <= r2);
                unsigned m1 = __ballot_sync(0xffffffffu, wa);
                unsigned m2 = __ballot_sync(0xffffffffu, wb);
                int pos1 = cnt + __popc(m1 & lmask);
                if (wa && pos1 < KK) my[pos1] = base + lane;
                int c1 = cnt + __popc(m1);
                int pos2 = c1 + __popc(m2 & lmask);
                if (wb && pos2 < KK) my[pos2] = base + 32 + lane;
                cnt = c1 + __popc(m2);
            }
            __syncwarp();
            if (cnt > KK) cnt = KK;
            int v = my[(lane < cnt) ? lane : 0];
            g_idx[((size_t)b*NN + n)*KK + lane] = v;
            __syncwarp();
        }

    } else if (blk < 1024) {
        // ---------- ga: GA/G1 precompute -> merged g_G rows (FFMA2 accumulators) ----------
        float* s_f  = sm;
        float* s_wa = sm + 4096;
        float* s_w1 = sm + 8192;
        int gb = blk - 512;
        int b  = gb >> 6;
        int j0 = (gb & 63) << 6;

        for (int lin = tid; lin < 64*64; lin += 512) {
            int i = lin >> 6, c = lin & 63;
            s_wa[i*64 + c] = w_attn[c*CIN + 3 + i];
            s_w1[i*64 + c] = w1[c*CIN + 3 + i];
        }
        for (int lin = tid; lin < 64*64; lin += 512) {
            int i = lin >> 6, jj = lin & 63;
            s_f[i*64 + jj] = f[((size_t)b*CC + i)*NN + j0 + jj];
        }
        __syncthreads();

        int j  = tid & 63;
        int c0 = (tid >> 6) << 3;     // 8 channels per thread
        unsigned long long accA2[4], acc12[4];
#pragma unroll
        for (int q = 0; q < 4; q++) {
            accA2[q] = pack2(__ldg(&b_attn[c0+2*q]), __ldg(&b_attn[c0+2*q+1]));
            acc12[q] = pack2(__ldg(&b1[c0+2*q]),     __ldg(&b1[c0+2*q+1]));
        }

#pragma unroll 4
        for (int i = 0; i < 64; i++) {
            float fv = s_f[i*64 + j];
            unsigned long long fv2 = pack2(fv, fv);
            const ulonglong2* wa = reinterpret_cast<const ulonglong2*>(&s_wa[i*64 + c0]);
            const ulonglong2* wb = reinterpret_cast<const ulonglong2*>(&s_w1[i*64 + c0]);
            ulonglong2 A0 = wa[0], A1 = wa[1];
            ulonglong2 B0 = wb[0], B1 = wb[1];
            fma2(accA2[0], A0.x, fv2); fma2(accA2[1], A0.y, fv2);
            fma2(accA2[2], A1.x, fv2); fma2(accA2[3], A1.y, fv2);
            fma2(acc12[0], B0.x, fv2); fma2(acc12[1], B0.y, fv2);
            fma2(acc12[2], B1.x, fv2); fma2(acc12[3], B1.y, fv2);
        }
        size_t base = ((size_t)b*NN + j0 + j)*128 + c0;
        {
            float2 a0 = unpack2(accA2[0]), a1 = unpack2(accA2[1]);
            float2 a2 = unpack2(accA2[2]), a3 = unpack2(accA2[3]);
            *reinterpret_cast<float4*>(&g_G[base + 0]) = make_float4(a0.x, a0.y, a1.x, a1.y);
            *reinterpret_cast<float4*>(&g_G[base + 4]) = make_float4(a2.x, a2.y, a3.x, a3.y);
            float2 o0 = unpack2(acc12[0]), o1 = unpack2(acc12[1]);
            float2 o2 = unpack2(acc12[2]), o3 = unpack2(acc12[3]);
            *reinterpret_cast<float4*>(&g_G[base + 64]) = make_float4(o0.x, o0.y, o1.x, o1.y);
            *reinterpret_cast<float4*>(&g_G[base + 68]) = make_float4(o2.x, o2.y, o3.x, o3.y);
        }

    } else if (blk < 1056) {
        // ---------- p passthrough copy into out[0 : B*N*3) ----------
        int cb = blk - 1024;
        const float4* src = reinterpret_cast<const float4*>(p);
        float4* dst = reinterpret_cast<float4*>(out);
        int lo = cb*768, hi = lo + 768;
        for (int i = lo + tid; i < hi; i += 512) dst[i] = src[i];

    } else {
        // ---------- prep: weight repack ----------
        for (int i = tid; i < 3*128; i += 512) {
            int d = i / 128, u = i % 128;
            g_wD3[i] = (u < 64) ? w_attn[u*CIN + d] : w1[(u-64)*CIN + d];
        }
        // w2 B-fragments for mma.sync m16n8k16 (row.col): B[k=cp][n=c] = w2[c][cp]
        for (int i = tid; i < 2048; i += 512) {
            int r    = i & 1;
            int lane = (i >> 1) & 31;
            int nt   = (i >> 6) & 7;
            int kt   = i >> 9;
            int k0 = kt*16 + (lane & 3)*2 + r*8;
            int n  = nt*8 + (lane >> 2);
            float v0 = w2[n*64 + k0], v1 = w2[n*64 + k0 + 1];
            __nv_bfloat16 h0 = __float2bfloat16(v0), h1 = __float2bfloat16(v1);
            __nv_bfloat162 hi2; hi2.x = h0; hi2.y = h1;
            __nv_bfloat162 lo2;
            lo2.x = __float2bfloat16(v0 - __bfloat162float(h0));
            lo2.y = __float2bfloat16(v1 - __bfloat162float(h1));
            g_bfH[i] = *reinterpret_cast<uint32_t*>(&hi2);
            g_bfL[i] = *reinterpret_cast<uint32_t*>(&lo2);
        }
        for (int i = tid; i < CC*CC; i += 512) {
            int c = i / CC, cp = i % CC;
            g_wf1T[cp*CC + c] = wf1[i];
            g_wf2T[cp*CC + c] = wf2[i];
        }
    }
}

// ---------------- fused main: mma.sync GEMM, 4 points/block, 3 blocks/SM ----------------
#define SMM_RHI  0
#define SMM_RLO  18432
#define SMM_E    36864
#define SMM_META 55296
#define SM_MAIN  59392

__global__ void __launch_bounds__(256, 3) main_kernel(const float* __restrict__ p,
        const float* __restrict__ b2) {
    extern __shared__ char smc[];
    uint32_t smem_base = smem_u32(smc);
    float4* s_meta = reinterpret_cast<float4*>(smc + SMM_META);

    int tid  = threadIdx.x;
    int w    = tid >> 5;
    int lane = tid & 31;
    int pbase = blockIdx.x * 4;

    // meta: warps 0..3 stage (dp, j) for point w
    if (w < 4) {
        int pid = pbase + w;
        int b = pid >> 12, n = pid & 4095;
        int j = g_idx[(size_t)pid*KK + lane];
        const float* pn = p + ((size_t)b*NN + n)*3;
        const float* pj = p + ((size_t)b*NN + j)*3;
        float4 m;
        m.x = pj[0] - pn[0];
        m.y = pj[1] - pn[1];
        m.z = pj[2] - pn[2];
        m.w = __int_as_float(j);
        s_meta[w*32 + lane] = m;
    }
    __syncthreads();

    // ---- phase 1: gather + attn/exp (lanes 0-15) | relu + bf16 hi/lo R store (lanes 16-31) ----
    {
        int pt = w & 3;
        int k0 = (w >> 2) * 16;
        int pid = pbase + pt;
        int b = pid >> 12;
        int u = lane * 4;
        bool isE = (lane < 16);
        float4 wx = *reinterpret_cast<const float4*>(&g_wD3[0*128 + u]);
        float4 wy = *reinterpret_cast<const float4*>(&g_wD3[1*128 + u]);
        float4 wz = *reinterpret_cast<const float4*>(&g_wD3[2*128 + u]);
        __half* Ep = reinterpret_cast<__half*>(smc + SMM_E) + pt*2304;
        const float* Gb = g_G + (size_t)b*NN*128;
        int cpb = u - 64;

#pragma unroll 4
        for (int kk = 0; kk < 16; kk++) {
            int k = k0 + kk;
            float4 m = s_meta[pt*32 + k];
            int j = __float_as_int(m.w);
            float4 g = __ldg(reinterpret_cast<const float4*>(&Gb[(size_t)j*128 + u]));
            float4 v;
            v.x = g.x + wx.x*m.x + wy.x*m.y + wz.x*m.z;
            v.y = g.y + wx.y*m.x + wy.y*m.y + wz.y*m.z;
            v.z = g.z + wx.z*m.x + wy.z*m.y + wz.z*m.z;
            v.w = g.w + wx.w*m.x + wy.w*m.y + wz.w*m.z;
            if (isE) {
                union { __half2 h[2]; uint2 u2; } cv;
                cv.h[0] = __floats2half2_rn(__expf(v.x), __expf(v.y));
                cv.h[1] = __floats2half2_rn(__expf(v.z), __expf(v.w));
                *reinterpret_cast<uint2*>(&Ep[k*72 + u]) = cv.u2;
            } else {
                float r0 = fmaxf(v.x, 0.0f), r1 = fmaxf(v.y, 0.0f);
                float r2v = fmaxf(v.z, 0.0f), r3 = fmaxf(v.w, 0.0f);
                __nv_bfloat16 h0 = __float2bfloat16(r0), h1 = __float2bfloat16(r1);
                __nv_bfloat16 h2 = __float2bfloat16(r2v), h3 = __float2bfloat16(r3);
                __nv_bfloat162 hp0; hp0.x = h0; hp0.y = h1;
                __nv_bfloat162 hp1; hp1.x = h2; hp1.y = h3;
                __nv_bfloat162 lp0; lp0.x = __float2bfloat16(r0 - __bfloat162float(h0));
                                    lp0.y = __float2bfloat16(r1 - __bfloat162float(h1));
                __nv_bfloat162 lp1; lp1.x = __float2bfloat16(r2v - __bfloat162float(h2));
                                    lp1.y = __float2bfloat16(r3 - __bfloat162float(h3));
                int row = pt*32 + k;
                uint32_t roff = (uint32_t)(row*72 + cpb)*2;
                *reinterpret_cast<uint2*>(smc + SMM_RHI + roff) =
                    make_uint2(*reinterpret_cast<uint32_t*>(&hp0), *reinterpret_cast<uint32_t*>(&hp1));
                *reinterpret_cast<uint2*>(smc + SMM_RLO + roff) =
                    make_uint2(*reinterpret_cast<uint32_t*>(&lp0), *reinterpret_cast<uint32_t*>(&lp1));
            }
        }
    }
    __syncthreads();

    // ---- mma GEMM + softmax-weighted epilogue: warp = (pt = w&3, mh = w>>2) ----
    {
        int pt = w & 3;
        int mh = w >> 2;

        int r8 = lane & 7, mmat = lane >> 3;
        int arow = pt*32 + mh*16 + r8 + ((mmat & 1) << 3);
        uint32_t acolB = (uint32_t)(((mmat >> 1) << 3) * 2);
        uint32_t abase = smem_base + (uint32_t)(arow * 144) + acolB;

        float acc[8][4];
#pragma unroll
        for (int nt = 0; nt < 8; nt++)
#pragma unroll
            for (int q = 0; q < 4; q++) acc[nt][q] = 0.0f;

#pragma unroll
        for (int kt = 0; kt < 4; kt++) {
            uint32_t ah[4], al[4];
            ldsm_x4(ah, abase + SMM_RHI + kt*32);
            ldsm_x4(al, abase + SMM_RLO + kt*32);
#pragma unroll
            for (int nt = 0; nt < 8; nt++) {
                int bidx = ((kt*8 + nt)*32 + lane)*2;
                uint2 bh = __ldg(reinterpret_cast<const uint2*>(&g_bfH[bidx]));
                uint2 bl = __ldg(reinterpret_cast<const uint2*>(&g_bfL[bidx]));
                mma_bf16(acc[nt], ah, bh.x, bh.y);
                mma_bf16(acc[nt], al, bh.x, bh.y);
                mma_bf16(acc[nt], ah, bl.x, bl.y);
            }
        }

        const __half* Eb = reinterpret_cast<const __half*>(smc + SMM_E);
        float* red = reinterpret_cast<float*>(smc + SMM_META);
        int r0 = mh*16 + (lane >> 2);
        int c00 = (lane & 3) * 2;
#pragma unroll
        for (int nt = 0; nt < 8; nt++) {
            int c0 = nt*8 + c00;
            float2 e0 = __half22float2(*reinterpret_cast<const __half2*>(&Eb[pt*2304 + r0*72 + c0]));
            float2 e1 = __half22float2(*reinterpret_cast<const __half2*>(&Eb[pt*2304 + (r0+8)*72 + c0]));
            float num0 = e0.x*acc[nt][0] + e1.x*acc[nt][2];
            float num1 = e0.y*acc[nt][1] + e1.y*acc[nt][3];
            float den0 = e0.x + e1.x;
            float den1 = e0.y + e1.y;
#pragma unroll
            for (int off = 4; off <= 16; off <<= 1) {
                num0 += __shfl_xor_sync(0xffffffffu, num0, off);
                num1 += __shfl_xor_sync(0xffffffffu, num1, off);
                den0 += __shfl_xor_sync(0xffffffffu, den0, off);
                den1 += __shfl_xor_sync(0xffffffffu, den1, off);
            }
            if (lane < 4) {
                int base = ((mh*4 + pt)*64 + c0)*2;
                red[base+0] = num0; red[base+1] = den0;
                red[base+2] = num1; red[base+3] = den1;
            }
        }
    }
    __syncthreads();

    // ---- final: combine mh halves, divide, add bias, coalesced store ----
    {
        int pt = tid >> 6, c = tid & 63;
        const float* red = reinterpret_cast<const float*>(smc + SMM_META);
        float num = red[(pt*64 + c)*2 + 0] + red[((4 + pt)*64 + c)*2 + 0];
        float den = red[(pt*64 + c)*2 + 1] + red[((4 + pt)*64 + c)*2 + 1];
        g_F0[(size_t)(pbase + pt)*CC + c] = num / den + __ldg(&b2[c]);
    }
}

// ---------------- tail: relu(F0+f) -> 2x (64x64) MLP -> relu residual ----------------
__global__ void __launch_bounds__(256) tail_kernel(const float* __restrict__ f,
        const float* __restrict__ bf1, const float* __restrict__ bf2,
        float* __restrict__ outF) {
    __shared__ float s_F1[64*68];
    __shared__ float s_H[64*68];

    int b   = blockIdx.x >> 6;
    int n0g = (blockIdx.x & 63) << 6;
    int tid = threadIdx.x;

    {
        int c = tid >> 2, q = tid & 3;
        const float* frow = f + ((size_t)b*CC + c)*NN + n0g;
        const float* f0b  = g_F0 + ((size_t)b*NN + n0g)*CC + c;
#pragma unroll
        for (int i = 0; i < 4; i++) {
            int nn = q*16 + i*4;
            float4 fv = *reinterpret_cast<const float4*>(frow + nn);
            float a0 = __ldg(&f0b[(nn+0)*CC]);
            float a1 = __ldg(&f0b[(nn+1)*CC]);
            float a2 = __ldg(&f0b[(nn+2)*CC]);
            float a3 = __ldg(&f0b[(nn+3)*CC]);
            float4 r;
            r.x = fmaxf(a0 + fv.x, 0.0f);
            r.y = fmaxf(a1 + fv.y, 0.0f);
            r.z = fmaxf(a2 + fv.z, 0.0f);
            r.w = fmaxf(a3 + fv.w, 0.0f);
            *reinterpret_cast<float4*>(&s_F1[c*68 + nn]) = r;
        }
    }
    __syncthreads();

    int ct = (tid >> 4) << 2;
    int nt = (tid & 15) << 2;

    {
        float acc[16];
#pragma unroll
        for (int r = 0; r < 4; r++) {
            float bv = __ldg(&bf1[ct+r]);
#pragma unroll
            for (int jj = 0; jj < 4; jj++) acc[r*4+jj] = bv;
        }
#pragma unroll 4
        for (int cp = 0; cp < 64; cp++) {
            float4 wv = __ldg(reinterpret_cast<const float4*>(&g_wf1T[cp*64 + ct]));
            float4 fv = *reinterpret_cast<const float4*>(&s_F1[cp*68 + nt]);
            acc[0]  += wv.x*fv.x; acc[1]  += wv.x*fv.y; acc[2]  += wv.x*fv.z; acc[3]  += wv.x*fv.w;
            acc[4]  += wv.y*fv.x; acc[5]  += wv.y*fv.y; acc[6]  += wv.y*fv.z; acc[7]  += wv.y*fv.w;
            acc[8]  += wv.z*fv.x; acc[9]  += wv.z*fv.y; acc[10] += wv.z*fv.z; acc[11] += wv.z*fv.w;
            acc[12] += wv.w*fv.x; acc[13] += wv.w*fv.y; acc[14] += wv.w*fv.z; acc[15] += wv.w*fv.w;
        }
#pragma unroll
        for (int r = 0; r < 4; r++) {
            float4 o;
            o.x = fmaxf(acc[r*4+0], 0.0f);
            o.y = fmaxf(acc[r*4+1], 0.0f);
            o.z = fmaxf(acc[r*4+2], 0.0f);
            o.w = fmaxf(acc[r*4+3], 0.0f);
            *reinterpret_cast<float4*>(&s_H[(ct+r)*68 + nt]) = o;
        }
    }
    __syncthreads();

    {
        float acc[16];
#pragma unroll
        for (int r = 0; r < 4; r++) {
            float bv = __ldg(&bf2[ct+r]);
#pragma unroll
            for (int jj = 0; jj < 4; jj++) acc[r*4+jj] = bv;
        }
#pragma unroll 4
        for (int cp = 0; cp < 64; cp++) {
            float4 wv = __ldg(reinterpret_cast<const float4*>(&g_wf2T[cp*64 + ct]));
            float4 hv = *reinterpret_cast<const float4*>(&s_H[cp*68 + nt]);
            acc[0]  += wv.x*hv.x; acc[1]  += wv.x*hv.y; acc[2]  += wv.x*hv.z; acc[3]  += wv.x*hv.w;
            acc[4]  += wv.y*hv.x; acc[5]  += wv.y*hv.y; acc[6]  += wv.y*hv.z; acc[7]  += wv.y*hv.w;
            acc[8]  += wv.z*hv.x; acc[9]  += wv.z*hv.y; acc[10] += wv.z*hv.z; acc[11] += wv.z*hv.w;
            acc[12] += wv.w*hv.x; acc[13] += wv.w*hv.y; acc[14] += wv.w*hv.z; acc[15] += wv.w*hv.w;
        }
#pragma unroll
        for (int r = 0; r < 4; r++) {
            const float* idn = &s_F1[(ct+r)*68 + nt];
            float4 o;
            o.x = fmaxf(acc[r*4+0] + idn[0], 0.0f);
            o.y = fmaxf(acc[r*4+1] + idn[1], 0.0f);
            o.z = fmaxf(acc[r*4+2] + idn[2], 0.0f);
            o.w = fmaxf(acc[r*4+3] + idn[3], 0.0f);
            *reinterpret_cast<float4*>(&outF[((size_t)b*CC + ct + r)*NN + n0g + nt]) = o;
        }
    }
}

// ---------------- launch ----------------
extern "C" void kernel_launch(void* const* d_in, const int* in_sizes, int n_in,
                              void* d_out, int out_size) {
    const float* p      = (const float*)d_in[0];
    const float* f      = (const float*)d_in[1];
    const float* w_attn = (const float*)d_in[2];
    const float* b_attn = (const float*)d_in[3];
    const float* w1     = (const float*)d_in[4];
    const float* b1     = (const float*)d_in[5];
    const float* w2     = (const float*)d_in[6];
    const float* b2     = (const float*)d_in[7];
    const float* wf1    = (const float*)d_in[8];
    const float* bf1    = (const float*)d_in[9];
    const float* wf2    = (const float*)d_in[10];
    const float* bf2    = (const float*)d_in[11];
    float* out = (float*)d_out;

    cudaFuncSetAttribute(fused_pre, cudaFuncAttributeMaxDynamicSharedMemorySize, PRE_SMEM);
    fused_pre<<<1057, 512, PRE_SMEM>>>(p, f, w_attn, b_attn, w1, b1, w2, wf1, wf2, out);

    cudaFuncSetAttribute(main_kernel, cudaFuncAttributeMaxDynamicSharedMemorySize, SM_MAIN);
    main_kernel<<<BB*NN/4, 256, SM_MAIN>>>(p, b2);

    tail_kernel<<<BB*(NN/64), 256>>>(f, bf1, bf2, out + (size_t)BB*NN*3);
}

// round 10
// speedup vs baseline: 3.0354x; 1.0583x over previous
#include <cuda_runtime.h>
#include <cuda_fp16.h>
#include <cuda_bf16.h>
#include <cstdint>
#include <cstddef>

#define BB  8
#define NN  4096
#define KK  32
#define CC  64
#define CIN 67

// -------- scratch (no allocation allowed -> __device__ globals) --------
__device__ __align__(16) float g_G[(size_t)BB*NN*128]; // merged [b][j][0:64]=GA, [64:128]=G1
__device__ __align__(16) float g_F0[(size_t)BB*NN*CC]; // attention output (pre-residual), [b, n, c]
__device__ int   g_idx[(size_t)BB*NN*KK];              // ball-query neighbor indices
__device__ __align__(16) float g_wD3[3*128];           // [d][u]: u<64 -> w_attn[u][d], else w1[u-64][d]
__device__ __align__(16) uint32_t g_bfH[2048];         // w2 hi-bf16 B-fragments [kt][nt][lane][2]
__device__ __align__(16) uint32_t g_bfL[2048];         // w2 lo-bf16 residual fragments
__device__ __align__(16) float g_wf1T[CC*CC];          // wf1 transposed [cp][c]
__device__ __align__(16) float g_wf2T[CC*CC];          // wf2 transposed [cp][c]

// ---------------- helpers ----------------
__device__ __forceinline__ uint32_t smem_u32(const void* p_) {
    uint32_t a;
    asm("{ .reg .u64 t; cvta.to.shared.u64 t, %1; cvt.u32.u64 %0, t; }" : "=r"(a) : "l"(p_));
    return a;
}
__device__ __forceinline__ void ldsm_x4(uint32_t* r, uint32_t addr) {
    asm volatile("ldmatrix.sync.aligned.m8n8.x4.shared.b16 {%0,%1,%2,%3}, [%4];"
        : "=r"(r[0]), "=r"(r[1]), "=r"(r[2]), "=r"(r[3]) : "r"(addr));
}
__device__ __forceinline__ void mma_bf16(float* d, const uint32_t* a, uint32_t b0, uint32_t b1) {
    asm volatile("mma.sync.aligned.m16n8k16.row.col.f32.bf16.bf16.f32 "
        "{%0,%1,%2,%3}, {%4,%5,%6,%7}, {%8,%9}, {%0,%1,%2,%3};"
        : "+f"(d[0]), "+f"(d[1]), "+f"(d[2]), "+f"(d[3])
        : "r"(a[0]), "r"(a[1]), "r"(a[2]), "r"(a[3]), "r"(b0), "r"(b1));
}
__device__ __forceinline__ unsigned long long pack2(float lo, float hi) {
    unsigned long long r;
    asm("mov.b64 %0, {%1, %2};" : "=l"(r) : "f"(lo), "f"(hi));
    return r;
}
__device__ __forceinline__ float2 unpack2(unsigned long long v) {
    float2 r;
    asm("mov.b64 {%0, %1}, %2;" : "=f"(r.x), "=f"(r.y) : "l"(v));
    return r;
}
__device__ __forceinline__ void fma2(unsigned long long &acc, unsigned long long a, unsigned long long b) {
    asm("fma.rn.f32x2 %0, %1, %2, %3;" : "=l"(acc) : "l"(a), "l"(b), "l"(acc));
}

// ================== fused pre-kernel: bq | ga | p-copy | prep ==================
// grid: [0,512) bq (64 queries/block, scheduled FIRST - longest pole),
//       [512,1024) ga, [1024,1056) copy, 1056 prep. block=512.
#define PRE_SMEM 67584

__global__ void __launch_bounds__(512) fused_pre(
        const float* __restrict__ p, const float* __restrict__ f,
        const float* __restrict__ w_attn, const float* __restrict__ b_attn,
        const float* __restrict__ w1, const float* __restrict__ b1,
        const float* __restrict__ w2,
        const float* __restrict__ wf1, const float* __restrict__ wf2,
        float* __restrict__ out) {
    extern __shared__ float sm[];
    int blk = blockIdx.x;
    int tid = threadIdx.x;

    if (blk < 512) {
        // ---------- bq: ball query, 64 queries/block (4 per warp), 64 candidates/iter ----------
        int bb = blk;
        float4* s_p4 = reinterpret_cast<float4*>(sm);
        int*    s_idx = reinterpret_cast<int*>(sm + 4*NN);

        int b     = bb >> 6;
        int nbase = (bb & 63) << 6;
        const float* pb = p + (size_t)b*NN*3;
        for (int jj = tid; jj < NN; jj += 512) {
            float x = pb[jj*3+0], y = pb[jj*3+1], z = pb[jj*3+2];
            float sq = __fadd_rn(__fadd_rn(__fmul_rn(x,x), __fmul_rn(y,y)), __fmul_rn(z,z));
            s_p4[jj] = make_float4(x, y, z, sq);
        }
        __syncthreads();

        int wi = tid >> 5, lane = tid & 31;
        const float r2 = (float)(0.15*0.15);
        unsigned lmask = (1u << lane) - 1u;
        int* my = s_idx + wi*KK;

#pragma unroll 1
        for (int qq = 0; qq < 4; qq++) {
            int n = nbase + wi*4 + qq;
            float4 pn = s_p4[n];
            float sqn = pn.w;
            float n2x = -2.0f*pn.x, n2y = -2.0f*pn.y, n2z = -2.0f*pn.z;

            int cnt = 0;
#pragma unroll 1
            for (int base = 0; base < NN && cnt < KK; base += 64) {
                float4 pa = s_p4[base + lane];
                float4 pbv = s_p4[base + 32 + lane];
                float d2a = fmaf(n2x, pa.x,  fmaf(n2y, pa.y,  fmaf(n2z, pa.z,  sqn + pa.w)));
                float d2b = fmaf(n2x, pbv.x, fmaf(n2y, pbv.y, fmaf(n2z, pbv.z, sqn + pbv.w)));
                bool wa = (d2a <= r2);
                bool wb = (d2b <= r2);
                unsigned m1 = __ballot_sync(0xffffffffu, wa);
                unsigned m2 = __ballot_sync(0xffffffffu, wb);
                int pos1 = cnt + __popc(m1 & lmask);
                if (wa && pos1 < KK) my[pos1] = base + lane;
                int c1 = cnt + __popc(m1);
                int pos2 = c1 + __popc(m2 & lmask);
                if (wb && pos2 < KK) my[pos2] = base + 32 + lane;
                cnt = c1 + __popc(m2);
            }
            __syncwarp();
            if (cnt > KK) cnt = KK;
            int v = my[(lane < cnt) ? lane : 0];
            g_idx[((size_t)b*NN + n)*KK + lane] = v;
            __syncwarp();
        }

    } else if (blk < 1024) {
        // ---------- ga: GA/G1 precompute -> merged g_G rows (FFMA2 accumulators) ----------
        float* s_f  = sm;
        float* s_wa = sm + 4096;
        float* s_w1 = sm + 8192;
        int gb = blk - 512;
        int b  = gb >> 6;
        int j0 = (gb & 63) << 6;

        for (int lin = tid; lin < 64*64; lin += 512) {
            int i = lin >> 6, c = lin & 63;
            s_wa[i*64 + c] = w_attn[c*CIN + 3 + i];
            s_w1[i*64 + c] = w1[c*CIN + 3 + i];
        }
        for (int lin = tid; lin < 64*64; lin += 512) {
            int i = lin >> 6, jj = lin & 63;
            s_f[i*64 + jj] = f[((size_t)b*CC + i)*NN + j0 + jj];
        }
        __syncthreads();

        int j  = tid & 63;
        int c0 = (tid >> 6) << 3;     // 8 channels per thread
        unsigned long long accA2[4], acc12[4];
#pragma unroll
        for (int q = 0; q < 4; q++) {
            accA2[q] = pack2(__ldg(&b_attn[c0+2*q]), __ldg(&b_attn[c0+2*q+1]));
            acc12[q] = pack2(__ldg(&b1[c0+2*q]),     __ldg(&b1[c0+2*q+1]));
        }

#pragma unroll 4
        for (int i = 0; i < 64; i++) {
            float fv = s_f[i*64 + j];
            unsigned long long fv2 = pack2(fv, fv);
            const ulonglong2* wa = reinterpret_cast<const ulonglong2*>(&s_wa[i*64 + c0]);
            const ulonglong2* wb = reinterpret_cast<const ulonglong2*>(&s_w1[i*64 + c0]);
            ulonglong2 A0 = wa[0], A1 = wa[1];
            ulonglong2 B0 = wb[0], B1 = wb[1];
            fma2(accA2[0], A0.x, fv2); fma2(accA2[1], A0.y, fv2);
            fma2(accA2[2], A1.x, fv2); fma2(accA2[3], A1.y, fv2);
            fma2(acc12[0], B0.x, fv2); fma2(acc12[1], B0.y, fv2);
            fma2(acc12[2], B1.x, fv2); fma2(acc12[3], B1.y, fv2);
        }
        size_t base = ((size_t)b*NN + j0 + j)*128 + c0;
        {
            float2 a0 = unpack2(accA2[0]), a1 = unpack2(accA2[1]);
            float2 a2 = unpack2(accA2[2]), a3 = unpack2(accA2[3]);
            *reinterpret_cast<float4*>(&g_G[base + 0]) = make_float4(a0.x, a0.y, a1.x, a1.y);
            *reinterpret_cast<float4*>(&g_G[base + 4]) = make_float4(a2.x, a2.y, a3.x, a3.y);
            float2 o0 = unpack2(acc12[0]), o1 = unpack2(acc12[1]);
            float2 o2 = unpack2(acc12[2]), o3 = unpack2(acc12[3]);
            *reinterpret_cast<float4*>(&g_G[base + 64]) = make_float4(o0.x, o0.y, o1.x, o1.y);
            *reinterpret_cast<float4*>(&g_G[base + 68]) = make_float4(o2.x, o2.y, o3.x, o3.y);
        }

    } else if (blk < 1056) {
        // ---------- p passthrough copy into out[0 : B*N*3) ----------
        int cb = blk - 1024;
        const float4* src = reinterpret_cast<const float4*>(p);
        float4* dst = reinterpret_cast<float4*>(out);
        int lo = cb*768, hi = lo + 768;
        for (int i = lo + tid; i < hi; i += 512) dst[i] = src[i];

    } else {
        // ---------- prep: weight repack ----------
        for (int i = tid; i < 3*128; i += 512) {
            int d = i / 128, u = i % 128;
            g_wD3[i] = (u < 64) ? w_attn[u*CIN + d] : w1[(u-64)*CIN + d];
        }
        // w2 B-fragments for mma.sync m16n8k16 (row.col): B[k=cp][n=c] = w2[c][cp]
        for (int i = tid; i < 2048; i += 512) {
            int r    = i & 1;
            int lane = (i >> 1) & 31;
            int nt   = (i >> 6) & 7;
            int kt   = i >> 9;
            int k0 = kt*16 + (lane & 3)*2 + r*8;
            int n  = nt*8 + (lane >> 2);
            float v0 = w2[n*64 + k0], v1 = w2[n*64 + k0 + 1];
            __nv_bfloat16 h0 = __float2bfloat16(v0), h1 = __float2bfloat16(v1);
            __nv_bfloat162 hi2; hi2.x = h0; hi2.y = h1;
            __nv_bfloat162 lo2;
            lo2.x = __float2bfloat16(v0 - __bfloat162float(h0));
            lo2.y = __float2bfloat16(v1 - __bfloat162float(h1));
            g_bfH[i] = *reinterpret_cast<uint32_t*>(&hi2);
            g_bfL[i] = *reinterpret_cast<uint32_t*>(&lo2);
        }
        for (int i = tid; i < CC*CC; i += 512) {
            int c = i / CC, cp = i % CC;
            g_wf1T[cp*CC + c] = wf1[i];
            g_wf2T[cp*CC + c] = wf2[i];
        }
    }
}

// ---------------- fused main: mma.sync GEMM, 4 points/block, 3 blocks/SM ----------------
#define SMM_RHI  0
#define SMM_RLO  18432
#define SMM_E    36864
#define SMM_META 55296
#define SM_MAIN  59392

__global__ void __launch_bounds__(256, 3) main_kernel(const float* __restrict__ p,
        const float* __restrict__ b2) {
    extern __shared__ char smc[];
    uint32_t smem_base = smem_u32(smc);
    float4* s_meta = reinterpret_cast<float4*>(smc + SMM_META);

    int tid  = threadIdx.x;
    int w    = tid >> 5;
    int lane = tid & 31;
    int pbase = blockIdx.x * 4;

    // meta: warps 0..3 stage (dp, j) for point w
    if (w < 4) {
        int pid = pbase + w;
        int b = pid >> 12, n = pid & 4095;
        int j = g_idx[(size_t)pid*KK + lane];
        const float* pn = p + ((size_t)b*NN + n)*3;
        const float* pj = p + ((size_t)b*NN + j)*3;
        float4 m;
        m.x = pj[0] - pn[0];
        m.y = pj[1] - pn[1];
        m.z = pj[2] - pn[2];
        m.w = __int_as_float(j);
        s_meta[w*32 + lane] = m;
    }
    __syncthreads();

    // ---- phase 1 (warp-specialized): warps 0-3 -> R(pt=w), warps 4-7 -> E(pt=w-4) ----
    // lane = (k-parity lh = lane>>4, channel-quad (lane&15)*4); iter kk covers k = kk*2 + lh.
    {
        bool isR = (w < 4);
        int pt = w & 3;
        int pid = pbase + pt;
        int b = pid >> 12;
        int lh  = lane >> 4;
        int u16 = (lane & 15) * 4;             // channel quad 0..60
        int u   = isR ? (64 + u16) : u16;      // G row offset: R reads G1 half, E reads GA half
        float4 wx = *reinterpret_cast<const float4*>(&g_wD3[0*128 + u]);
        float4 wy = *reinterpret_cast<const float4*>(&g_wD3[1*128 + u]);
        float4 wz = *reinterpret_cast<const float4*>(&g_wD3[2*128 + u]);
        __half* Ep = reinterpret_cast<__half*>(smc + SMM_E) + pt*2304;
        const float* Gb = g_G + (size_t)b*NN*128;

#pragma unroll 8
        for (int kk = 0; kk < 16; kk++) {
            int k = kk*2 + lh;
            float4 m = s_meta[pt*32 + k];
            int j = __float_as_int(m.w);
            float4 g = __ldg(reinterpret_cast<const float4*>(&Gb[(size_t)j*128 + u]));
            float4 v;
            v.x = g.x + wx.x*m.x + wy.x*m.y + wz.x*m.z;
            v.y = g.y + wx.y*m.x + wy.y*m.y + wz.y*m.z;
            v.z = g.z + wx.z*m.x + wy.z*m.y + wz.z*m.z;
            v.w = g.w + wx.w*m.x + wy.w*m.y + wz.w*m.z;
            if (isR) {
                float r0 = fmaxf(v.x, 0.0f), r1 = fmaxf(v.y, 0.0f);
                float r2v = fmaxf(v.z, 0.0f), r3 = fmaxf(v.w, 0.0f);
                __nv_bfloat16 h0 = __float2bfloat16(r0), h1 = __float2bfloat16(r1);
                __nv_bfloat16 h2 = __float2bfloat16(r2v), h3 = __float2bfloat16(r3);
                __nv_bfloat162 hp0; hp0.x = h0; hp0.y = h1;
                __nv_bfloat162 hp1; hp1.x = h2; hp1.y = h3;
                __nv_bfloat162 lp0; lp0.x = __float2bfloat16(r0 - __bfloat162float(h0));
                                    lp0.y = __float2bfloat16(r1 - __bfloat162float(h1));
                __nv_bfloat162 lp1; lp1.x = __float2bfloat16(r2v - __bfloat162float(h2));
                                    lp1.y = __float2bfloat16(r3 - __bfloat162float(h3));
                int row = pt*32 + k;
                uint32_t roff = (uint32_t)(row*72 + u16)*2;
                *reinterpret_cast<uint2*>(smc + SMM_RHI + roff) =
                    make_uint2(*reinterpret_cast<uint32_t*>(&hp0), *reinterpret_cast<uint32_t*>(&hp1));
                *reinterpret_cast<uint2*>(smc + SMM_RLO + roff) =
                    make_uint2(*reinterpret_cast<uint32_t*>(&lp0), *reinterpret_cast<uint32_t*>(&lp1));
            } else {
                union { __half2 h[2]; uint2 u2; } cv;
                cv.h[0] = __floats2half2_rn(__expf(v.x), __expf(v.y));
                cv.h[1] = __floats2half2_rn(__expf(v.z), __expf(v.w));
                *reinterpret_cast<uint2*>(&Ep[k*72 + u16]) = cv.u2;
            }
        }
    }
    __syncthreads();

    // ---- mma GEMM + softmax-weighted epilogue: warp = (pt = w&3, mh = w>>2) ----
    {
        int pt = w & 3;
        int mh = w >> 2;

        int r8 = lane & 7, mmat = lane >> 3;
        int arow = pt*32 + mh*16 + r8 + ((mmat & 1) << 3);
        uint32_t acolB = (uint32_t)(((mmat >> 1) << 3) * 2);
        uint32_t abase = smem_base + (uint32_t)(arow * 144) + acolB;

        float acc[8][4];
#pragma unroll
        for (int nt = 0; nt < 8; nt++)
#pragma unroll
            for (int q = 0; q < 4; q++) acc[nt][q] = 0.0f;

#pragma unroll
        for (int kt = 0; kt < 4; kt++) {
            uint32_t ah[4], al[4];
            ldsm_x4(ah, abase + SMM_RHI + kt*32);
            ldsm_x4(al, abase + SMM_RLO + kt*32);
#pragma unroll
            for (int nt = 0; nt < 8; nt++) {
                int bidx = ((kt*8 + nt)*32 + lane)*2;
                uint2 bh = __ldg(reinterpret_cast<const uint2*>(&g_bfH[bidx]));
                uint2 bl = __ldg(reinterpret_cast<const uint2*>(&g_bfL[bidx]));
                mma_bf16(acc[nt], ah, bh.x, bh.y);
                mma_bf16(acc[nt], al, bh.x, bh.y);
                mma_bf16(acc[nt], ah, bl.x, bl.y);
            }
        }

        const __half* Eb = reinterpret_cast<const __half*>(smc + SMM_E);
        float* red = reinterpret_cast<float*>(smc + SMM_META);
        int r0 = mh*16 + (lane >> 2);
        int c00 = (lane & 3) * 2;
#pragma unroll
        for (int nt = 0; nt < 8; nt++) {
            int c0 = nt*8 + c00;
            float2 e0 = __half22float2(*reinterpret_cast<const __half2*>(&Eb[pt*2304 + r0*72 + c0]));
            float2 e1 = __half22float2(*reinterpret_cast<const __half2*>(&Eb[pt*2304 + (r0+8)*72 + c0]));
            float num0 = e0.x*acc[nt][0] + e1.x*acc[nt][2];
            float num1 = e0.y*acc[nt][1] + e1.y*acc[nt][3];
            float den0 = e0.x + e1.x;
            float den1 = e0.y + e1.y;
#pragma unroll
            for (int off = 4; off <= 16; off <<= 1) {
                num0 += __shfl_xor_sync(0xffffffffu, num0, off);
                num1 += __shfl_xor_sync(0xffffffffu, num1, off);
                den0 += __shfl_xor_sync(0xffffffffu, den0, off);
                den1 += __shfl_xor_sync(0xffffffffu, den1, off);
            }
            if (lane < 4) {
                int base = ((mh*4 + pt)*64 + c0)*2;
                red[base+0] = num0; red[base+1] = den0;
                red[base+2] = num1; red[base+3] = den1;
            }
        }
    }
    __syncthreads();

    // ---- final: combine mh halves, divide, add bias, coalesced store ----
    {
        int pt = tid >> 6, c = tid & 63;
        const float* red = reinterpret_cast<const float*>(smc + SMM_META);
        float num = red[(pt*64 + c)*2 + 0] + red[((4 + pt)*64 + c)*2 + 0];
        float den = red[(pt*64 + c)*2 + 1] + red[((4 + pt)*64 + c)*2 + 1];
        g_F0[(size_t)(pbase + pt)*CC + c] = num / den + __ldg(&b2[c]);
    }
}

// ---------------- tail: relu(F0+f) -> 2x (64x64) MLP -> relu residual ----------------
__global__ void __launch_bounds__(256) tail_kernel(const float* __restrict__ f,
        const float* __restrict__ bf1, const float* __restrict__ bf2,
        float* __restrict__ outF) {
    __shared__ float s_F1[64*68];
    __shared__ float s_H[64*68];

    int b   = blockIdx.x >> 6;
    int n0g = (blockIdx.x & 63) << 6;
    int tid = threadIdx.x;

    {
        int c = tid >> 2, q = tid & 3;
        const float* frow = f + ((size_t)b*CC + c)*NN + n0g;
        const float* f0b  = g_F0 + ((size_t)b*NN + n0g)*CC + c;
#pragma unroll
        for (int i = 0; i < 4; i++) {
            int nn = q*16 + i*4;
            float4 fv = *reinterpret_cast<const float4*>(frow + nn);
            float a0 = __ldg(&f0b[(nn+0)*CC]);
            float a1 = __ldg(&f0b[(nn+1)*CC]);
            float a2 = __ldg(&f0b[(nn+2)*CC]);
            float a3 = __ldg(&f0b[(nn+3)*CC]);
            float4 r;
            r.x = fmaxf(a0 + fv.x, 0.0f);
            r.y = fmaxf(a1 + fv.y, 0.0f);
            r.z = fmaxf(a2 + fv.z, 0.0f);
            r.w = fmaxf(a3 + fv.w, 0.0f);
            *reinterpret_cast<float4*>(&s_F1[c*68 + nn]) = r;
        }
    }
    __syncthreads();

    int ct = (tid >> 4) << 2;
    int nt = (tid & 15) << 2;

    {
        float acc[16];
#pragma unroll
        for (int r = 0; r < 4; r++) {
            float bv = __ldg(&bf1[ct+r]);
#pragma unroll
            for (int jj = 0; jj < 4; jj++) acc[r*4+jj] = bv;
        }
#pragma unroll 4
        for (int cp = 0; cp < 64; cp++) {
            float4 wv = __ldg(reinterpret_cast<const float4*>(&g_wf1T[cp*64 + ct]));
            float4 fv = *reinterpret_cast<const float4*>(&s_F1[cp*68 + nt]);
            acc[0]  += wv.x*fv.x; acc[1]  += wv.x*fv.y; acc[2]  += wv.x*fv.z; acc[3]  += wv.x*fv.w;
            acc[4]  += wv.y*fv.x; acc[5]  += wv.y*fv.y; acc[6]  += wv.y*fv.z; acc[7]  += wv.y*fv.w;
            acc[8]  += wv.z*fv.x; acc[9]  += wv.z*fv.y; acc[10] += wv.z*fv.z; acc[11] += wv.z*fv.w;
            acc[12] += wv.w*fv.x; acc[13] += wv.w*fv.y; acc[14] += wv.w*fv.z; acc[15] += wv.w*fv.w;
        }
#pragma unroll
        for (int r = 0; r < 4; r++) {
            float4 o;
            o.x = fmaxf(acc[r*4+0], 0.0f);
            o.y = fmaxf(acc[r*4+1], 0.0f);
            o.z = fmaxf(acc[r*4+2], 0.0f);
            o.w = fmaxf(acc[r*4+3], 0.0f);
            *reinterpret_cast<float4*>(&s_H[(ct+r)*68 + nt]) = o;
        }
    }
    __syncthreads();

    {
        float acc[16];
#pragma unroll
        for (int r = 0; r < 4; r++) {
            float bv = __ldg(&bf2[ct+r]);
#pragma unroll
            for (int jj = 0; jj < 4; jj++) acc[r*4+jj] = bv;
        }
#pragma unroll 4
        for (int cp = 0; cp < 64; cp++) {
            float4 wv = __ldg(reinterpret_cast<const float4*>(&g_wf2T[cp*64 + ct]));
            float4 hv = *reinterpret_cast<const float4*>(&s_H[cp*68 + nt]);
            acc[0]  += wv.x*hv.x; acc[1]  += wv.x*hv.y; acc[2]  += wv.x*hv.z; acc[3]  += wv.x*hv.w;
            acc[4]  += wv.y*hv.x; acc[5]  += wv.y*hv.y; acc[6]  += wv.y*hv.z; acc[7]  += wv.y*hv.w;
            acc[8]  += wv.z*hv.x; acc[9]  += wv.z*hv.y; acc[10] += wv.z*hv.z; acc[11] += wv.z*hv.w;
            acc[12] += wv.w*hv.x; acc[13] += wv.w*hv.y; acc[14] += wv.w*hv.z; acc[15] += wv.w*hv.w;
        }
#pragma unroll
        for (int r = 0; r < 4; r++) {
            const float* idn = &s_F1[(ct+r)*68 + nt];
            float4 o;
            o.x = fmaxf(acc[r*4+0] + idn[0], 0.0f);
            o.y = fmaxf(acc[r*4+1] + idn[1], 0.0f);
            o.z = fmaxf(acc[r*4+2] + idn[2], 0.0f);
            o.w = fmaxf(acc[r*4+3] + idn[3], 0.0f);
            *reinterpret_cast<float4*>(&outF[((size_t)b*CC + ct + r)*NN + n0g + nt]) = o;
        }
    }
}

// ---------------- launch ----------------
extern "C" void kernel_launch(void* const* d_in, const int* in_sizes, int n_in,
                              void* d_out, int out_size) {
    const float* p      = (const float*)d_in[0];
    const float* f      = (const float*)d_in[1];
    const float* w_attn = (const float*)d_in[2];
    const float* b_attn = (const float*)d_in[3];
    const float* w1     = (const float*)d_in[4];
    const float* b1     = (const float*)d_in[5];
    const float* w2     = (const float*)d_in[6];
    const float* b2     = (const float*)d_in[7];
    const float* wf1    = (const float*)d_in[8];
    const float* bf1    = (const float*)d_in[9];
    const float* wf2    = (const float*)d_in[10];
    const float* bf2    = (const float*)d_in[11];
    float* out = (float*)d_out;

    cudaFuncSetAttribute(fused_pre, cudaFuncAttributeMaxDynamicSharedMemorySize, PRE_SMEM);
    fused_pre<<<1057, 512, PRE_SMEM>>>(p, f, w_attn, b_attn, w1, b1, w2, wf1, wf2, out);

    cudaFuncSetAttribute(main_kernel, cudaFuncAttributeMaxDynamicSharedMemorySize, SM_MAIN);
    main_kernel<<<BB*NN/4, 256, SM_MAIN>>>(p, b2);

    tail_kernel<<<BB*(NN/64), 256>>>(f, bf1, bf2, out + (size_t)BB*NN*3);
}

// round 11
// speedup vs baseline: 3.0498x; 1.0047x over previous
#include <cuda_runtime.h>
#include <cuda_fp16.h>
#include <cuda_bf16.h>
#include <cstdint>
#include <cstddef>

#define BB  8
#define NN  4096
#define KK  32
#define CC  64
#define CIN 67

// -------- scratch (no allocation allowed -> __device__ globals) --------
__device__ __align__(16) float g_G[(size_t)BB*NN*128]; // merged [b][j][0:64]=GA, [64:128]=G1
__device__ __align__(16) float g_F0[(size_t)BB*NN*CC]; // attention output (pre-residual), [b, n, c]
__device__ int   g_idx[(size_t)BB*NN*KK];              // ball-query neighbor indices
__device__ __align__(16) float g_wD3[3*128];           // [d][u]: u<64 -> w_attn[u][d], else w1[u-64][d]
__device__ __align__(16) uint32_t g_bfH[2048];         // w2 hi-bf16 B-fragments [kt][nt][lane][2]
__device__ __align__(16) uint32_t g_bfL[2048];         // w2 lo-bf16 residual fragments
__device__ __align__(16) float g_wf1T[CC*CC];          // wf1 transposed [cp][c]
__device__ __align__(16) float g_wf2T[CC*CC];          // wf2 transposed [cp][c]

// ---------------- helpers ----------------
__device__ __forceinline__ uint32_t smem_u32(const void* p_) {
    uint32_t a;
    asm("{ .reg .u64 t; cvta.to.shared.u64 t, %1; cvt.u32.u64 %0, t; }" : "=r"(a) : "l"(p_));
    return a;
}
__device__ __forceinline__ void ldsm_x4(uint32_t* r, uint32_t addr) {
    asm volatile("ldmatrix.sync.aligned.m8n8.x4.shared.b16 {%0,%1,%2,%3}, [%4];"
        : "=r"(r[0]), "=r"(r[1]), "=r"(r[2]), "=r"(r[3]) : "r"(addr));
}
__device__ __forceinline__ void mma_bf16(float* d, const uint32_t* a, uint32_t b0, uint32_t b1) {
    asm volatile("mma.sync.aligned.m16n8k16.row.col.f32.bf16.bf16.f32 "
        "{%0,%1,%2,%3}, {%4,%5,%6,%7}, {%8,%9}, {%0,%1,%2,%3};"
        : "+f"(d[0]), "+f"(d[1]), "+f"(d[2]), "+f"(d[3])
        : "r"(a[0]), "r"(a[1]), "r"(a[2]), "r"(a[3]), "r"(b0), "r"(b1));
}
__device__ __forceinline__ unsigned long long pack2(float lo, float hi) {
    unsigned long long r;
    asm("mov.b64 %0, {%1, %2};" : "=l"(r) : "f"(lo), "f"(hi));
    return r;
}
__device__ __forceinline__ float2 unpack2(unsigned long long v) {
    float2 r;
    asm("mov.b64 {%0, %1}, %2;" : "=f"(r.x), "=f"(r.y) : "l"(v));
    return r;
}
__device__ __forceinline__ void fma2(unsigned long long &acc, unsigned long long a, unsigned long long b) {
    asm("fma.rn.f32x2 %0, %1, %2, %3;" : "=l"(acc) : "l"(a), "l"(b), "l"(acc));
}

// ================== fused pre-kernel: bq | ga | p-copy | prep ==================
// grid: [0,512) bq (64 queries/block, 2 queries share each candidate stream),
//       [512,1024) ga, [1024,1056) copy, 1056 prep. block=512.
#define PRE_SMEM 73728

__global__ void __launch_bounds__(512) fused_pre(
        const float* __restrict__ p, const float* __restrict__ f,
        const float* __restrict__ w_attn, const float* __restrict__ b_attn,
        const float* __restrict__ w1, const float* __restrict__ b1,
        const float* __restrict__ w2,
        const float* __restrict__ wf1, const float* __restrict__ wf2,
        float* __restrict__ out) {
    extern __shared__ float sm[];
    int blk = blockIdx.x;
    int tid = threadIdx.x;

    if (blk < 512) {
        // ---------- bq: ball query, 64 queries/block; 2 queries per candidate stream ----------
        int bb = blk;
        float4* s_p4 = reinterpret_cast<float4*>(sm);
        int*    s_idx = reinterpret_cast<int*>(sm + 4*NN);   // [16 warps][4][KK]

        int b     = bb >> 6;
        int nbase = (bb & 63) << 6;
        const float* pb = p + (size_t)b*NN*3;
        for (int jj = tid; jj < NN; jj += 512) {
            float x = pb[jj*3+0], y = pb[jj*3+1], z = pb[jj*3+2];
            float sq = __fadd_rn(__fadd_rn(__fmul_rn(x,x), __fmul_rn(y,y)), __fmul_rn(z,z));
            s_p4[jj] = make_float4(x, y, z, sq);
        }
        __syncthreads();

        int wi = tid >> 5, lane = tid & 31;
        const float r2 = (float)(0.15*0.15);
        unsigned lmask = (1u << lane) - 1u;

#pragma unroll 1
        for (int pr = 0; pr < 2; pr++) {
            int n0 = nbase + wi*4 + pr*2;
            float4 q0 = s_p4[n0];
            float4 q1 = s_p4[n0 + 1];
            float sq0 = q0.w, a0x = -2.0f*q0.x, a0y = -2.0f*q0.y, a0z = -2.0f*q0.z;
            float sq1 = q1.w, a1x = -2.0f*q1.x, a1y = -2.0f*q1.y, a1z = -2.0f*q1.z;
            int* my0 = s_idx + (wi*4 + pr*2)*KK;
            int* my1 = my0 + KK;

            int c0 = 0, c1 = 0;
#pragma unroll 1
            for (int base = 0; base < NN && (c0 < KK || c1 < KK); base += 32) {
                float4 pc = s_p4[base + lane];
                float d20 = fmaf(a0x, pc.x, fmaf(a0y, pc.y, fmaf(a0z, pc.z, sq0 + pc.w)));
                float d21 = fmaf(a1x, pc.x, fmaf(a1y, pc.y, fmaf(a1z, pc.z, sq1 + pc.w)));
                bool w0 = (d20 <= r2);
                bool w1v = (d21 <= r2);
                unsigned m0 = __ballot_sync(0xffffffffu, w0);
                unsigned m1 = __ballot_sync(0xffffffffu, w1v);
                int p0 = c0 + __popc(m0 & lmask);
                if (w0 && p0 < KK) my0[p0] = base + lane;
                int p1 = c1 + __popc(m1 & lmask);
                if (w1v && p1 < KK) my1[p1] = base + lane;
                c0 += __popc(m0);
                c1 += __popc(m1);
            }
            __syncwarp();
            if (c0 > KK) c0 = KK;
            if (c1 > KK) c1 = KK;
            g_idx[((size_t)b*NN + n0)*KK + lane]     = my0[(lane < c0) ? lane : 0];
            g_idx[((size_t)b*NN + n0 + 1)*KK + lane] = my1[(lane < c1) ? lane : 0];
            __syncwarp();
        }

    } else if (blk < 1024) {
        // ---------- ga: GA/G1 precompute -> merged g_G rows (FFMA2 accumulators) ----------
        float* s_f  = sm;
        float* s_wa = sm + 4096;
        float* s_w1 = sm + 8192;
        int gb = blk - 512;
        int b  = gb >> 6;
        int j0 = (gb & 63) << 6;

        for (int lin = tid; lin < 64*64; lin += 512) {
            int i = lin >> 6, c = lin & 63;
            s_wa[i*64 + c] = w_attn[c*CIN + 3 + i];
            s_w1[i*64 + c] = w1[c*CIN + 3 + i];
        }
        for (int lin = tid; lin < 64*64; lin += 512) {
            int i = lin >> 6, jj = lin & 63;
            s_f[i*64 + jj] = f[((size_t)b*CC + i)*NN + j0 + jj];
        }
        __syncthreads();

        int j  = tid & 63;
        int c0 = (tid >> 6) << 3;     // 8 channels per thread
        unsigned long long accA2[4], acc12[4];
#pragma unroll
        for (int q = 0; q < 4; q++) {
            accA2[q] = pack2(__ldg(&b_attn[c0+2*q]), __ldg(&b_attn[c0+2*q+1]));
            acc12[q] = pack2(__ldg(&b1[c0+2*q]),     __ldg(&b1[c0+2*q+1]));
        }

#pragma unroll 4
        for (int i = 0; i < 64; i++) {
            float fv = s_f[i*64 + j];
            unsigned long long fv2 = pack2(fv, fv);
            const ulonglong2* wa = reinterpret_cast<const ulonglong2*>(&s_wa[i*64 + c0]);
            const ulonglong2* wb = reinterpret_cast<const ulonglong2*>(&s_w1[i*64 + c0]);
            ulonglong2 A0 = wa[0], A1 = wa[1];
            ulonglong2 B0 = wb[0], B1 = wb[1];
            fma2(accA2[0], A0.x, fv2); fma2(accA2[1], A0.y, fv2);
            fma2(accA2[2], A1.x, fv2); fma2(accA2[3], A1.y, fv2);
            fma2(acc12[0], B0.x, fv2); fma2(acc12[1], B0.y, fv2);
            fma2(acc12[2], B1.x, fv2); fma2(acc12[3], B1.y, fv2);
        }
        size_t base = ((size_t)b*NN + j0 + j)*128 + c0;
        {
            float2 a0 = unpack2(accA2[0]), a1 = unpack2(accA2[1]);
            float2 a2 = unpack2(accA2[2]), a3 = unpack2(accA2[3]);
            *reinterpret_cast<float4*>(&g_G[base + 0]) = make_float4(a0.x, a0.y, a1.x, a1.y);
            *reinterpret_cast<float4*>(&g_G[base + 4]) = make_float4(a2.x, a2.y, a3.x, a3.y);
            float2 o0 = unpack2(acc12[0]), o1 = unpack2(acc12[1]);
            float2 o2 = unpack2(acc12[2]), o3 = unpack2(acc12[3]);
            *reinterpret_cast<float4*>(&g_G[base + 64]) = make_float4(o0.x, o0.y, o1.x, o1.y);
            *reinterpret_cast<float4*>(&g_G[base + 68]) = make_float4(o2.x, o2.y, o3.x, o3.y);
        }

    } else if (blk < 1056) {
        // ---------- p passthrough copy into out[0 : B*N*3) ----------
        int cb = blk - 1024;
        const float4* src = reinterpret_cast<const float4*>(p);
        float4* dst = reinterpret_cast<float4*>(out);
        int lo = cb*768, hi = lo + 768;
        for (int i = lo + tid; i < hi; i += 512) dst[i] = src[i];

    } else {
        // ---------- prep: weight repack ----------
        for (int i = tid; i < 3*128; i += 512) {
            int d = i / 128, u = i % 128;
            g_wD3[i] = (u < 64) ? w_attn[u*CIN + d] : w1[(u-64)*CIN + d];
        }
        // w2 B-fragments for mma.sync m16n8k16 (row.col): B[k=cp][n=c] = w2[c][cp]
        for (int i = tid; i < 2048; i += 512) {
            int r    = i & 1;
            int lane = (i >> 1) & 31;
            int nt   = (i >> 6) & 7;
            int kt   = i >> 9;
            int k0 = kt*16 + (lane & 3)*2 + r*8;
            int n  = nt*8 + (lane >> 2);
            float v0 = w2[n*64 + k0], v1 = w2[n*64 + k0 + 1];
            __nv_bfloat16 h0 = __float2bfloat16(v0), h1 = __float2bfloat16(v1);
            __nv_bfloat162 hi2; hi2.x = h0; hi2.y = h1;
            __nv_bfloat162 lo2;
            lo2.x = __float2bfloat16(v0 - __bfloat162float(h0));
            lo2.y = __float2bfloat16(v1 - __bfloat162float(h1));
            g_bfH[i] = *reinterpret_cast<uint32_t*>(&hi2);
            g_bfL[i] = *reinterpret_cast<uint32_t*>(&lo2);
        }
        for (int i = tid; i < CC*CC; i += 512) {
            int c = i / CC, cp = i % CC;
            g_wf1T[cp*CC + c] = wf1[i];
            g_wf2T[cp*CC + c] = wf2[i];
        }
    }
}

// ---------------- fused main: mma.sync GEMM, 4 points/block, 3 blocks/SM ----------------
#define SMM_RHI  0
#define SMM_RLO  18432
#define SMM_E    36864
#define SMM_META 55296
#define SM_MAIN  59392

__global__ void __launch_bounds__(256, 3) main_kernel(const float* __restrict__ p,
        const float* __restrict__ b2) {
    extern __shared__ char smc[];
    uint32_t smem_base = smem_u32(smc);
    float4* s_meta = reinterpret_cast<float4*>(smc + SMM_META);

    int tid  = threadIdx.x;
    int w    = tid >> 5;
    int lane = tid & 31;
    int pbase = blockIdx.x * 4;

    // meta: warps 0..3 stage (dp, j) for point w
    if (w < 4) {
        int pid = pbase + w;
        int b = pid >> 12, n = pid & 4095;
        int j = g_idx[(size_t)pid*KK + lane];
        const float* pn = p + ((size_t)b*NN + n)*3;
        const float* pj = p + ((size_t)b*NN + j)*3;
        float4 m;
        m.x = pj[0] - pn[0];
        m.y = pj[1] - pn[1];
        m.z = pj[2] - pn[2];
        m.w = __int_as_float(j);
        s_meta[w*32 + lane] = m;
    }
    __syncthreads();

    // ---- phase 1 (warp-specialized): warps 0-3 -> R(pt=w), warps 4-7 -> E(pt=w-4) ----
    {
        bool isR = (w < 4);
        int pt = w & 3;
        int pid = pbase + pt;
        int b = pid >> 12;
        int lh  = lane >> 4;
        int u16 = (lane & 15) * 4;             // channel quad 0..60
        int u   = isR ? (64 + u16) : u16;      // G row offset: R reads G1 half, E reads GA half
        float4 wx = *reinterpret_cast<const float4*>(&g_wD3[0*128 + u]);
        float4 wy = *reinterpret_cast<const float4*>(&g_wD3[1*128 + u]);
        float4 wz = *reinterpret_cast<const float4*>(&g_wD3[2*128 + u]);
        __half* Ep = reinterpret_cast<__half*>(smc + SMM_E) + pt*2304;
        const float* Gb = g_G + (size_t)b*NN*128;

#pragma unroll 8
        for (int kk = 0; kk < 16; kk++) {
            int k = kk*2 + lh;
            float4 m = s_meta[pt*32 + k];
            int j = __float_as_int(m.w);
            float4 g = __ldg(reinterpret_cast<const float4*>(&Gb[(size_t)j*128 + u]));
            float4 v;
            v.x = g.x + wx.x*m.x + wy.x*m.y + wz.x*m.z;
            v.y = g.y + wx.y*m.x + wy.y*m.y + wz.y*m.z;
            v.z = g.z + wx.z*m.x + wy.z*m.y + wz.z*m.z;
            v.w = g.w + wx.w*m.x + wy.w*m.y + wz.w*m.z;
            if (isR) {
                float r0 = fmaxf(v.x, 0.0f), r1 = fmaxf(v.y, 0.0f);
                float r2v = fmaxf(v.z, 0.0f), r3 = fmaxf(v.w, 0.0f);
                __nv_bfloat16 h0 = __float2bfloat16(r0), h1 = __float2bfloat16(r1);
                __nv_bfloat16 h2 = __float2bfloat16(r2v), h3 = __float2bfloat16(r3);
                __nv_bfloat162 hp0; hp0.x = h0; hp0.y = h1;
                __nv_bfloat162 hp1; hp1.x = h2; hp1.y = h3;
                __nv_bfloat162 lp0; lp0.x = __float2bfloat16(r0 - __bfloat162float(h0));
                                    lp0.y = __float2bfloat16(r1 - __bfloat162float(h1));
                __nv_bfloat162 lp1; lp1.x = __float2bfloat16(r2v - __bfloat162float(h2));
                                    lp1.y = __float2bfloat16(r3 - __bfloat162float(h3));
                int row = pt*32 + k;
                uint32_t roff = (uint32_t)(row*72 + u16)*2;
                *reinterpret_cast<uint2*>(smc + SMM_RHI + roff) =
                    make_uint2(*reinterpret_cast<uint32_t*>(&hp0), *reinterpret_cast<uint32_t*>(&hp1));
                *reinterpret_cast<uint2*>(smc + SMM_RLO + roff) =
                    make_uint2(*reinterpret_cast<uint32_t*>(&lp0), *reinterpret_cast<uint32_t*>(&lp1));
            } else {
                union { __half2 h[2]; uint2 u2; } cv;
                cv.h[0] = __floats2half2_rn(__expf(v.x), __expf(v.y));
                cv.h[1] = __floats2half2_rn(__expf(v.z), __expf(v.w));
                *reinterpret_cast<uint2*>(&Ep[k*72 + u16]) = cv.u2;
            }
        }
    }
    __syncthreads();

    // ---- mma GEMM + softmax-weighted epilogue: warp = (pt = w&3, mh = w>>2) ----
    {
        int pt = w & 3;
        int mh = w >> 2;

        int r8 = lane & 7, mmat = lane >> 3;
        int arow = pt*32 + mh*16 + r8 + ((mmat & 1) << 3);
        uint32_t acolB = (uint32_t)(((mmat >> 1) << 3) * 2);
        uint32_t abase = smem_base + (uint32_t)(arow * 144) + acolB;

        float acc[8][4];
#pragma unroll
        for (int nt = 0; nt < 8; nt++)
#pragma unroll
            for (int q = 0; q < 4; q++) acc[nt][q] = 0.0f;

#pragma unroll
        for (int kt = 0; kt < 4; kt++) {
            uint32_t ah[4], al[4];
            ldsm_x4(ah, abase + SMM_RHI + kt*32);
            ldsm_x4(al, abase + SMM_RLO + kt*32);
#pragma unroll
            for (int nt = 0; nt < 8; nt++) {
                int bidx = ((kt*8 + nt)*32 + lane)*2;
                uint2 bh = __ldg(reinterpret_cast<const uint2*>(&g_bfH[bidx]));
                uint2 bl = __ldg(reinterpret_cast<const uint2*>(&g_bfL[bidx]));
                mma_bf16(acc[nt], ah, bh.x, bh.y);
                mma_bf16(acc[nt], al, bh.x, bh.y);
                mma_bf16(acc[nt], ah, bl.x, bl.y);
            }
        }

        // Epilogue with distributed merging reduction over lane bits {2,3,4}:
        // initial values per lane: v0=num0, v1=num1, v2=den0, v3=den1.
        // After 3 steps, lane (bits: 0,1 = c-quad, 2 = kind num/den, 3 = channel parity)
        // holds its complete sum; lanes >= 16 are duplicates.
        const __half* Eb = reinterpret_cast<const __half*>(smc + SMM_E);
        float* red = reinterpret_cast<float*>(smc + SMM_META);
        int r0 = mh*16 + (lane >> 2);
        int c00 = (lane & 3) * 2;
#pragma unroll
        for (int nt = 0; nt < 8; nt++) {
            int c0 = nt*8 + c00;
            float2 e0 = __half22float2(*reinterpret_cast<const __half2*>(&Eb[pt*2304 + r0*72 + c0]));
            float2 e1 = __half22float2(*reinterpret_cast<const __half2*>(&Eb[pt*2304 + (r0+8)*72 + c0]));
            float v0 = e0.x*acc[nt][0] + e1.x*acc[nt][2];   // num0
            float v1 = e0.y*acc[nt][1] + e1.y*acc[nt][3];   // num1
            float v2 = e0.x + e1.x;                          // den0
            float v3 = e0.y + e1.y;                          // den1
            bool up4 = (lane & 4) != 0;
            float s0 = up4 ? v0 : v2;
            float s1 = up4 ? v1 : v3;
            float rA = __shfl_xor_sync(0xffffffffu, s0, 4);
            float rB = __shfl_xor_sync(0xffffffffu, s1, 4);
            v0 = (up4 ? v2 : v0) + rA;
            v1 = (up4 ? v3 : v1) + rB;
            bool up8 = (lane & 8) != 0;
            float s2 = up8 ? v0 : v1;
            float rC = __shfl_xor_sync(0xffffffffu, s2, 8);
            v0 = (up8 ? v1 : v0) + rC;
            v0 += __shfl_xor_sync(0xffffffffu, v0, 16);
            if (lane < 16) {
                int c = nt*8 + (lane & 3)*2 + ((lane >> 3) & 1);
                int d = (lane >> 2) & 1;
                red[((mh*4 + pt)*64 + c)*2 + d] = v0;
            }
        }
    }
    __syncthreads();

    // ---- final: combine mh halves, divide, add bias, coalesced store ----
    {
        int pt = tid >> 6, c = tid & 63;
        const float* red = reinterpret_cast<const float*>(smc + SMM_META);
        float num = red[(pt*64 + c)*2 + 0] + red[((4 + pt)*64 + c)*2 + 0];
        float den = red[(pt*64 + c)*2 + 1] + red[((4 + pt)*64 + c)*2 + 1];
        g_F0[(size_t)(pbase + pt)*CC + c] = num / den + __ldg(&b2[c]);
    }
}

// ---------------- tail: relu(F0+f) -> 2x (64x64) MLP -> relu residual ----------------
__global__ void __launch_bounds__(256) tail_kernel(const float* __restrict__ f,
        const float* __restrict__ bf1, const float* __restrict__ bf2,
        float* __restrict__ outF) {
    __shared__ float s_F1[64*68];
    __shared__ float s_H[64*68];

    int b   = blockIdx.x >> 6;
    int n0g = (blockIdx.x & 63) << 6;
    int tid = threadIdx.x;

    {
        int c = tid >> 2, q = tid & 3;
        const float* frow = f + ((size_t)b*CC + c)*NN + n0g;
        const float* f0b  = g_F0 + ((size_t)b*NN + n0g)*CC + c;
#pragma unroll
        for (int i = 0; i < 4; i++) {
            int nn = q*16 + i*4;
            float4 fv = *reinterpret_cast<const float4*>(frow + nn);
            float a0 = __ldg(&f0b[(nn+0)*CC]);
            float a1 = __ldg(&f0b[(nn+1)*CC]);
            float a2 = __ldg(&f0b[(nn+2)*CC]);
            float a3 = __ldg(&f0b[(nn+3)*CC]);
            float4 r;
            r.x = fmaxf(a0 + fv.x, 0.0f);
            r.y = fmaxf(a1 + fv.y, 0.0f);
            r.z = fmaxf(a2 + fv.z, 0.0f);
            r.w = fmaxf(a3 + fv.w, 0.0f);
            *reinterpret_cast<float4*>(&s_F1[c*68 + nn]) = r;
        }
    }
    __syncthreads();

    int ct = (tid >> 4) << 2;
    int nt = (tid & 15) << 2;

    {
        float acc[16];
#pragma unroll
        for (int r = 0; r < 4; r++) {
            float bv = __ldg(&bf1[ct+r]);
#pragma unroll
            for (int jj = 0; jj < 4; jj++) acc[r*4+jj] = bv;
        }
#pragma unroll 4
        for (int cp = 0; cp < 64; cp++) {
            float4 wv = __ldg(reinterpret_cast<const float4*>(&g_wf1T[cp*64 + ct]));
            float4 fv = *reinterpret_cast<const float4*>(&s_F1[cp*68 + nt]);
            acc[0]  += wv.x*fv.x; acc[1]  += wv.x*fv.y; acc[2]  += wv.x*fv.z; acc[3]  += wv.x*fv.w;
            acc[4]  += wv.y*fv.x; acc[5]  += wv.y*fv.y; acc[6]  += wv.y*fv.z; acc[7]  += wv.y*fv.w;
            acc[8]  += wv.z*fv.x; acc[9]  += wv.z*fv.y; acc[10] += wv.z*fv.z; acc[11] += wv.z*fv.w;
            acc[12] += wv.w*fv.x; acc[13] += wv.w*fv.y; acc[14] += wv.w*fv.z; acc[15] += wv.w*fv.w;
        }
#pragma unroll
        for (int r = 0; r < 4; r++) {
            float4 o;
            o.x = fmaxf(acc[r*4+0], 0.0f);
            o.y = fmaxf(acc[r*4+1], 0.0f);
            o.z = fmaxf(acc[r*4+2], 0.0f);
            o.w = fmaxf(acc[r*4+3], 0.0f);
            *reinterpret_cast<float4*>(&s_H[(ct+r)*68 + nt]) = o;
        }
    }
    __syncthreads();

    {
        float acc[16];
#pragma unroll
        for (int r = 0; r < 4; r++) {
            float bv = __ldg(&bf2[ct+r]);
#pragma unroll
            for (int jj = 0; jj < 4; jj++) acc[r*4+jj] = bv;
        }
#pragma unroll 4
        for (int cp = 0; cp < 64; cp++) {
            float4 wv = __ldg(reinterpret_cast<const float4*>(&g_wf2T[cp*64 + ct]));
            float4 hv = *reinterpret_cast<const float4*>(&s_H[cp*68 + nt]);
            acc[0]  += wv.x*hv.x; acc[1]  += wv.x*hv.y; acc[2]  += wv.x*hv.z; acc[3]  += wv.x*hv.w;
            acc[4]  += wv.y*hv.x; acc[5]  += wv.y*hv.y; acc[6]  += wv.y*hv.z; acc[7]  += wv.y*hv.w;
            acc[8]  += wv.z*hv.x; acc[9]  += wv.z*hv.y; acc[10] += wv.z*hv.z; acc[11] += wv.z*hv.w;
            acc[12] += wv.w*hv.x; acc[13] += wv.w*hv.y; acc[14] += wv.w*hv.z; acc[15] += wv.w*hv.w;
        }
#pragma unroll
        for (int r = 0; r < 4; r++) {
            const float* idn = &s_F1[(ct+r)*68 + nt];
            float4 o;
            o.x = fmaxf(acc[r*4+0] + idn[0], 0.0f);
            o.y = fmaxf(acc[r*4+1] + idn[1], 0.0f);
            o.z = fmaxf(acc[r*4+2] + idn[2], 0.0f);
            o.w = fmaxf(acc[r*4+3] + idn[3], 0.0f);
            *reinterpret_cast<float4*>(&outF[((size_t)b*CC + ct + r)*NN + n0g + nt]) = o;
        }
    }
}

// ---------------- launch ----------------
extern "C" void kernel_launch(void* const* d_in, const int* in_sizes, int n_in,
                              void* d_out, int out_size) {
    const float* p      = (const float*)d_in[0];
    const float* f      = (const float*)d_in[1];
    const float* w_attn = (const float*)d_in[2];
    const float* b_attn = (const float*)d_in[3];
    const float* w1     = (const float*)d_in[4];
    const float* b1     = (const float*)d_in[5];
    const float* w2     = (const float*)d_in[6];
    const float* b2     = (const float*)d_in[7];
    const float* wf1    = (const float*)d_in[8];
    const float* bf1    = (const float*)d_in[9];
    const float* wf2    = (const float*)d_in[10];
    const float* bf2    = (const float*)d_in[11];
    float* out = (float*)d_out;

    cudaFuncSetAttribute(fused_pre, cudaFuncAttributeMaxDynamicSharedMemorySize, PRE_SMEM);
    fused_pre<<<1057, 512, PRE_SMEM>>>(p, f, w_attn, b_attn, w1, b1, w2, wf1, wf2, out);

    cudaFuncSetAttribute(main_kernel, cudaFuncAttributeMaxDynamicSharedMemorySize, SM_MAIN);
    main_kernel<<<BB*NN/4, 256, SM_MAIN>>>(p, b2);

    tail_kernel<<<BB*(NN/64), 256>>>(f, bf1, bf2, out + (size_t)BB*NN*3);
}

// round 12
// speedup vs baseline: 3.0678x; 1.0059x over previous
#include <cuda_runtime.h>
#include <cuda_fp16.h>
#include <cuda_bf16.h>
#include <cstdint>
#include <cstddef>

#define BB  8
#define NN  4096
#define KK  32
#define CC  64
#define CIN 67
#define NCELL 216   // 6x6x6

// -------- scratch (no allocation allowed -> __device__ globals) --------
__device__ __align__(16) float g_G[(size_t)BB*NN*128]; // merged [b][j][0:64]=GA, [64:128]=G1
__device__ __align__(16) float g_F0[(size_t)BB*NN*CC]; // attention output (pre-residual), [b, n, c]
__device__ int   g_idx[(size_t)BB*NN*KK];              // ball-query neighbor indices
__device__ __align__(16) float4 g_sp4[(size_t)BB*NN];  // cell-sorted points (x,y,z,|p|^2)
__device__ int   g_sidx[(size_t)BB*NN];                // original index of sorted points
__device__ int   g_cellstart[BB][NCELL+8];             // cell range starts (+ total sentinel)
__device__ __align__(16) float g_wD3[3*128];           // [d][u]: u<64 -> w_attn[u][d], else w1[u-64][d]
__device__ __align__(16) uint32_t g_bfH[2048];         // w2 hi-bf16 B-fragments [kt][nt][lane][2]
__device__ __align__(16) uint32_t g_bfL[2048];         // w2 lo-bf16 residual fragments
__device__ __align__(16) float g_wf1T[CC*CC];          // wf1 transposed [cp][c]
__device__ __align__(16) float g_wf2T[CC*CC];          // wf2 transposed [cp][c]

// ---------------- helpers ----------------
__device__ __forceinline__ uint32_t smem_u32(const void* p_) {
    uint32_t a;
    asm("{ .reg .u64 t; cvta.to.shared.u64 t, %1; cvt.u32.u64 %0, t; }" : "=r"(a) : "l"(p_));
    return a;
}
__device__ __forceinline__ void ldsm_x4(uint32_t* r, uint32_t addr) {
    asm volatile("ldmatrix.sync.aligned.m8n8.x4.shared.b16 {%0,%1,%2,%3}, [%4];"
        : "=r"(r[0]), "=r"(r[1]), "=r"(r[2]), "=r"(r[3]) : "r"(addr));
}
__device__ __forceinline__ void mma_bf16(float* d, const uint32_t* a, uint32_t b0, uint32_t b1) {
    asm volatile("mma.sync.aligned.m16n8k16.row.col.f32.bf16.bf16.f32 "
        "{%0,%1,%2,%3}, {%4,%5,%6,%7}, {%8,%9}, {%0,%1,%2,%3};"
        : "+f"(d[0]), "+f"(d[1]), "+f"(d[2]), "+f"(d[3])
        : "r"(a[0]), "r"(a[1]), "r"(a[2]), "r"(a[3]), "r"(b0), "r"(b1));
}
__device__ __forceinline__ unsigned long long pack2(float lo, float hi) {
    unsigned long long r;
    asm("mov.b64 %0, {%1, %2};" : "=l"(r) : "f"(lo), "f"(hi));
    return r;
}
__device__ __forceinline__ float2 unpack2(unsigned long long v) {
    float2 r;
    asm("mov.b64 {%0, %1}, %2;" : "=f"(r.x), "=f"(r.y) : "l"(v));
    return r;
}
__device__ __forceinline__ void fma2(unsigned long long &acc, unsigned long long a, unsigned long long b) {
    asm("fma.rn.f32x2 %0, %1, %2, %3;" : "=l"(acc) : "l"(a), "l"(b), "l"(acc));
}
__device__ __forceinline__ int cell_coord(float x) {
    int c = (int)(x * 6.0f);
    return c > 5 ? 5 : c;
}

// ================== launch 1: grid-build | ga | p-copy | prep ==================
// grid: [0,8) build, [8,520) ga, [520,552) copy, 552 prep. block=512, dynsmem 49152.
#define PRE_SMEM 49152

__global__ void __launch_bounds__(512) prep_build(
        const float* __restrict__ p, const float* __restrict__ f,
        const float* __restrict__ w_attn, const float* __restrict__ b_attn,
        const float* __restrict__ w1, const float* __restrict__ b1,
        const float* __restrict__ w2,
        const float* __restrict__ wf1, const float* __restrict__ wf2,
        float* __restrict__ out) {
    extern __shared__ float sm[];
    int blk = blockIdx.x;
    int tid = threadIdx.x;

    if (blk < 8) {
        // ---------- build: counting-sort points into 6x6x6 cells ----------
        int b = blk;
        int* s_cell = reinterpret_cast<int*>(sm);          // [NN]
        int* s_cnt  = s_cell + NN;                          // [NCELL]
        int* s_ofs  = s_cnt + NCELL;                        // [NCELL]
        for (int i = tid; i < NCELL; i += 512) s_cnt[i] = 0;
        __syncthreads();

        const float* pb = p + (size_t)b*NN*3;
        for (int jj = tid; jj < NN; jj += 512) {
            float x = pb[jj*3+0], y = pb[jj*3+1], z = pb[jj*3+2];
            int cell = (cell_coord(z)*6 + cell_coord(y))*6 + cell_coord(x);
            s_cell[jj] = cell;
            atomicAdd(&s_cnt[cell], 1);
        }
        __syncthreads();
        if (tid == 0) {
            int run = 0;
            for (int i = 0; i < NCELL; i++) {
                g_cellstart[b][i] = run;
                s_ofs[i] = run;
                run += s_cnt[i];
            }
            g_cellstart[b][NCELL] = run;   // == NN
        }
        __syncthreads();
        for (int jj = tid; jj < NN; jj += 512) {
            int cell = s_cell[jj];
            int pos = atomicAdd(&s_ofs[cell], 1);
            float x = pb[jj*3+0], y = pb[jj*3+1], z = pb[jj*3+2];
            float sq = __fadd_rn(__fadd_rn(__fmul_rn(x,x), __fmul_rn(y,y)), __fmul_rn(z,z));
            g_sp4[(size_t)b*NN + pos] = make_float4(x, y, z, sq);
            g_sidx[(size_t)b*NN + pos] = jj;
        }

    } else if (blk < 520) {
        // ---------- ga: GA/G1 precompute -> merged g_G rows (FFMA2 accumulators) ----------
        float* s_f  = sm;
        float* s_wa = sm + 4096;
        float* s_w1 = sm + 8192;
        int gb = blk - 8;
        int b  = gb >> 6;
        int j0 = (gb & 63) << 6;

        for (int lin = tid; lin < 64*64; lin += 512) {
            int i = lin >> 6, c = lin & 63;
            s_wa[i*64 + c] = w_attn[c*CIN + 3 + i];
            s_w1[i*64 + c] = w1[c*CIN + 3 + i];
        }
        for (int lin = tid; lin < 64*64; lin += 512) {
            int i = lin >> 6, jj = lin & 63;
            s_f[i*64 + jj] = f[((size_t)b*CC + i)*NN + j0 + jj];
        }
        __syncthreads();

        int j  = tid & 63;
        int c0 = (tid >> 6) << 3;
        unsigned long long accA2[4], acc12[4];
#pragma unroll
        for (int q = 0; q < 4; q++) {
            accA2[q] = pack2(__ldg(&b_attn[c0+2*q]), __ldg(&b_attn[c0+2*q+1]));
            acc12[q] = pack2(__ldg(&b1[c0+2*q]),     __ldg(&b1[c0+2*q+1]));
        }

#pragma unroll 4
        for (int i = 0; i < 64; i++) {
            float fv = s_f[i*64 + j];
            unsigned long long fv2 = pack2(fv, fv);
            const ulonglong2* wa = reinterpret_cast<const ulonglong2*>(&s_wa[i*64 + c0]);
            const ulonglong2* wb = reinterpret_cast<const ulonglong2*>(&s_w1[i*64 + c0]);
            ulonglong2 A0 = wa[0], A1 = wa[1];
            ulonglong2 B0 = wb[0], B1 = wb[1];
            fma2(accA2[0], A0.x, fv2); fma2(accA2[1], A0.y, fv2);
            fma2(accA2[2], A1.x, fv2); fma2(accA2[3], A1.y, fv2);
            fma2(acc12[0], B0.x, fv2); fma2(acc12[1], B0.y, fv2);
            fma2(acc12[2], B1.x, fv2); fma2(acc12[3], B1.y, fv2);
        }
        size_t base = ((size_t)b*NN + j0 + j)*128 + c0;
        {
            float2 a0 = unpack2(accA2[0]), a1 = unpack2(accA2[1]);
            float2 a2 = unpack2(accA2[2]), a3 = unpack2(accA2[3]);
            *reinterpret_cast<float4*>(&g_G[base + 0]) = make_float4(a0.x, a0.y, a1.x, a1.y);
            *reinterpret_cast<float4*>(&g_G[base + 4]) = make_float4(a2.x, a2.y, a3.x, a3.y);
            float2 o0 = unpack2(acc12[0]), o1 = unpack2(acc12[1]);
            float2 o2 = unpack2(acc12[2]), o3 = unpack2(acc12[3]);
            *reinterpret_cast<float4*>(&g_G[base + 64]) = make_float4(o0.x, o0.y, o1.x, o1.y);
            *reinterpret_cast<float4*>(&g_G[base + 68]) = make_float4(o2.x, o2.y, o3.x, o3.y);
        }

    } else if (blk < 552) {
        // ---------- p passthrough copy into out[0 : B*N*3) ----------
        int cb = blk - 520;
        const float4* src = reinterpret_cast<const float4*>(p);
        float4* dst = reinterpret_cast<float4*>(out);
        int lo = cb*768, hi = lo + 768;
        for (int i = lo + tid; i < hi; i += 512) dst[i] = src[i];

    } else {
        // ---------- prep: weight repack ----------
        for (int i = tid; i < 3*128; i += 512) {
            int d = i / 128, u = i % 128;
            g_wD3[i] = (u < 64) ? w_attn[u*CIN + d] : w1[(u-64)*CIN + d];
        }
        for (int i = tid; i < 2048; i += 512) {
            int r    = i & 1;
            int lane = (i >> 1) & 31;
            int nt   = (i >> 6) & 7;
            int kt   = i >> 9;
            int k0 = kt*16 + (lane & 3)*2 + r*8;
            int n  = nt*8 + (lane >> 2);
            float v0 = w2[n*64 + k0], v1 = w2[n*64 + k0 + 1];
            __nv_bfloat16 h0 = __float2bfloat16(v0), h1 = __float2bfloat16(v1);
            __nv_bfloat162 hi2; hi2.x = h0; hi2.y = h1;
            __nv_bfloat162 lo2;
            lo2.x = __float2bfloat16(v0 - __bfloat162float(h0));
            lo2.y = __float2bfloat16(v1 - __bfloat162float(h1));
            g_bfH[i] = *reinterpret_cast<uint32_t*>(&hi2);
            g_bfL[i] = *reinterpret_cast<uint32_t*>(&lo2);
        }
        for (int i = tid; i < CC*CC; i += 512) {
            int c = i / CC, cp = i % CC;
            g_wf1T[cp*CC + c] = wf1[i];
            g_wf2T[cp*CC + c] = wf2[i];
        }
    }
}

// ================== launch 2: grid-accelerated ball query ==================
// 512 blocks x 512 threads; warp per query, 4 queries sequentially (64 queries/block).
__global__ void __launch_bounds__(512) bq_kernel(const float* __restrict__ p) {
    __shared__ int s_hit[16][130];

    int bb = blockIdx.x;
    int b = bb >> 6;
    int nbase = (bb & 63) << 6;
    int tid = threadIdx.x;
    int wi = tid >> 5, lane = tid & 31;
    const float r2 = (float)(0.15*0.15);
    unsigned lmask = (1u << lane) - 1u;
    const float4* sp4 = g_sp4 + (size_t)b*NN;
    const int* sidx = g_sidx + (size_t)b*NN;
    const int* cs = &g_cellstart[b][0];

#pragma unroll 1
    for (int qq = 0; qq < 4; qq++) {
        int n = nbase + wi*4 + qq;
        const float* pn = p + ((size_t)b*NN + n)*3;
        float x = pn[0], y = pn[1], z = pn[2];
        float sq = __fadd_rn(__fadd_rn(__fmul_rn(x,x), __fmul_rn(y,y)), __fmul_rn(z,z));
        float ax = -2.0f*x, ay = -2.0f*y, az = -2.0f*z;
        int cx = cell_coord(x), cy = cell_coord(y), cz = cell_coord(z);
        int x0 = max(cx-1, 0), x1 = min(cx+1, 5);
        int y0 = max(cy-1, 0), y1 = min(cy+1, 5);
        int z0 = max(cz-1, 0), z1 = min(cz+1, 5);

        int hcnt = 0;
#pragma unroll 1
        for (int dz = z0; dz <= z1; dz++) {
#pragma unroll 1
            for (int dy = y0; dy <= y1; dy++) {
                int rowb = (dz*6 + dy)*6;
                int start = __ldg(&cs[rowb + x0]);
                int end   = __ldg(&cs[rowb + x1 + 1]);
#pragma unroll 1
                for (int base2 = start; base2 < end; base2 += 32) {
                    int pos = base2 + lane;
                    bool inr = pos < end;
                    float4 sp = make_float4(0.f, 0.f, 0.f, 1e9f);
                    if (inr) sp = __ldg(&sp4[pos]);
                    float d2 = fmaf(ax, sp.x, fmaf(ay, sp.y, fmaf(az, sp.z, sq + sp.w)));
                    bool within = inr && (d2 <= r2);
                    unsigned m = __ballot_sync(0xffffffffu, within);
                    int pr = hcnt + __popc(m & lmask);
                    if (within && pr < 128) s_hit[wi][pr] = __ldg(&sidx[pos]);
                    hcnt += __popc(m);
                }
            }
        }
        if (hcnt > 128) hcnt = 128;
        __syncwarp();

        int h0 = (lane        < hcnt) ? s_hit[wi][lane]      : 0x7FFFFFFF;
        int h1 = (lane + 32   < hcnt) ? s_hit[wi][lane + 32] : 0x7FFFFFFF;
        int h2 = (lane + 64   < hcnt) ? s_hit[wi][lane + 64] : 0x7FFFFFFF;
        int h3 = (lane + 96   < hcnt) ? s_hit[wi][lane + 96] : 0x7FFFFFFF;

        int v;
        if (hcnt <= 32) {
            // all hits + pad with min index
            int mn = h0;
#pragma unroll
            for (int off = 16; off > 0; off >>= 1)
                mn = min(mn, __shfl_xor_sync(0xffffffffu, mn, off));
            v = (lane < hcnt) ? h0 : mn;
        } else {
            // binary search threshold T = 32nd smallest index
            int lo = 0, hi = 4095;
            while (lo < hi) {
                int mid = (lo + hi) >> 1;
                int c = __popc(__ballot_sync(0xffffffffu, h0 <= mid))
                      + __popc(__ballot_sync(0xffffffffu, h1 <= mid))
                      + __popc(__ballot_sync(0xffffffffu, h2 <= mid))
                      + __popc(__ballot_sync(0xffffffffu, h3 <= mid));
                if (c >= 32) hi = mid; else lo = mid + 1;
            }
            int T = lo;
            __syncwarp();
            int bc = 0;
#pragma unroll
            for (int i = 0; i < 4; i++) {
                int hv = (i == 0) ? h0 : (i == 1) ? h1 : (i == 2) ? h2 : h3;
                bool sel = hv <= T;
                unsigned m = __ballot_sync(0xffffffffu, sel);
                int ppos = bc + __popc(m & lmask);
                if (sel) s_hit[wi][ppos] = hv;   // exactly 32 total (indices distinct)
                bc += __popc(m);
            }
            __syncwarp();
            v = s_hit[wi][lane];
        }

        // bitonic sort ascending across lanes -> deterministic output order
#pragma unroll
        for (int kk2 = 2; kk2 <= 32; kk2 <<= 1) {
#pragma unroll
            for (int jx = kk2 >> 1; jx > 0; jx >>= 1) {
                int partner = __shfl_xor_sync(0xffffffffu, v, jx);
                bool up = ((lane & kk2) == 0);
                bool smallh = ((lane & jx) == 0);
                int mn = min(v, partner), mx = max(v, partner);
                v = (smallh == up) ? mn : mx;
            }
        }
        g_idx[((size_t)b*NN + n)*KK + lane] = v;
        __syncwarp();
    }
}

// ---------------- fused main: mma.sync GEMM, 4 points/block, 3 blocks/SM ----------------
#define SMM_RHI  0
#define SMM_RLO  18432
#define SMM_E    36864
#define SMM_META 55296
#define SM_MAIN  59392

__global__ void __launch_bounds__(256, 3) main_kernel(const float* __restrict__ p,
        const float* __restrict__ b2) {
    extern __shared__ char smc[];
    uint32_t smem_base = smem_u32(smc);
    float4* s_meta = reinterpret_cast<float4*>(smc + SMM_META);

    int tid  = threadIdx.x;
    int w    = tid >> 5;
    int lane = tid & 31;
    int pbase = blockIdx.x * 4;

    if (w < 4) {
        int pid = pbase + w;
        int b = pid >> 12, n = pid & 4095;
        int j = g_idx[(size_t)pid*KK + lane];
        const float* pn = p + ((size_t)b*NN + n)*3;
        const float* pj = p + ((size_t)b*NN + j)*3;
        float4 m;
        m.x = pj[0] - pn[0];
        m.y = pj[1] - pn[1];
        m.z = pj[2] - pn[2];
        m.w = __int_as_float(j);
        s_meta[w*32 + lane] = m;
    }
    __syncthreads();

    // ---- phase 1 (warp-specialized): warps 0-3 -> R(pt=w), warps 4-7 -> E(pt=w-4) ----
    {
        bool isR = (w < 4);
        int pt = w & 3;
        int pid = pbase + pt;
        int b = pid >> 12;
        int lh  = lane >> 4;
        int u16 = (lane & 15) * 4;
        int u   = isR ? (64 + u16) : u16;
        float4 wx = *reinterpret_cast<const float4*>(&g_wD3[0*128 + u]);
        float4 wy = *reinterpret_cast<const float4*>(&g_wD3[1*128 + u]);
        float4 wz = *reinterpret_cast<const float4*>(&g_wD3[2*128 + u]);
        __half* Ep = reinterpret_cast<__half*>(smc + SMM_E) + pt*2304;
        const float* Gb = g_G + (size_t)b*NN*128;

#pragma unroll 8
        for (int kk = 0; kk < 16; kk++) {
            int k = kk*2 + lh;
            float4 m = s_meta[pt*32 + k];
            int j = __float_as_int(m.w);
            float4 g = __ldg(reinterpret_cast<const float4*>(&Gb[(size_t)j*128 + u]));
            float4 v;
            v.x = g.x + wx.x*m.x + wy.x*m.y + wz.x*m.z;
            v.y = g.y + wx.y*m.x + wy.y*m.y + wz.y*m.z;
            v.z = g.z + wx.z*m.x + wy.z*m.y + wz.z*m.z;
            v.w = g.w + wx.w*m.x + wy.w*m.y + wz.w*m.z;
            if (isR) {
                float r0 = fmaxf(v.x, 0.0f), r1 = fmaxf(v.y, 0.0f);
                float r2v = fmaxf(v.z, 0.0f), r3 = fmaxf(v.w, 0.0f);
                __nv_bfloat16 h0 = __float2bfloat16(r0), h1 = __float2bfloat16(r1);
                __nv_bfloat16 h2 = __float2bfloat16(r2v), h3 = __float2bfloat16(r3);
                __nv_bfloat162 hp0; hp0.x = h0; hp0.y = h1;
                __nv_bfloat162 hp1; hp1.x = h2; hp1.y = h3;
                __nv_bfloat162 lp0; lp0.x = __float2bfloat16(r0 - __bfloat162float(h0));
                                    lp0.y = __float2bfloat16(r1 - __bfloat162float(h1));
                __nv_bfloat162 lp1; lp1.x = __float2bfloat16(r2v - __bfloat162float(h2));
                                    lp1.y = __float2bfloat16(r3 - __bfloat162float(h3));
                int row = pt*32 + k;
                uint32_t roff = (uint32_t)(row*72 + u16)*2;
                *reinterpret_cast<uint2*>(smc + SMM_RHI + roff) =
                    make_uint2(*reinterpret_cast<uint32_t*>(&hp0), *reinterpret_cast<uint32_t*>(&hp1));
                *reinterpret_cast<uint2*>(smc + SMM_RLO + roff) =
                    make_uint2(*reinterpret_cast<uint32_t*>(&lp0), *reinterpret_cast<uint32_t*>(&lp1));
            } else {
                union { __half2 h[2]; uint2 u2; } cv;
                cv.h[0] = __floats2half2_rn(__expf(v.x), __expf(v.y));
                cv.h[1] = __floats2half2_rn(__expf(v.z), __expf(v.w));
                *reinterpret_cast<uint2*>(&Ep[k*72 + u16]) = cv.u2;
            }
        }
    }
    __syncthreads();

    // ---- mma GEMM + softmax-weighted epilogue: warp = (pt = w&3, mh = w>>2) ----
    {
        int pt = w & 3;
        int mh = w >> 2;

        int r8 = lane & 7, mmat = lane >> 3;
        int arow = pt*32 + mh*16 + r8 + ((mmat & 1) << 3);
        uint32_t acolB = (uint32_t)(((mmat >> 1) << 3) * 2);
        uint32_t abase = smem_base + (uint32_t)(arow * 144) + acolB;

        float acc[8][4];
#pragma unroll
        for (int nt = 0; nt < 8; nt++)
#pragma unroll
            for (int q = 0; q < 4; q++) acc[nt][q] = 0.0f;

#pragma unroll
        for (int kt = 0; kt < 4; kt++) {
            uint32_t ah[4], al[4];
            ldsm_x4(ah, abase + SMM_RHI + kt*32);
            ldsm_x4(al, abase + SMM_RLO + kt*32);
#pragma unroll
            for (int nt = 0; nt < 8; nt++) {
                int bidx = ((kt*8 + nt)*32 + lane)*2;
                uint2 bh = __ldg(reinterpret_cast<const uint2*>(&g_bfH[bidx]));
                uint2 bl = __ldg(reinterpret_cast<const uint2*>(&g_bfL[bidx]));
                mma_bf16(acc[nt], ah, bh.x, bh.y);
                mma_bf16(acc[nt], al, bh.x, bh.y);
                mma_bf16(acc[nt], ah, bl.x, bl.y);
            }
        }

        const __half* Eb = reinterpret_cast<const __half*>(smc + SMM_E);
        float* red = reinterpret_cast<float*>(smc + SMM_META);
        int r0 = mh*16 + (lane >> 2);
        int c00 = (lane & 3) * 2;
#pragma unroll
        for (int nt = 0; nt < 8; nt++) {
            int c0 = nt*8 + c00;
            float2 e0 = __half22float2(*reinterpret_cast<const __half2*>(&Eb[pt*2304 + r0*72 + c0]));
            float2 e1 = __half22float2(*reinterpret_cast<const __half2*>(&Eb[pt*2304 + (r0+8)*72 + c0]));
            float v0 = e0.x*acc[nt][0] + e1.x*acc[nt][2];
            float v1 = e0.y*acc[nt][1] + e1.y*acc[nt][3];
            float v2 = e0.x + e1.x;
            float v3 = e0.y + e1.y;
            bool up4 = (lane & 4) != 0;
            float s0 = up4 ? v0 : v2;
            float s1 = up4 ? v1 : v3;
            float rA = __shfl_xor_sync(0xffffffffu, s0, 4);
            float rB = __shfl_xor_sync(0xffffffffu, s1, 4);
            v0 = (up4 ? v2 : v0) + rA;
            v1 = (up4 ? v3 : v1) + rB;
            bool up8 = (lane & 8) != 0;
            float s2 = up8 ? v0 : v1;
            float rC = __shfl_xor_sync(0xffffffffu, s2, 8);
            v0 = (up8 ? v1 : v0) + rC;
            v0 += __shfl_xor_sync(0xffffffffu, v0, 16);
            if (lane < 16) {
                int c = nt*8 + (lane & 3)*2 + ((lane >> 3) & 1);
                int d = (lane >> 2) & 1;
                red[((mh*4 + pt)*64 + c)*2 + d] = v0;
            }
        }
    }
    __syncthreads();

    {
        int pt = tid >> 6, c = tid & 63;
        const float* red = reinterpret_cast<const float*>(smc + SMM_META);
        float num = red[(pt*64 + c)*2 + 0] + red[((4 + pt)*64 + c)*2 + 0];
        float den = red[(pt*64 + c)*2 + 1] + red[((4 + pt)*64 + c)*2 + 1];
        g_F0[(size_t)(pbase + pt)*CC + c] = num / den + __ldg(&b2[c]);
    }
}

// ---------------- tail: relu(F0+f) -> 2x (64x64) MLP -> relu residual ----------------
__global__ void __launch_bounds__(256) tail_kernel(const float* __restrict__ f,
        const float* __restrict__ bf1, const float* __restrict__ bf2,
        float* __restrict__ outF) {
    __shared__ float s_F1[64*68];
    __shared__ float s_H[64*68];

    int b   = blockIdx.x >> 6;
    int n0g = (blockIdx.x & 63) << 6;
    int tid = threadIdx.x;

    {
        int c = tid >> 2, q = tid & 3;
        const float* frow = f + ((size_t)b*CC + c)*NN + n0g;
        const float* f0b  = g_F0 + ((size_t)b*NN + n0g)*CC + c;
#pragma unroll
        for (int i = 0; i < 4; i++) {
            int nn = q*16 + i*4;
            float4 fv = *reinterpret_cast<const float4*>(frow + nn);
            float a0 = __ldg(&f0b[(nn+0)*CC]);
            float a1 = __ldg(&f0b[(nn+1)*CC]);
            float a2 = __ldg(&f0b[(nn+2)*CC]);
            float a3 = __ldg(&f0b[(nn+3)*CC]);
            float4 r;
            r.x = fmaxf(a0 + fv.x, 0.0f);
            r.y = fmaxf(a1 + fv.y, 0.0f);
            r.z = fmaxf(a2 + fv.z, 0.0f);
            r.w = fmaxf(a3 + fv.w, 0.0f);
            *reinterpret_cast<float4*>(&s_F1[c*68 + nn]) = r;
        }
    }
    __syncthreads();

    int ct = (tid >> 4) << 2;
    int nt = (tid & 15) << 2;

    {
        float acc[16];
#pragma unroll
        for (int r = 0; r < 4; r++) {
            float bv = __ldg(&bf1[ct+r]);
#pragma unroll
            for (int jj = 0; jj < 4; jj++) acc[r*4+jj] = bv;
        }
#pragma unroll 4
        for (int cp = 0; cp < 64; cp++) {
            float4 wv = __ldg(reinterpret_cast<const float4*>(&g_wf1T[cp*64 + ct]));
            float4 fv = *reinterpret_cast<const float4*>(&s_F1[cp*68 + nt]);
            acc[0]  += wv.x*fv.x; acc[1]  += wv.x*fv.y; acc[2]  += wv.x*fv.z; acc[3]  += wv.x*fv.w;
            acc[4]  += wv.y*fv.x; acc[5]  += wv.y*fv.y; acc[6]  += wv.y*fv.z; acc[7]  += wv.y*fv.w;
            acc[8]  += wv.z*fv.x; acc[9]  += wv.z*fv.y; acc[10] += wv.z*fv.z; acc[11] += wv.z*fv.w;
            acc[12] += wv.w*fv.x; acc[13] += wv.w*fv.y; acc[14] += wv.w*fv.z; acc[15] += wv.w*fv.w;
        }
#pragma unroll
        for (int r = 0; r < 4; r++) {
            float4 o;
            o.x = fmaxf(acc[r*4+0], 0.0f);
            o.y = fmaxf(acc[r*4+1], 0.0f);
            o.z = fmaxf(acc[r*4+2], 0.0f);
            o.w = fmaxf(acc[r*4+3], 0.0f);
            *reinterpret_cast<float4*>(&s_H[(ct+r)*68 + nt]) = o;
        }
    }
    __syncthreads();

    {
        float acc[16];
#pragma unroll
        for (int r = 0; r < 4; r++) {
            float bv = __ldg(&bf2[ct+r]);
#pragma unroll
            for (int jj = 0; jj < 4; jj++) acc[r*4+jj] = bv;
        }
#pragma unroll 4
        for (int cp = 0; cp < 64; cp++) {
            float4 wv = __ldg(reinterpret_cast<const float4*>(&g_wf2T[cp*64 + ct]));
            float4 hv = *reinterpret_cast<const float4*>(&s_H[cp*68 + nt]);
            acc[0]  += wv.x*hv.x; acc[1]  += wv.x*hv.y; acc[2]  += wv.x*hv.z; acc[3]  += wv.x*hv.w;
            acc[4]  += wv.y*hv.x; acc[5]  += wv.y*hv.y; acc[6]  += wv.y*hv.z; acc[7]  += wv.y*hv.w;
            acc[8]  += wv.z*hv.x; acc[9]  += wv.z*hv.y; acc[10] += wv.z*hv.z; acc[11] += wv.z*hv.w;
            acc[12] += wv.w*hv.x; acc[13] += wv.w*hv.y; acc[14] += wv.w*hv.z; acc[15] += wv.w*hv.w;
        }
#pragma unroll
        for (int r = 0; r < 4; r++) {
            const float* idn = &s_F1[(ct+r)*68 + nt];
            float4 o;
            o.x = fmaxf(acc[r*4+0] + idn[0], 0.0f);
            o.y = fmaxf(acc[r*4+1] + idn[1], 0.0f);
            o.z = fmaxf(acc[r*4+2] + idn[2], 0.0f);
            o.w = fmaxf(acc[r*4+3] + idn[3], 0.0f);
            *reinterpret_cast<float4*>(&outF[((size_t)b*CC + ct + r)*NN + n0g + nt]) = o;
        }
    }
}

// ---------------- launch ----------------
extern "C" void kernel_launch(void* const* d_in, const int* in_sizes, int n_in,
                              void* d_out, int out_size) {
    const float* p      = (const float*)d_in[0];
    const float* f      = (const float*)d_in[1];
    const float* w_attn = (const float*)d_in[2];
    const float* b_attn = (const float*)d_in[3];
    const float* w1     = (const float*)d_in[4];
    const float* b1     = (const float*)d_in[5];
    const float* w2     = (const float*)d_in[6];
    const float* b2     = (const float*)d_in[7];
    const float* wf1    = (const float*)d_in[8];
    const float* bf1    = (const float*)d_in[9];
    const float* wf2    = (const float*)d_in[10];
    const float* bf2    = (const float*)d_in[11];
    float* out = (float*)d_out;

    cudaFuncSetAttribute(prep_build, cudaFuncAttributeMaxDynamicSharedMemorySize, PRE_SMEM);
    prep_build<<<553, 512, PRE_SMEM>>>(p, f, w_attn, b_attn, w1, b1, w2, wf1, wf2, out);

    bq_kernel<<<512, 512>>>(p);

    cudaFuncSetAttribute(main_kernel, cudaFuncAttributeMaxDynamicSharedMemorySize, SM_MAIN);
    main_kernel<<<BB*NN/4, 256, SM_MAIN>>>(p, b2);

    tail_kernel<<<BB*(NN/64), 256>>>(f, bf1, bf2, out + (size_t)BB*NN*3);
}

// round 14
// speedup vs baseline: 3.1023x; 1.0113x over previous
#include <cuda_runtime.h>
#include <cuda_fp16.h>
#include <cuda_bf16.h>
#include <cstdint>
#include <cstddef>

#define BB  8
#define NN  4096
#define KK  32
#define CC  64
#define CIN 67
#define NCELL 216   // 6x6x6

// -------- scratch (no allocation allowed -> __device__ globals) --------
__device__ __align__(16) float g_G[(size_t)BB*NN*128]; // merged [b][j][0:64]=GA, [64:128]=G1
__device__ __align__(16) float g_F0[(size_t)BB*NN*CC]; // attention output (pre-residual), [b, n, c]
__device__ int   g_idx[(size_t)BB*NN*KK];              // ball-query neighbor indices
__device__ __align__(16) float4 g_sp4[(size_t)BB*NN];  // cell-sorted points (x,y,z,|p|^2)
__device__ int   g_sidx[(size_t)BB*NN];                // original index of sorted points
__device__ int   g_cellstart[BB][NCELL+8];             // cell range starts (+ total sentinel)
__device__ __align__(16) float g_wD3[3*128];           // [d][u]: u<64 -> w_attn[u][d], else w1[u-64][d]
__device__ __align__(16) uint32_t g_bfH[2048];         // w2 hi-bf16 B-fragments [kt][nt][lane][2]
__device__ __align__(16) uint32_t g_bfL[2048];         // w2 lo-bf16 residual fragments
__device__ __align__(16) float g_wf1T[CC*CC];          // wf1 transposed [cp][c]
__device__ __align__(16) float g_wf2T[CC*CC];          // wf2 transposed [cp][c]

// ---------------- helpers ----------------
__device__ __forceinline__ uint32_t smem_u32(const void* p_) {
    uint32_t a;
    asm("{ .reg .u64 t; cvta.to.shared.u64 t, %1; cvt.u32.u64 %0, t; }" : "=r"(a) : "l"(p_));
    return a;
}
__device__ __forceinline__ void ldsm_x4(uint32_t* r, uint32_t addr) {
    asm volatile("ldmatrix.sync.aligned.m8n8.x4.shared.b16 {%0,%1,%2,%3}, [%4];"
        : "=r"(r[0]), "=r"(r[1]), "=r"(r[2]), "=r"(r[3]) : "r"(addr));
}
__device__ __forceinline__ void mma_bf16(float* d, const uint32_t* a, uint32_t b0, uint32_t b1) {
    asm volatile("mma.sync.aligned.m16n8k16.row.col.f32.bf16.bf16.f32 "
        "{%0,%1,%2,%3}, {%4,%5,%6,%7}, {%8,%9}, {%0,%1,%2,%3};"
        : "+f"(d[0]), "+f"(d[1]), "+f"(d[2]), "+f"(d[3])
        : "r"(a[0]), "r"(a[1]), "r"(a[2]), "r"(a[3]), "r"(b0), "r"(b1));
}
__device__ __forceinline__ unsigned long long pack2(float lo, float hi) {
    unsigned long long r;
    asm("mov.b64 %0, {%1, %2};" : "=l"(r) : "f"(lo), "f"(hi));
    return r;
}
__device__ __forceinline__ float2 unpack2(unsigned long long v) {
    float2 r;
    asm("mov.b64 {%0, %1}, %2;" : "=f"(r.x), "=f"(r.y) : "l"(v));
    return r;
}
__device__ __forceinline__ void fma2(unsigned long long &acc, unsigned long long a, unsigned long long b) {
    asm("fma.rn.f32x2 %0, %1, %2, %3;" : "=l"(acc) : "l"(a), "l"(b), "l"(acc));
}
__device__ __forceinline__ int cell_coord(float x) {
    int c = (int)(x * 6.0f);
    return c > 5 ? 5 : c;
}

// ================== launch A: grid-build | p-copy | prep (small, fast) ==================
#define PREA_SMEM 49152

__global__ void __launch_bounds__(512) prep_build(
        const float* __restrict__ p,
        const float* __restrict__ w_attn, const float* __restrict__ w1,
        const float* __restrict__ w2,
        const float* __restrict__ wf1, const float* __restrict__ wf2,
        float* __restrict__ out) {
    extern __shared__ float sm[];
    int blk = blockIdx.x;
    int tid = threadIdx.x;

    if (blk < 8) {
        // ---------- build: counting-sort points into 6x6x6 cells ----------
        int b = blk;
        int* s_cell = reinterpret_cast<int*>(sm);          // [NN]
        int* s_cnt  = s_cell + NN;                          // [NCELL]
        int* s_ofs  = s_cnt + NCELL;                        // [NCELL]
        for (int i = tid; i < NCELL; i += 512) s_cnt[i] = 0;
        __syncthreads();

        const float* pb = p + (size_t)b*NN*3;
        for (int jj = tid; jj < NN; jj += 512) {
            float x = pb[jj*3+0], y = pb[jj*3+1], z = pb[jj*3+2];
            int cell = (cell_coord(z)*6 + cell_coord(y))*6 + cell_coord(x);
            s_cell[jj] = cell;
            atomicAdd(&s_cnt[cell], 1);
        }
        __syncthreads();
        if (tid == 0) {
            int run = 0;
            for (int i = 0; i < NCELL; i++) {
                g_cellstart[b][i] = run;
                s_ofs[i] = run;
                run += s_cnt[i];
            }
            g_cellstart[b][NCELL] = run;   // == NN
        }
        __syncthreads();
        for (int jj = tid; jj < NN; jj += 512) {
            int cell = s_cell[jj];
            int pos = atomicAdd(&s_ofs[cell], 1);
            float x = pb[jj*3+0], y = pb[jj*3+1], z = pb[jj*3+2];
            float sq = __fadd_rn(__fadd_rn(__fmul_rn(x,x), __fmul_rn(y,y)), __fmul_rn(z,z));
            g_sp4[(size_t)b*NN + pos] = make_float4(x, y, z, sq);
            g_sidx[(size_t)b*NN + pos] = jj;
        }

    } else if (blk < 40) {
        // ---------- p passthrough copy into out[0 : B*N*3) ----------
        int cb = blk - 8;
        const float4* src = reinterpret_cast<const float4*>(p);
        float4* dst = reinterpret_cast<float4*>(out);
        int lo = cb*768, hi = lo + 768;
        for (int i = lo + tid; i < hi; i += 512) dst[i] = src[i];

    } else {
        // ---------- prep: weight repack ----------
        for (int i = tid; i < 3*128; i += 512) {
            int d = i / 128, u = i % 128;
            g_wD3[i] = (u < 64) ? w_attn[u*CIN + d] : w1[(u-64)*CIN + d];
        }
        for (int i = tid; i < 2048; i += 512) {
            int r    = i & 1;
            int lane = (i >> 1) & 31;
            int nt   = (i >> 6) & 7;
            int kt   = i >> 9;
            int k0 = kt*16 + (lane & 3)*2 + r*8;
            int n  = nt*8 + (lane >> 2);
            float v0 = w2[n*64 + k0], v1 = w2[n*64 + k0 + 1];
            __nv_bfloat16 h0 = __float2bfloat16(v0), h1 = __float2bfloat16(v1);
            __nv_bfloat162 hi2; hi2.x = h0; hi2.y = h1;
            __nv_bfloat162 lo2;
            lo2.x = __float2bfloat16(v0 - __bfloat162float(h0));
            lo2.y = __float2bfloat16(v1 - __bfloat162float(h1));
            g_bfH[i] = *reinterpret_cast<uint32_t*>(&hi2);
            g_bfL[i] = *reinterpret_cast<uint32_t*>(&lo2);
        }
        for (int i = tid; i < CC*CC; i += 512) {
            int c = i / CC, cp = i % CC;
            g_wf1T[cp*CC + c] = wf1[i];
            g_wf2T[cp*CC + c] = wf2[i];
        }
    }
}

// ================== launch B: bq | ga fused (mutually independent -> overlap) ==================
// grid: [0,512) bq (grid-accelerated), [512,1024) ga. block=512, dynsmem 49152.
#define PREB_SMEM 49152

__global__ void __launch_bounds__(512) bq_ga_kernel(
        const float* __restrict__ p, const float* __restrict__ f,
        const float* __restrict__ w_attn, const float* __restrict__ b_attn,
        const float* __restrict__ w1, const float* __restrict__ b1) {
    extern __shared__ float sm[];
    int blk = blockIdx.x;
    int tid = threadIdx.x;

    if (blk < 512) {
        // ---------- bq: grid-accelerated ball query ----------
        int (*s_hit)[130] = reinterpret_cast<int(*)[130]>(sm);   // [16][130]

        int bb = blk;
        int b = bb >> 6;
        int nbase = (bb & 63) << 6;
        int wi = tid >> 5, lane = tid & 31;
        const float r2 = (float)(0.15*0.15);
        unsigned lmask = (1u << lane) - 1u;
        const float4* sp4 = g_sp4 + (size_t)b*NN;
        const int* sidx = g_sidx + (size_t)b*NN;
        const int* cs = &g_cellstart[b][0];

#pragma unroll 1
        for (int qq = 0; qq < 4; qq++) {
            int n = nbase + wi*4 + qq;
            const float* pn = p + ((size_t)b*NN + n)*3;
            float x = pn[0], y = pn[1], z = pn[2];
            float sq = __fadd_rn(__fadd_rn(__fmul_rn(x,x), __fmul_rn(y,y)), __fmul_rn(z,z));
            float ax = -2.0f*x, ay = -2.0f*y, az = -2.0f*z;
            int cx = cell_coord(x), cy = cell_coord(y), cz = cell_coord(z);
            int x0 = max(cx-1, 0), x1 = min(cx+1, 5);
            int y0 = max(cy-1, 0), y1 = min(cy+1, 5);
            int z0 = max(cz-1, 0), z1 = min(cz+1, 5);

            int hcnt = 0;
#pragma unroll 1
            for (int dz = z0; dz <= z1; dz++) {
#pragma unroll 1
                for (int dy = y0; dy <= y1; dy++) {
                    int rowb = (dz*6 + dy)*6;
                    int start = __ldg(&cs[rowb + x0]);
                    int end   = __ldg(&cs[rowb + x1 + 1]);
#pragma unroll 1
                    for (int base2 = start; base2 < end; base2 += 32) {
                        int pos = base2 + lane;
                        bool inr = pos < end;
                        float4 sp = make_float4(0.f, 0.f, 0.f, 1e9f);
                        if (inr) sp = __ldg(&sp4[pos]);
                        float d2 = fmaf(ax, sp.x, fmaf(ay, sp.y, fmaf(az, sp.z, sq + sp.w)));
                        bool within = inr && (d2 <= r2);
                        unsigned m = __ballot_sync(0xffffffffu, within);
                        int pr = hcnt + __popc(m & lmask);
                        if (within && pr < 128) s_hit[wi][pr] = __ldg(&sidx[pos]);
                        hcnt += __popc(m);
                    }
                }
            }
            if (hcnt > 128) hcnt = 128;
            __syncwarp();

            int h0 = (lane        < hcnt) ? s_hit[wi][lane]      : 0x7FFFFFFF;
            int h1 = (lane + 32   < hcnt) ? s_hit[wi][lane + 32] : 0x7FFFFFFF;
            int h2 = (lane + 64   < hcnt) ? s_hit[wi][lane + 64] : 0x7FFFFFFF;
            int h3 = (lane + 96   < hcnt) ? s_hit[wi][lane + 96] : 0x7FFFFFFF;

            int v;
            if (hcnt <= 32) {
                int mn = h0;
#pragma unroll
                for (int off = 16; off > 0; off >>= 1)
                    mn = min(mn, __shfl_xor_sync(0xffffffffu, mn, off));
                v = (lane < hcnt) ? h0 : mn;
            } else {
                int lo = 0, hi = 4095;
                while (lo < hi) {
                    int mid = (lo + hi) >> 1;
                    int c = __popc(__ballot_sync(0xffffffffu, h0 <= mid))
                          + __popc(__ballot_sync(0xffffffffu, h1 <= mid))
                          + __popc(__ballot_sync(0xffffffffu, h2 <= mid))
                          + __popc(__ballot_sync(0xffffffffu, h3 <= mid));
                    if (c >= 32) hi = mid; else lo = mid + 1;
                }
                int T = lo;
                __syncwarp();
                int bc = 0;
#pragma unroll
                for (int i = 0; i < 4; i++) {
                    int hv = (i == 0) ? h0 : (i == 1) ? h1 : (i == 2) ? h2 : h3;
                    bool sel = hv <= T;
                    unsigned m = __ballot_sync(0xffffffffu, sel);
                    int ppos = bc + __popc(m & lmask);
                    if (sel) s_hit[wi][ppos] = hv;
                    bc += __popc(m);
                }
                __syncwarp();
                v = s_hit[wi][lane];
            }

            // bitonic sort ascending -> deterministic order
#pragma unroll
            for (int kk2 = 2; kk2 <= 32; kk2 <<= 1) {
#pragma unroll
                for (int jx = kk2 >> 1; jx > 0; jx >>= 1) {
                    int partner = __shfl_xor_sync(0xffffffffu, v, jx);
                    bool up = ((lane & kk2) == 0);
                    bool smallh = ((lane & jx) == 0);
                    int mn = min(v, partner), mx = max(v, partner);
                    v = (smallh == up) ? mn : mx;
                }
            }
            g_idx[((size_t)b*NN + n)*KK + lane] = v;
            __syncwarp();
        }

    } else {
        // ---------- ga: GA/G1 precompute -> merged g_G rows (FFMA2 accumulators) ----------
        float* s_f  = sm;
        float* s_wa = sm + 4096;
        float* s_w1 = sm + 8192;
        int gb = blk - 512;
        int b  = gb >> 6;
        int j0 = (gb & 63) << 6;

        for (int lin = tid; lin < 64*64; lin += 512) {
            int i = lin >> 6, c = lin & 63;
            s_wa[i*64 + c] = w_attn[c*CIN + 3 + i];
            s_w1[i*64 + c] = w1[c*CIN + 3 + i];
        }
        for (int lin = tid; lin < 64*64; lin += 512) {
            int i = lin >> 6, jj = lin & 63;
            s_f[i*64 + jj] = f[((size_t)b*CC + i)*NN + j0 + jj];
        }
        __syncthreads();

        int j  = tid & 63;
        int c0 = (tid >> 6) << 3;
        unsigned long long accA2[4], acc12[4];
#pragma unroll
        for (int q = 0; q < 4; q++) {
            accA2[q] = pack2(__ldg(&b_attn[c0+2*q]), __ldg(&b_attn[c0+2*q+1]));
            acc12[q] = pack2(__ldg(&b1[c0+2*q]),     __ldg(&b1[c0+2*q+1]));
        }

#pragma unroll 4
        for (int i = 0; i < 64; i++) {
            float fv = s_f[i*64 + j];
            unsigned long long fv2 = pack2(fv, fv);
            const ulonglong2* wa = reinterpret_cast<const ulonglong2*>(&s_wa[i*64 + c0]);
            const ulonglong2* wb = reinterpret_cast<const ulonglong2*>(&s_w1[i*64 + c0]);
            ulonglong2 A0 = wa[0], A1 = wa[1];
            ulonglong2 B0 = wb[0], B1 = wb[1];
            fma2(accA2[0], A0.x, fv2); fma2(accA2[1], A0.y, fv2);
            fma2(accA2[2], A1.x, fv2); fma2(accA2[3], A1.y, fv2);
            fma2(acc12[0], B0.x, fv2); fma2(acc12[1], B0.y, fv2);
            fma2(acc12[2], B1.x, fv2); fma2(acc12[3], B1.y, fv2);
        }
        size_t base = ((size_t)b*NN + j0 + j)*128 + c0;
        {
            float2 a0 = unpack2(accA2[0]), a1 = unpack2(accA2[1]);
            float2 a2 = unpack2(accA2[2]), a3 = unpack2(accA2[3]);
            *reinterpret_cast<float4*>(&g_G[base + 0]) = make_float4(a0.x, a0.y, a1.x, a1.y);
            *reinterpret_cast<float4*>(&g_G[base + 4]) = make_float4(a2.x, a2.y, a3.x, a3.y);
            float2 o0 = unpack2(acc12[0]), o1 = unpack2(acc12[1]);
            float2 o2 = unpack2(acc12[2]), o3 = unpack2(acc12[3]);
            *reinterpret_cast<float4*>(&g_G[base + 64]) = make_float4(o0.x, o0.y, o1.x, o1.y);
            *reinterpret_cast<float4*>(&g_G[base + 68]) = make_float4(o2.x, o2.y, o3.x, o3.y);
        }
    }
}

// ---------------- fused main: mma.sync GEMM, 4 points/block, 3 blocks/SM ----------------
#define SMM_RHI  0
#define SMM_RLO  18432
#define SMM_E    36864
#define SMM_META 55296
#define SM_MAIN  59392

__global__ void __launch_bounds__(256, 3) main_kernel(const float* __restrict__ p,
        const float* __restrict__ b2) {
    extern __shared__ char smc[];
    uint32_t smem_base = smem_u32(smc);
    float4* s_meta = reinterpret_cast<float4*>(smc + SMM_META);

    int tid  = threadIdx.x;
    int w    = tid >> 5;
    int lane = tid & 31;
    int pbase = blockIdx.x * 4;

    if (w < 4) {
        int pid = pbase + w;
        int b = pid >> 12, n = pid & 4095;
        int j = g_idx[(size_t)pid*KK + lane];
        const float* pn = p + ((size_t)b*NN + n)*3;
        const float* pj = p + ((size_t)b*NN + j)*3;
        float4 m;
        m.x = pj[0] - pn[0];
        m.y = pj[1] - pn[1];
        m.z = pj[2] - pn[2];
        m.w = __int_as_float(j);
        s_meta[w*32 + lane] = m;
    }
    __syncthreads();

    // ---- phase 1 (warp-specialized): warps 0-3 -> R(pt=w), warps 4-7 -> E(pt=w-4) ----
    {
        bool isR = (w < 4);
        int pt = w & 3;
        int pid = pbase + pt;
        int b = pid >> 12;
        int lh  = lane >> 4;
        int u16 = (lane & 15) * 4;
        int u   = isR ? (64 + u16) : u16;
        float4 wx = *reinterpret_cast<const float4*>(&g_wD3[0*128 + u]);
        float4 wy = *reinterpret_cast<const float4*>(&g_wD3[1*128 + u]);
        float4 wz = *reinterpret_cast<const float4*>(&g_wD3[2*128 + u]);
        __half* Ep = reinterpret_cast<__half*>(smc + SMM_E) + pt*2304;
        const float* Gb = g_G + (size_t)b*NN*128;

#pragma unroll 8
        for (int kk = 0; kk < 16; kk++) {
            int k = kk*2 + lh;
            float4 m = s_meta[pt*32 + k];
            int j = __float_as_int(m.w);
            float4 g = __ldg(reinterpret_cast<const float4*>(&Gb[(size_t)j*128 + u]));
            float4 v;
            v.x = g.x + wx.x*m.x + wy.x*m.y + wz.x*m.z;
            v.y = g.y + wx.y*m.x + wy.y*m.y + wz.y*m.z;
            v.z = g.z + wx.z*m.x + wy.z*m.y + wz.z*m.z;
            v.w = g.w + wx.w*m.x + wy.w*m.y + wz.w*m.z;
            if (isR) {
                float r0 = fmaxf(v.x, 0.0f), r1 = fmaxf(v.y, 0.0f);
                float r2v = fmaxf(v.z, 0.0f), r3 = fmaxf(v.w, 0.0f);
                __nv_bfloat16 h0 = __float2bfloat16(r0), h1 = __float2bfloat16(r1);
                __nv_bfloat16 h2 = __float2bfloat16(r2v), h3 = __float2bfloat16(r3);
                __nv_bfloat162 hp0; hp0.x = h0; hp0.y = h1;
                __nv_bfloat162 hp1; hp1.x = h2; hp1.y = h3;
                __nv_bfloat162 lp0; lp0.x = __float2bfloat16(r0 - __bfloat162float(h0));
                                    lp0.y = __float2bfloat16(r1 - __bfloat162float(h1));
                __nv_bfloat162 lp1; lp1.x = __float2bfloat16(r2v - __bfloat162float(h2));
                                    lp1.y = __float2bfloat16(r3 - __bfloat162float(h3));
                int row = pt*32 + k;
                uint32_t roff = (uint32_t)(row*72 + u16)*2;
                *reinterpret_cast<uint2*>(smc + SMM_RHI + roff) =
                    make_uint2(*reinterpret_cast<uint32_t*>(&hp0), *reinterpret_cast<uint32_t*>(&hp1));
                *reinterpret_cast<uint2*>(smc + SMM_RLO + roff) =
                    make_uint2(*reinterpret_cast<uint32_t*>(&lp0), *reinterpret_cast<uint32_t*>(&lp1));
            } else {
                union { __half2 h[2]; uint2 u2; } cv;
                cv.h[0] = __floats2half2_rn(__expf(v.x), __expf(v.y));
                cv.h[1] = __floats2half2_rn(__expf(v.z), __expf(v.w));
                *reinterpret_cast<uint2*>(&Ep[k*72 + u16]) = cv.u2;
            }
        }
    }
    __syncthreads();

    // ---- mma GEMM + softmax-weighted epilogue: warp = (pt = w&3, mh = w>>2) ----
    {
        int pt = w & 3;
        int mh = w >> 2;

        int r8 = lane & 7, mmat = lane >> 3;
        int arow = pt*32 + mh*16 + r8 + ((mmat & 1) << 3);
        uint32_t acolB = (uint32_t)(((mmat >> 1) << 3) * 2);
        uint32_t abase = smem_base + (uint32_t)(arow * 144) + acolB;

        float acc[8][4];
#pragma unroll
        for (int nt = 0; nt < 8; nt++)
#pragma unroll
            for (int q = 0; q < 4; q++) acc[nt][q] = 0.0f;

#pragma unroll
        for (int kt = 0; kt < 4; kt++) {
            uint32_t ah[4], al[4];
            ldsm_x4(ah, abase + SMM_RHI + kt*32);
            ldsm_x4(al, abase + SMM_RLO + kt*32);
#pragma unroll
            for (int nt = 0; nt < 8; nt++) {
                int bidx = ((kt*8 + nt)*32 + lane)*2;
                uint2 bh = __ldg(reinterpret_cast<const uint2*>(&g_bfH[bidx]));
                uint2 bl = __ldg(reinterpret_cast<const uint2*>(&g_bfL[bidx]));
                mma_bf16(acc[nt], ah, bh.x, bh.y);
                mma_bf16(acc[nt], al, bh.x, bh.y);
                mma_bf16(acc[nt], ah, bl.x, bl.y);
            }
        }

        const __half* Eb = reinterpret_cast<const __half*>(smc + SMM_E);
        float* red = reinterpret_cast<float*>(smc + SMM_META);
        int r0 = mh*16 + (lane >> 2);
        int c00 = (lane & 3) * 2;
#pragma unroll
        for (int nt = 0; nt < 8; nt++) {
            int c0 = nt*8 + c00;
            float2 e0 = __half22float2(*reinterpret_cast<const __half2*>(&Eb[pt*2304 + r0*72 + c0]));
            float2 e1 = __half22float2(*reinterpret_cast<const __half2*>(&Eb[pt*2304 + (r0+8)*72 + c0]));
            float v0 = e0.x*acc[nt][0] + e1.x*acc[nt][2];
            float v1 = e0.y*acc[nt][1] + e1.y*acc[nt][3];
            float v2 = e0.x + e1.x;
            float v3 = e0.y + e1.y;
            bool up4 = (lane & 4) != 0;
            float s0 = up4 ? v0 : v2;
            float s1 = up4 ? v1 : v3;
            float rA = __shfl_xor_sync(0xffffffffu, s0, 4);
            float rB = __shfl_xor_sync(0xffffffffu, s1, 4);
            v0 = (up4 ? v2 : v0) + rA;
            v1 = (up4 ? v3 : v1) + rB;
            bool up8 = (lane & 8) != 0;
            float s2 = up8 ? v0 : v1;
            float rC = __shfl_xor_sync(0xffffffffu, s2, 8);
            v0 = (up8 ? v1 : v0) + rC;
            v0 += __shfl_xor_sync(0xffffffffu, v0, 16);
            if (lane < 16) {
                int c = nt*8 + (lane & 3)*2 + ((lane >> 3) & 1);
                int d = (lane >> 2) & 1;
                red[((mh*4 + pt)*64 + c)*2 + d] = v0;
            }
        }
    }
    __syncthreads();

    {
        int pt = tid >> 6, c = tid & 63;
        const float* red = reinterpret_cast<const float*>(smc + SMM_META);
        float num = red[(pt*64 + c)*2 + 0] + red[((4 + pt)*64 + c)*2 + 0];
        float den = red[(pt*64 + c)*2 + 1] + red[((4 + pt)*64 + c)*2 + 1];
        g_F0[(size_t)(pbase + pt)*CC + c] = num / den + __ldg(&b2[c]);
    }
}

// ---------------- tail: relu(F0+f) -> 2x (64x64) MLP -> relu residual ----------------
__global__ void __launch_bounds__(256) tail_kernel(const float* __restrict__ f,
        const float* __restrict__ bf1, const float* __restrict__ bf2,
        float* __restrict__ outF) {
    __shared__ float s_F1[64*68];
    __shared__ float s_H[64*68];

    int b   = blockIdx.x >> 6;
    int n0g = (blockIdx.x & 63) << 6;
    int tid = threadIdx.x;

    {
        int c = tid >> 2, q = tid & 3;
        const float* frow = f + ((size_t)b*CC + c)*NN + n0g;
        const float* f0b  = g_F0 + ((size_t)b*NN + n0g)*CC + c;
#pragma unroll
        for (int i = 0; i < 4; i++) {
            int nn = q*16 + i*4;
            float4 fv = *reinterpret_cast<const float4*>(frow + nn);
            float a0 = __ldg(&f0b[(nn+0)*CC]);
            float a1 = __ldg(&f0b[(nn+1)*CC]);
            float a2 = __ldg(&f0b[(nn+2)*CC]);
            float a3 = __ldg(&f0b[(nn+3)*CC]);
            float4 r;
            r.x = fmaxf(a0 + fv.x, 0.0f);
            r.y = fmaxf(a1 + fv.y, 0.0f);
            r.z = fmaxf(a2 + fv.z, 0.0f);
            r.w = fmaxf(a3 + fv.w, 0.0f);
            *reinterpret_cast<float4*>(&s_F1[c*68 + nn]) = r;
        }
    }
    __syncthreads();

    int ct = (tid >> 4) << 2;
    int nt = (tid & 15) << 2;

    {
        float acc[16];
#pragma unroll
        for (int r = 0; r < 4; r++) {
            float bv = __ldg(&bf1[ct+r]);
#pragma unroll
            for (int jj = 0; jj < 4; jj++) acc[r*4+jj] = bv;
        }
#pragma unroll 4
        for (int cp = 0; cp < 64; cp++) {
            float4 wv = __ldg(reinterpret_cast<const float4*>(&g_wf1T[cp*64 + ct]));
            float4 fv = *reinterpret_cast<const float4*>(&s_F1[cp*68 + nt]);
            acc[0]  += wv.x*fv.x; acc[1]  += wv.x*fv.y; acc[2]  += wv.x*fv.z; acc[3]  += wv.x*fv.w;
            acc[4]  += wv.y*fv.x; acc[5]  += wv.y*fv.y; acc[6]  += wv.y*fv.z; acc[7]  += wv.y*fv.w;
            acc[8]  += wv.z*fv.x; acc[9]  += wv.z*fv.y; acc[10] += wv.z*fv.z; acc[11] += wv.z*fv.w;
            acc[12] += wv.w*fv.x; acc[13] += wv.w*fv.y; acc[14] += wv.w*fv.z; acc[15] += wv.w*fv.w;
        }
#pragma unroll
        for (int r = 0; r < 4; r++) {
            float4 o;
            o.x = fmaxf(acc[r*4+0], 0.0f);
            o.y = fmaxf(acc[r*4+1], 0.0f);
            o.z = fmaxf(acc[r*4+2], 0.0f);
            o.w = fmaxf(acc[r*4+3], 0.0f);
            *reinterpret_cast<float4*>(&s_H[(ct+r)*68 + nt]) = o;
        }
    }
    __syncthreads();

    {
        float acc[16];
#pragma unroll
        for (int r = 0; r < 4; r++) {
            float bv = __ldg(&bf2[ct+r]);
#pragma unroll
            for (int jj = 0; jj < 4; jj++) acc[r*4+jj] = bv;
        }
#pragma unroll 4
        for (int cp = 0; cp < 64; cp++) {
            float4 wv = __ldg(reinterpret_cast<const float4*>(&g_wf2T[cp*64 + ct]));
            float4 hv = *reinterpret_cast<const float4*>(&s_H[cp*68 + nt]);
            acc[0]  += wv.x*hv.x; acc[1]  += wv.x*hv.y; acc[2]  += wv.x*hv.z; acc[3]  += wv.x*hv.w;
            acc[4]  += wv.y*hv.x; acc[5]  += wv.y*hv.y; acc[6]  += wv.y*hv.z; acc[7]  += wv.y*hv.w;
            acc[8]  += wv.z*hv.x; acc[9]  += wv.z*hv.y; acc[10] += wv.z*hv.z; acc[11] += wv.z*hv.w;
            acc[12] += wv.w*hv.x; acc[13] += wv.w*hv.y; acc[14] += wv.w*hv.z; acc[15] += wv.w*hv.w;
        }
#pragma unroll
        for (int r = 0; r < 4; r++) {
            const float* idn = &s_F1[(ct+r)*68 + nt];
            float4 o;
            o.x = fmaxf(acc[r*4+0] + idn[0], 0.0f);
            o.y = fmaxf(acc[r*4+1] + idn[1], 0.0f);
            o.z = fmaxf(acc[r*4+2] + idn[2], 0.0f);
            o.w = fmaxf(acc[r*4+3] + idn[3], 0.0f);
            *reinterpret_cast<float4*>(&outF[((size_t)b*CC + ct + r)*NN + n0g + nt]) = o;
        }
    }
}

// ---------------- launch ----------------
extern "C" void kernel_launch(void* const* d_in, const int* in_sizes, int n_in,
                              void* d_out, int out_size) {
    const float* p      = (const float*)d_in[0];
    const float* f      = (const float*)d_in[1];
    const float* w_attn = (const float*)d_in[2];
    const float* b_attn = (const float*)d_in[3];
    const float* w1     = (const float*)d_in[4];
    const float* b1     = (const float*)d_in[5];
    const float* w2     = (const float*)d_in[6];
    const float* b2     = (const float*)d_in[7];
    const float* wf1    = (const float*)d_in[8];
    const float* bf1    = (const float*)d_in[9];
    const float* wf2    = (const float*)d_in[10];
    const float* bf2    = (const float*)d_in[11];
    float* out = (float*)d_out;

    cudaFuncSetAttribute(prep_build, cudaFuncAttributeMaxDynamicSharedMemorySize, PREA_SMEM);
    prep_build<<<41, 512, PREA_SMEM>>>(p, w_attn, w1, w2, wf1, wf2, out);

    cudaFuncSetAttribute(bq_ga_kernel, cudaFuncAttributeMaxDynamicSharedMemorySize, PREB_SMEM);
    bq_ga_kernel<<<1024, 512, PREB_SMEM>>>(p, f, w_attn, b_attn, w1, b1);

    cudaFuncSetAttribute(main_kernel, cudaFuncAttributeMaxDynamicSharedMemorySize, SM_MAIN);
    main_kernel<<<BB*NN/4, 256, SM_MAIN>>>(p, b2);

    tail_kernel<<<BB*(NN/64), 256>>>(f, bf1, bf2, out + (size_t)BB*NN*3);
}